// round 1
// baseline (speedup 1.0000x reference)
#include <cuda_runtime.h>

#define B_  4
#define T_  2048
#define C_  1024
#define H_  16
#define HD_ 64
#define BH_ (B_*H_)

// Scratch (device globals — no allocation allowed in kernel_launch)
__device__ float g_Q[(size_t)BH_ * T_ * HD_];  // [B,H,T,HD], pre-scaled by 1/8
__device__ float g_K[(size_t)BH_ * T_ * HD_];
__device__ float g_V[(size_t)BH_ * T_ * HD_];
__device__ float g_O[(size_t)B_ * T_ * C_];    // attention output, [B,T,C]

// ---------------------------------------------------------------------------
// Kernel 1: qkv = x @ W_attn^T + b_attn, scattered into g_Q/g_K/g_V
// M=8192, N=3072, K=1024. 128x128 tile, BK=8, 256 threads, 8x8 per thread.
// ---------------------------------------------------------------------------
__global__ void __launch_bounds__(256) qkv_gemm_kernel(
    const float* __restrict__ X, const float* __restrict__ W,
    const float* __restrict__ bias)
{
    __shared__ float Ast[8][128];
    __shared__ float Bst[8][128];
    const int K = C_;

    int tid = threadIdx.x;
    int bm = blockIdx.y * 128;
    int bn = blockIdx.x * 128;
    int tx = tid & 15, ty = tid >> 4;
    int lr = tid >> 1;          // 0..127 (tile row)
    int lc = (tid & 1) * 4;     // 0 or 4 (k offset)

    float acc[8][8];
#pragma unroll
    for (int i = 0; i < 8; i++)
#pragma unroll
        for (int j = 0; j < 8; j++) acc[i][j] = 0.f;

    const float* Aptr = X + (size_t)(bm + lr) * K + lc;
    const float* Bptr = W + (size_t)(bn + lr) * K + lc;

    for (int k0 = 0; k0 < K; k0 += 8) {
        float4 av = *reinterpret_cast<const float4*>(Aptr + k0);
        float4 bv = *reinterpret_cast<const float4*>(Bptr + k0);
        Ast[lc + 0][lr] = av.x; Ast[lc + 1][lr] = av.y;
        Ast[lc + 2][lr] = av.z; Ast[lc + 3][lr] = av.w;
        Bst[lc + 0][lr] = bv.x; Bst[lc + 1][lr] = bv.y;
        Bst[lc + 2][lr] = bv.z; Bst[lc + 3][lr] = bv.w;
        __syncthreads();
#pragma unroll
        for (int kk = 0; kk < 8; kk++) {
            float a[8], b[8];
            *(float4*)&a[0] = *(float4*)&Ast[kk][ty * 4];
            *(float4*)&a[4] = *(float4*)&Ast[kk][64 + ty * 4];
            *(float4*)&b[0] = *(float4*)&Bst[kk][tx * 4];
            *(float4*)&b[4] = *(float4*)&Bst[kk][64 + tx * 4];
#pragma unroll
            for (int i = 0; i < 8; i++)
#pragma unroll
                for (int j = 0; j < 8; j++)
                    acc[i][j] += a[i] * b[j];
        }
        __syncthreads();
    }

    // Epilogue: add bias, scatter into [B,H,T,HD] layout; scale Q by 1/8.
#pragma unroll
    for (int i = 0; i < 8; i++) {
        int row = bm + ((i < 4) ? (ty * 4 + i) : (64 + ty * 4 + (i - 4)));
        int b = row / T_;
        int t = row - b * T_;
#pragma unroll
        for (int j = 0; j < 8; j++) {
            int col = bn + ((j < 4) ? (tx * 4 + j) : (64 + tx * 4 + (j - 4)));
            float v = acc[i][j] + bias[col];
            int seg = col >> 10;      // 0=q, 1=k, 2=v
            int cn  = col & 1023;
            int h = cn >> 6, d = cn & 63;
            size_t idx = (((size_t)(b * H_ + h) * T_) + t) * HD_ + d;
            if (seg == 0)      g_Q[idx] = v * 0.125f;   // 1/sqrt(64)
            else if (seg == 1) g_K[idx] = v;
            else               g_V[idx] = v;
        }
    }
}

// ---------------------------------------------------------------------------
// Kernel 2: flash attention. grid = (T/64, B*H), 256 threads.
// Online softmax over key tiles of 64. HD=64. Q pre-scaled.
// Dynamic SMEM: Qst[64][64] (d-major) | Kst[64][64] (d-major) |
//               Vs[64][64] (key-major) | Ss[64][68] | m/l/corr[64 each]
// ---------------------------------------------------------------------------
#define SS_PITCH 68
#define ATTN_SMEM_FLOATS (4096 * 3 + 64 * SS_PITCH + 192)
#define ATTN_SMEM_BYTES  (ATTN_SMEM_FLOATS * 4)

__global__ void __launch_bounds__(256) attn_kernel()
{
    extern __shared__ float sh[];
    float* Qst = sh;                       // [d][row]
    float* Kst = sh + 4096;                // [d][col]
    float* Vs  = sh + 8192;                // [key][d]
    float* Ss  = sh + 12288;               // [row][SS_PITCH]
    float* m_sh    = sh + 12288 + 64 * SS_PITCH;
    float* l_sh    = m_sh + 64;
    float* corr_sh = l_sh + 64;

    int tid = threadIdx.x;
    int tx = tid & 15, ty = tid >> 4;
    int bh = blockIdx.y;
    int qbase = blockIdx.x * 64;

    const float* Qg = g_Q + (size_t)bh * T_ * HD_ + (size_t)qbase * HD_;
    const float* Kg = g_K + (size_t)bh * T_ * HD_;
    const float* Vg = g_V + (size_t)bh * T_ * HD_;

    // Load Q tile transposed into Qst[d][row]
#pragma unroll
    for (int i = 0; i < 4; i++) {
        int idx = tid + i * 256;          // float4 index 0..1023
        int row = idx >> 4;
        int dc = (idx & 15) * 4;
        float4 v = *reinterpret_cast<const float4*>(Qg + row * 64 + dc);
        Qst[(dc + 0) * 64 + row] = v.x;
        Qst[(dc + 1) * 64 + row] = v.y;
        Qst[(dc + 2) * 64 + row] = v.z;
        Qst[(dc + 3) * 64 + row] = v.w;
    }
    if (tid < 64) { m_sh[tid] = -1e30f; l_sh[tid] = 0.f; }

    float o[4][4];
#pragma unroll
    for (int i = 0; i < 4; i++)
#pragma unroll
        for (int j = 0; j < 4; j++) o[i][j] = 0.f;

    for (int kt = 0; kt < T_; kt += 64) {
        // Load K (transposed) and V (direct)
#pragma unroll
        for (int i = 0; i < 4; i++) {
            int idx = tid + i * 256;
            int row = idx >> 4;
            int dc = (idx & 15) * 4;
            float4 kv = *reinterpret_cast<const float4*>(Kg + (size_t)(kt + row) * 64 + dc);
            Kst[(dc + 0) * 64 + row] = kv.x;
            Kst[(dc + 1) * 64 + row] = kv.y;
            Kst[(dc + 2) * 64 + row] = kv.z;
            Kst[(dc + 3) * 64 + row] = kv.w;
            float4 vv = *reinterpret_cast<const float4*>(Vg + (size_t)(kt + row) * 64 + dc);
            *reinterpret_cast<float4*>(&Vs[row * 64 + dc]) = vv;
        }
        __syncthreads();

        // S = Q K^T (Q already scaled)
        float s[4][4];
#pragma unroll
        for (int i = 0; i < 4; i++)
#pragma unroll
            for (int j = 0; j < 4; j++) s[i][j] = 0.f;
#pragma unroll 8
        for (int d = 0; d < 64; d++) {
            float4 a = *(float4*)&Qst[d * 64 + ty * 4];
            float4 b = *(float4*)&Kst[d * 64 + tx * 4];
            s[0][0] += a.x * b.x; s[0][1] += a.x * b.y; s[0][2] += a.x * b.z; s[0][3] += a.x * b.w;
            s[1][0] += a.y * b.x; s[1][1] += a.y * b.y; s[1][2] += a.y * b.z; s[1][3] += a.y * b.w;
            s[2][0] += a.z * b.x; s[2][1] += a.z * b.y; s[2][2] += a.z * b.z; s[2][3] += a.z * b.w;
            s[3][0] += a.w * b.x; s[3][1] += a.w * b.y; s[3][2] += a.w * b.z; s[3][3] += a.w * b.w;
        }
#pragma unroll
        for (int rr = 0; rr < 4; rr++)
            *(float4*)&Ss[(ty * 4 + rr) * SS_PITCH + tx * 4] =
                make_float4(s[rr][0], s[rr][1], s[rr][2], s[rr][3]);
        __syncthreads();

        // Online softmax: 4 threads per row, 16 cols each
        {
            int row = tid >> 2;
            int sub = tid & 3;
            float* p = &Ss[row * SS_PITCH + sub * 16];
            float mx = -1e30f;
#pragma unroll
            for (int j = 0; j < 16; j++) mx = fmaxf(mx, p[j]);
            mx = fmaxf(mx, __shfl_xor_sync(0xffffffffu, mx, 1));
            mx = fmaxf(mx, __shfl_xor_sync(0xffffffffu, mx, 2));
            float m_old = m_sh[row];
            float m_new = fmaxf(m_old, mx);
            float ssum = 0.f;
#pragma unroll
            for (int j = 0; j < 16; j++) {
                float e = __expf(p[j] - m_new);
                p[j] = e;
                ssum += e;
            }
            ssum += __shfl_xor_sync(0xffffffffu, ssum, 1);
            ssum += __shfl_xor_sync(0xffffffffu, ssum, 2);
            if (sub == 0) {
                float corr = __expf(m_old - m_new);
                corr_sh[row] = corr;
                l_sh[row] = l_sh[row] * corr + ssum;
                m_sh[row] = m_new;
            }
        }
        __syncthreads();

        // O = O*corr + P @ V
#pragma unroll
        for (int rr = 0; rr < 4; rr++) {
            float c = corr_sh[ty * 4 + rr];
            o[rr][0] *= c; o[rr][1] *= c; o[rr][2] *= c; o[rr][3] *= c;
        }
#pragma unroll 8
        for (int kk = 0; kk < 64; kk++) {
            float4 v = *(float4*)&Vs[kk * 64 + tx * 4];
#pragma unroll
            for (int rr = 0; rr < 4; rr++) {
                float pp = Ss[(ty * 4 + rr) * SS_PITCH + kk];
                o[rr][0] += pp * v.x; o[rr][1] += pp * v.y;
                o[rr][2] += pp * v.z; o[rr][3] += pp * v.w;
            }
        }
        __syncthreads();
    }

    // Normalize and write to g_O in [B,T,C] layout
    int b = bh >> 4, h = bh & 15;
#pragma unroll
    for (int rr = 0; rr < 4; rr++) {
        int r = ty * 4 + rr;
        float invl = 1.0f / l_sh[r];
        size_t oidx = ((size_t)(b * T_ + qbase + r)) * C_ + h * HD_ + tx * 4;
        *reinterpret_cast<float4*>(&g_O[oidx]) =
            make_float4(o[rr][0] * invl, o[rr][1] * invl,
                        o[rr][2] * invl, o[rr][3] * invl);
    }
}

// ---------------------------------------------------------------------------
// Kernel 3: out = g_O @ W_proj^T + b_proj. M=8192, N=1024, K=1024.
// ---------------------------------------------------------------------------
__global__ void __launch_bounds__(256) proj_gemm_kernel(
    const float* __restrict__ W, const float* __restrict__ bias,
    float* __restrict__ out)
{
    __shared__ float Ast[8][128];
    __shared__ float Bst[8][128];
    const int K = C_;

    int tid = threadIdx.x;
    int bm = blockIdx.y * 128;
    int bn = blockIdx.x * 128;
    int tx = tid & 15, ty = tid >> 4;
    int lr = tid >> 1;
    int lc = (tid & 1) * 4;

    float acc[8][8];
#pragma unroll
    for (int i = 0; i < 8; i++)
#pragma unroll
        for (int j = 0; j < 8; j++) acc[i][j] = 0.f;

    const float* Aptr = g_O + (size_t)(bm + lr) * K + lc;
    const float* Bptr = W + (size_t)(bn + lr) * K + lc;

    for (int k0 = 0; k0 < K; k0 += 8) {
        float4 av = *reinterpret_cast<const float4*>(Aptr + k0);
        float4 bv = *reinterpret_cast<const float4*>(Bptr + k0);
        Ast[lc + 0][lr] = av.x; Ast[lc + 1][lr] = av.y;
        Ast[lc + 2][lr] = av.z; Ast[lc + 3][lr] = av.w;
        Bst[lc + 0][lr] = bv.x; Bst[lc + 1][lr] = bv.y;
        Bst[lc + 2][lr] = bv.z; Bst[lc + 3][lr] = bv.w;
        __syncthreads();
#pragma unroll
        for (int kk = 0; kk < 8; kk++) {
            float a[8], b[8];
            *(float4*)&a[0] = *(float4*)&Ast[kk][ty * 4];
            *(float4*)&a[4] = *(float4*)&Ast[kk][64 + ty * 4];
            *(float4*)&b[0] = *(float4*)&Bst[kk][tx * 4];
            *(float4*)&b[4] = *(float4*)&Bst[kk][64 + tx * 4];
#pragma unroll
            for (int i = 0; i < 8; i++)
#pragma unroll
                for (int j = 0; j < 8; j++)
                    acc[i][j] += a[i] * b[j];
        }
        __syncthreads();
    }

#pragma unroll
    for (int i = 0; i < 8; i++) {
        int row = bm + ((i < 4) ? (ty * 4 + i) : (64 + ty * 4 + (i - 4)));
#pragma unroll
        for (int j = 0; j < 8; j++) {
            int col = bn + ((j < 4) ? (tx * 4 + j) : (64 + tx * 4 + (j - 4)));
            out[(size_t)row * C_ + col] = acc[i][j] + bias[col];
        }
    }
}

// ---------------------------------------------------------------------------
extern "C" void kernel_launch(void* const* d_in, const int* in_sizes, int n_in,
                              void* d_out, int out_size)
{
    const float* x      = (const float*)d_in[0];
    const float* W_attn = (const float*)d_in[1];
    const float* b_attn = (const float*)d_in[2];
    const float* W_proj = (const float*)d_in[3];
    const float* b_proj = (const float*)d_in[4];
    float* out = (float*)d_out;

    cudaFuncSetAttribute(attn_kernel,
                         cudaFuncAttributeMaxDynamicSharedMemorySize,
                         ATTN_SMEM_BYTES);

    dim3 gq(3072 / 128, 8192 / 128);
    qkv_gemm_kernel<<<gq, 256>>>(x, W_attn, b_attn);

    attn_kernel<<<dim3(T_ / 64, BH_), 256, ATTN_SMEM_BYTES>>>();

    dim3 gp(1024 / 128, 8192 / 128);
    proj_gemm_kernel<<<gp, 256>>>(W_proj, b_proj, out);
}

// round 3
// speedup vs baseline: 1.3040x; 1.3040x over previous
#include <cuda_runtime.h>
#include <cuda_bf16.h>
#include <cstdint>

#define B_  4
#define T_  2048
#define C_  1024
#define H_  16
#define HD_ 64
#define BH_ (B_*H_)
#define KD_ 1024

// ---------------------------------------------------------------------------
// Device-global scratch (no allocation allowed in kernel_launch)
// ---------------------------------------------------------------------------
__device__ float g_Q[(size_t)BH_ * T_ * HD_];  // [B,H,T,HD], pre-scaled by 1/8
__device__ float g_K[(size_t)BH_ * T_ * HD_];
__device__ float g_V[(size_t)BH_ * T_ * HD_];

__device__ __nv_bfloat16 g_Xhi[(size_t)B_*T_*C_],   g_Xlo[(size_t)B_*T_*C_];
__device__ __nv_bfloat16 g_Wahi[(size_t)3*C_*C_],   g_Walo[(size_t)3*C_*C_];
__device__ __nv_bfloat16 g_Wphi[(size_t)C_*C_],     g_Wplo[(size_t)C_*C_];
__device__ __nv_bfloat16 g_Ohi[(size_t)B_*T_*C_],   g_Olo[(size_t)B_*T_*C_];

// ---------------------------------------------------------------------------
// Kernel A: fp32 -> bf16 hi/lo split.  mode 0: x, 1: W_attn, 2: W_proj
// ---------------------------------------------------------------------------
__global__ void __launch_bounds__(256) split_kernel(const float4* __restrict__ in, int mode)
{
    __nv_bfloat16 *hi, *lo;
    if (mode == 0)      { hi = g_Xhi;  lo = g_Xlo;  }
    else if (mode == 1) { hi = g_Wahi; lo = g_Walo; }
    else                { hi = g_Wphi; lo = g_Wplo; }

    size_t i = (size_t)blockIdx.x * blockDim.x + threadIdx.x;
    float4 v = in[i];
    __nv_bfloat16 hx = __float2bfloat16(v.x), hy = __float2bfloat16(v.y);
    __nv_bfloat16 hz = __float2bfloat16(v.z), hw = __float2bfloat16(v.w);
    __nv_bfloat16 lx = __float2bfloat16(v.x - __bfloat162float(hx));
    __nv_bfloat16 ly = __float2bfloat16(v.y - __bfloat162float(hy));
    __nv_bfloat16 lz = __float2bfloat16(v.z - __bfloat162float(hz));
    __nv_bfloat16 lw = __float2bfloat16(v.w - __bfloat162float(hw));
    __nv_bfloat162* Hh = reinterpret_cast<__nv_bfloat162*>(hi + 4 * i);
    __nv_bfloat162* Ll = reinterpret_cast<__nv_bfloat162*>(lo + 4 * i);
    Hh[0] = __halves2bfloat162(hx, hy); Hh[1] = __halves2bfloat162(hz, hw);
    Ll[0] = __halves2bfloat162(lx, ly); Ll[1] = __halves2bfloat162(lz, lw);
}

// ---------------------------------------------------------------------------
// Kernel B: HMMA (mma.sync bf16) split-precision GEMM.
//   C[M,N] = A[M,K] * B[N,K]^T + bias
// Block tile 128x128, BK=32, 2-stage cp.async double buffer, 256 threads,
// 8 warps each computing 64x32 via m16n8k16.
// SMEM rows padded to 80B (40 bf16): row-stride of 5 16B-groups mod 8 is
// coprime -> conflict-free ldmatrix, no swizzle needed.
// mode 0: A=g_X*, B=g_Wa* (N=3072), epilogue scatters Q/K/V (+lo*lo term).
// mode 1: A=g_O*, B=g_Wp* (N=1024), epilogue writes Cout.
// ---------------------------------------------------------------------------
#define BK_     32
#define ROWB    80
#define TILE_B  (128 * ROWB)          // 10240 bytes per operand tile
#define STAGE_B (4 * TILE_B)          // Ahi,Alo,Bhi,Blo
#define GEMM_SMEM_BYTES (2 * STAGE_B) // 81920

__device__ __forceinline__ uint32_t smem_u32(const void* p) {
    uint32_t a;
    asm("{ .reg .u64 t; cvta.to.shared.u64 t, %1; cvt.u32.u64 %0, t; }"
        : "=r"(a) : "l"(p));
    return a;
}

#define CP_ASYNC16(dst, src) \
    asm volatile("cp.async.cg.shared.global [%0], [%1], 16;" :: "r"(dst), "l"(src))
#define CP_COMMIT() asm volatile("cp.async.commit_group;" ::: "memory")
#define CP_WAIT1()  asm volatile("cp.async.wait_group 1;" ::: "memory")
#define CP_WAIT0()  asm volatile("cp.async.wait_group 0;" ::: "memory")

#define LDSM_X4(r0, r1, r2, r3, addr) \
    asm volatile("ldmatrix.sync.aligned.m8n8.x4.shared.b16 {%0,%1,%2,%3}, [%4];" \
        : "=r"(r0), "=r"(r1), "=r"(r2), "=r"(r3) : "r"(addr))

#define MMA16816(c, a, b) \
    asm volatile("mma.sync.aligned.m16n8k16.row.col.f32.bf16.bf16.f32 " \
        "{%0,%1,%2,%3}, {%4,%5,%6,%7}, {%8,%9}, {%0,%1,%2,%3};" \
        : "+f"((c)[0]), "+f"((c)[1]), "+f"((c)[2]), "+f"((c)[3]) \
        : "r"((a)[0]), "r"((a)[1]), "r"((a)[2]), "r"((a)[3]), \
          "r"((b)[0]), "r"((b)[1]))

__global__ void __launch_bounds__(256) hmma_gemm_kernel(
    const float* __restrict__ bias, float* __restrict__ Cout, int mode)
{
    extern __shared__ __align__(128) char smem[];
    const __nv_bfloat16 *Ahi, *Alo, *Bhi, *Blo;
    if (mode == 0) { Ahi = g_Xhi; Alo = g_Xlo; Bhi = g_Wahi; Blo = g_Walo; }
    else           { Ahi = g_Ohi; Alo = g_Olo; Bhi = g_Wphi; Blo = g_Wplo; }

    uint32_t sb = smem_u32(smem);
    int tid = threadIdx.x, lane = tid & 31, wid = tid >> 5;
    int bm = blockIdx.y * 128, bn = blockIdx.x * 128;
    int warp_m = wid >> 2;        // 0..1 (64 rows each)
    int warp_n = wid & 3;         // 0..3 (32 cols each)

    // ---- prefetch one BK=32 chunk into a stage ----
    auto prefetch = [&](int chunk, int stage) {
        int k0 = chunk * BK_;
        uint32_t sbase = sb + stage * STAGE_B;
#pragma unroll
        for (int it = 0; it < 8; it++) {
            int idx = tid + it * 256;
            int tile = idx >> 9;           // 0=Ahi 1=Alo 2=Bhi 3=Blo
            int within = idx & 511;
            int row = within >> 2;
            int ch = within & 3;
            int rb = (tile < 2) ? bm : bn;
            const __nv_bfloat16* base =
                (tile == 0) ? Ahi : (tile == 1) ? Alo : (tile == 2) ? Bhi : Blo;
            const __nv_bfloat16* g = base + (size_t)(rb + row) * KD_ + k0 + ch * 8;
            uint32_t daddr = sbase + tile * TILE_B + row * ROWB + ch * 16;
            CP_ASYNC16(daddr, g);
        }
        CP_COMMIT();
    };

    float acc[4][4][4];
#pragma unroll
    for (int mi = 0; mi < 4; mi++)
#pragma unroll
        for (int ni = 0; ni < 4; ni++)
#pragma unroll
            for (int r = 0; r < 4; r++) acc[mi][ni][r] = 0.f;

    prefetch(0, 0);
    prefetch(1, 1);

    const int NCH = KD_ / BK_;   // 32
    for (int ch = 0; ch < NCH; ch++) {
        if (ch < NCH - 1) CP_WAIT1(); else CP_WAIT0();
        __syncthreads();

        uint32_t sbase = sb + (ch & 1) * STAGE_B;
        uint32_t abase = sbase + (warp_m * 64) * ROWB;
        uint32_t bbase = sbase + 2 * TILE_B + (warp_n * 32) * ROWB;

#pragma unroll
        for (int ks = 0; ks < 2; ks++) {
            uint32_t ah[4][4], al[4][4], bh[4][2], bl[4][2];
            int acol = (ks * 16 + ((lane >> 4) << 3)) * 2;
#pragma unroll
            for (int mi = 0; mi < 4; mi++) {
                uint32_t addr = abase + (mi * 16 + (lane & 15)) * ROWB + acol;
                LDSM_X4(ah[mi][0], ah[mi][1], ah[mi][2], ah[mi][3], addr);
                addr += TILE_B;
                LDSM_X4(al[mi][0], al[mi][1], al[mi][2], al[mi][3], addr);
            }
            int brow = ((lane >> 4) << 3) + (lane & 7);
            int bcol = (ks * 16 + (((lane >> 3) & 1) << 3)) * 2;
#pragma unroll
            for (int np = 0; np < 2; np++) {
                uint32_t addr = bbase + (np * 16 + brow) * ROWB + bcol;
                LDSM_X4(bh[2*np][0], bh[2*np][1], bh[2*np+1][0], bh[2*np+1][1], addr);
                addr += TILE_B;
                LDSM_X4(bl[2*np][0], bl[2*np][1], bl[2*np+1][0], bl[2*np+1][1], addr);
            }
#pragma unroll
            for (int mi = 0; mi < 4; mi++)
#pragma unroll
                for (int ni = 0; ni < 4; ni++) {
                    MMA16816(acc[mi][ni], ah[mi], bh[ni]);
                    MMA16816(acc[mi][ni], ah[mi], bl[ni]);
                    MMA16816(acc[mi][ni], al[mi], bh[ni]);
                    if (mode == 0)  // extra lo*lo precision for logits path
                        MMA16816(acc[mi][ni], al[mi], bl[ni]);
                }
        }
        __syncthreads();
        if (ch + 2 < NCH) prefetch(ch + 2, ch & 1);
    }

    // ---- epilogue ----
    int g = lane >> 2, t = lane & 3;
    if (mode == 0) {
#pragma unroll
        for (int mi = 0; mi < 4; mi++)
#pragma unroll
            for (int ni = 0; ni < 4; ni++) {
                int r0 = bm + warp_m * 64 + mi * 16 + g;
                int c0 = bn + warp_n * 32 + ni * 8 + t * 2;
#pragma unroll
                for (int e = 0; e < 4; e++) {
                    int m = r0 + (e >> 1) * 8;
                    int col = c0 + (e & 1);
                    float v = acc[mi][ni][e] + bias[col];
                    int b = m >> 11, tt = m & 2047;
                    int seg = col >> 10, cn = col & 1023;
                    int h = cn >> 6, d = cn & 63;
                    size_t o = (((size_t)(b * H_ + h) * T_) + tt) * HD_ + d;
                    if (seg == 0)      g_Q[o] = v * 0.125f;
                    else if (seg == 1) g_K[o] = v;
                    else               g_V[o] = v;
                }
            }
    } else {
#pragma unroll
        for (int mi = 0; mi < 4; mi++)
#pragma unroll
            for (int ni = 0; ni < 4; ni++) {
                int r0 = bm + warp_m * 64 + mi * 16 + g;
                int c0 = bn + warp_n * 32 + ni * 8 + t * 2;
                float2 v0 = make_float2(acc[mi][ni][0] + bias[c0],
                                        acc[mi][ni][1] + bias[c0 + 1]);
                float2 v1 = make_float2(acc[mi][ni][2] + bias[c0],
                                        acc[mi][ni][3] + bias[c0 + 1]);
                *reinterpret_cast<float2*>(&Cout[(size_t)r0 * C_ + c0]) = v0;
                *reinterpret_cast<float2*>(&Cout[(size_t)(r0 + 8) * C_ + c0]) = v1;
            }
    }
}

// ---------------------------------------------------------------------------
// Kernel C: flash attention (fp32 SIMT; epilogue emits bf16 hi/lo for proj)
// ---------------------------------------------------------------------------
#define SS_PITCH 68
#define ATTN_SMEM_FLOATS (4096 * 3 + 64 * SS_PITCH + 192)
#define ATTN_SMEM_BYTES  (ATTN_SMEM_FLOATS * 4)

__global__ void __launch_bounds__(256) attn_kernel()
{
    extern __shared__ float sh[];
    float* Qst = sh;
    float* Kst = sh + 4096;
    float* Vs  = sh + 8192;
    float* Ss  = sh + 12288;
    float* m_sh    = sh + 12288 + 64 * SS_PITCH;
    float* l_sh    = m_sh + 64;
    float* corr_sh = l_sh + 64;

    int tid = threadIdx.x;
    int tx = tid & 15, ty = tid >> 4;
    int bh = blockIdx.y;
    int qbase = blockIdx.x * 64;

    const float* Qg = g_Q + (size_t)bh * T_ * HD_ + (size_t)qbase * HD_;
    const float* Kg = g_K + (size_t)bh * T_ * HD_;
    const float* Vg = g_V + (size_t)bh * T_ * HD_;

#pragma unroll
    for (int i = 0; i < 4; i++) {
        int idx = tid + i * 256;
        int row = idx >> 4;
        int dc = (idx & 15) * 4;
        float4 v = *reinterpret_cast<const float4*>(Qg + row * 64 + dc);
        Qst[(dc + 0) * 64 + row] = v.x;
        Qst[(dc + 1) * 64 + row] = v.y;
        Qst[(dc + 2) * 64 + row] = v.z;
        Qst[(dc + 3) * 64 + row] = v.w;
    }
    if (tid < 64) { m_sh[tid] = -1e30f; l_sh[tid] = 0.f; }

    float o[4][4];
#pragma unroll
    for (int i = 0; i < 4; i++)
#pragma unroll
        for (int j = 0; j < 4; j++) o[i][j] = 0.f;

    for (int kt = 0; kt < T_; kt += 64) {
#pragma unroll
        for (int i = 0; i < 4; i++) {
            int idx = tid + i * 256;
            int row = idx >> 4;
            int dc = (idx & 15) * 4;
            float4 kv = *reinterpret_cast<const float4*>(Kg + (size_t)(kt + row) * 64 + dc);
            Kst[(dc + 0) * 64 + row] = kv.x;
            Kst[(dc + 1) * 64 + row] = kv.y;
            Kst[(dc + 2) * 64 + row] = kv.z;
            Kst[(dc + 3) * 64 + row] = kv.w;
            float4 vv = *reinterpret_cast<const float4*>(Vg + (size_t)(kt + row) * 64 + dc);
            *reinterpret_cast<float4*>(&Vs[row * 64 + dc]) = vv;
        }
        __syncthreads();

        float s[4][4];
#pragma unroll
        for (int i = 0; i < 4; i++)
#pragma unroll
            for (int j = 0; j < 4; j++) s[i][j] = 0.f;
#pragma unroll 8
        for (int d = 0; d < 64; d++) {
            float4 a = *(float4*)&Qst[d * 64 + ty * 4];
            float4 b = *(float4*)&Kst[d * 64 + tx * 4];
            s[0][0] += a.x * b.x; s[0][1] += a.x * b.y; s[0][2] += a.x * b.z; s[0][3] += a.x * b.w;
            s[1][0] += a.y * b.x; s[1][1] += a.y * b.y; s[1][2] += a.y * b.z; s[1][3] += a.y * b.w;
            s[2][0] += a.z * b.x; s[2][1] += a.z * b.y; s[2][2] += a.z * b.z; s[2][3] += a.z * b.w;
            s[3][0] += a.w * b.x; s[3][1] += a.w * b.y; s[3][2] += a.w * b.z; s[3][3] += a.w * b.w;
        }
#pragma unroll
        for (int rr = 0; rr < 4; rr++)
            *(float4*)&Ss[(ty * 4 + rr) * SS_PITCH + tx * 4] =
                make_float4(s[rr][0], s[rr][1], s[rr][2], s[rr][3]);
        __syncthreads();

        {
            int row = tid >> 2;
            int sub = tid & 3;
            float* p = &Ss[row * SS_PITCH + sub * 16];
            float mx = -1e30f;
#pragma unroll
            for (int j = 0; j < 16; j++) mx = fmaxf(mx, p[j]);
            mx = fmaxf(mx, __shfl_xor_sync(0xffffffffu, mx, 1));
            mx = fmaxf(mx, __shfl_xor_sync(0xffffffffu, mx, 2));
            float m_old = m_sh[row];
            float m_new = fmaxf(m_old, mx);
            float ssum = 0.f;
#pragma unroll
            for (int j = 0; j < 16; j++) {
                float e = __expf(p[j] - m_new);
                p[j] = e;
                ssum += e;
            }
            ssum += __shfl_xor_sync(0xffffffffu, ssum, 1);
            ssum += __shfl_xor_sync(0xffffffffu, ssum, 2);
            if (sub == 0) {
                float corr = __expf(m_old - m_new);
                corr_sh[row] = corr;
                l_sh[row] = l_sh[row] * corr + ssum;
                m_sh[row] = m_new;
            }
        }
        __syncthreads();

#pragma unroll
        for (int rr = 0; rr < 4; rr++) {
            float c = corr_sh[ty * 4 + rr];
            o[rr][0] *= c; o[rr][1] *= c; o[rr][2] *= c; o[rr][3] *= c;
        }
#pragma unroll 8
        for (int kk = 0; kk < 64; kk++) {
            float4 v = *(float4*)&Vs[kk * 64 + tx * 4];
#pragma unroll
            for (int rr = 0; rr < 4; rr++) {
                float pp = Ss[(ty * 4 + rr) * SS_PITCH + kk];
                o[rr][0] += pp * v.x; o[rr][1] += pp * v.y;
                o[rr][2] += pp * v.z; o[rr][3] += pp * v.w;
            }
        }
        __syncthreads();
    }

    // Normalize; write bf16 hi/lo for the proj GEMM
    int b = bh >> 4, h = bh & 15;
#pragma unroll
    for (int rr = 0; rr < 4; rr++) {
        int r = ty * 4 + rr;
        float invl = 1.0f / l_sh[r];
        size_t base = ((size_t)(b * T_ + qbase + r)) * C_ + h * HD_ + tx * 4;
        __nv_bfloat16 hh[4], ll[4];
#pragma unroll
        for (int c = 0; c < 4; c++) {
            float v = o[rr][c] * invl;
            hh[c] = __float2bfloat16(v);
            ll[c] = __float2bfloat16(v - __bfloat162float(hh[c]));
        }
        __nv_bfloat162* Hh = reinterpret_cast<__nv_bfloat162*>(g_Ohi + base);
        __nv_bfloat162* Ll = reinterpret_cast<__nv_bfloat162*>(g_Olo + base);
        Hh[0] = __halves2bfloat162(hh[0], hh[1]); Hh[1] = __halves2bfloat162(hh[2], hh[3]);
        Ll[0] = __halves2bfloat162(ll[0], ll[1]); Ll[1] = __halves2bfloat162(ll[2], ll[3]);
    }
}

// ---------------------------------------------------------------------------
extern "C" void kernel_launch(void* const* d_in, const int* in_sizes, int n_in,
                              void* d_out, int out_size)
{
    const float* x      = (const float*)d_in[0];
    const float* W_attn = (const float*)d_in[1];
    const float* b_attn = (const float*)d_in[2];
    const float* W_proj = (const float*)d_in[3];
    const float* b_proj = (const float*)d_in[4];
    float* out = (float*)d_out;

    cudaFuncSetAttribute(attn_kernel,
                         cudaFuncAttributeMaxDynamicSharedMemorySize, ATTN_SMEM_BYTES);
    cudaFuncSetAttribute(hmma_gemm_kernel,
                         cudaFuncAttributeMaxDynamicSharedMemorySize, GEMM_SMEM_BYTES);

    // fp32 -> bf16 hi/lo splits
    split_kernel<<<(B_*T_*C_) / 4 / 256, 256>>>((const float4*)x, 0);
    split_kernel<<<(3*C_*C_)  / 4 / 256, 256>>>((const float4*)W_attn, 1);
    split_kernel<<<(C_*C_)    / 4 / 256, 256>>>((const float4*)W_proj, 2);

    // QKV GEMM: M=8192, N=3072
    hmma_gemm_kernel<<<dim3(3 * C_ / 128, B_ * T_ / 128), 256, GEMM_SMEM_BYTES>>>(
        b_attn, nullptr, 0);

    // attention
    attn_kernel<<<dim3(T_ / 64, BH_), 256, ATTN_SMEM_BYTES>>>();

    // proj GEMM: M=8192, N=1024
    hmma_gemm_kernel<<<dim3(C_ / 128, B_ * T_ / 128), 256, GEMM_SMEM_BYTES>>>(
        b_proj, out, 1);
}

// round 4
// speedup vs baseline: 2.6517x; 2.0336x over previous
#include <cuda_runtime.h>
#include <cuda_bf16.h>
#include <cstdint>

#define B_  4
#define T_  2048
#define C_  1024
#define H_  16
#define HD_ 64
#define BH_ (B_*H_)
#define KD_ 1024

// ---------------------------------------------------------------------------
// Device-global scratch
// ---------------------------------------------------------------------------
__device__ __nv_bfloat16 g_Qh[(size_t)BH_*T_*HD_], g_Ql[(size_t)BH_*T_*HD_];
__device__ __nv_bfloat16 g_Kh[(size_t)BH_*T_*HD_], g_Kl[(size_t)BH_*T_*HD_];
__device__ __nv_bfloat16 g_Vh[(size_t)BH_*T_*HD_], g_Vl[(size_t)BH_*T_*HD_];

__device__ __nv_bfloat16 g_Xhi[(size_t)B_*T_*C_],   g_Xlo[(size_t)B_*T_*C_];
__device__ __nv_bfloat16 g_Wahi[(size_t)3*C_*C_],   g_Walo[(size_t)3*C_*C_];
__device__ __nv_bfloat16 g_Wphi[(size_t)C_*C_],     g_Wplo[(size_t)C_*C_];
__device__ __nv_bfloat16 g_Ohi[(size_t)B_*T_*C_],   g_Olo[(size_t)B_*T_*C_];

// ---------------------------------------------------------------------------
// Helpers
// ---------------------------------------------------------------------------
__device__ __forceinline__ uint32_t smem_u32(const void* p) {
    uint32_t a;
    asm("{ .reg .u64 t; cvta.to.shared.u64 t, %1; cvt.u32.u64 %0, t; }"
        : "=r"(a) : "l"(p));
    return a;
}

#define CP_ASYNC16(dst, src) \
    asm volatile("cp.async.cg.shared.global [%0], [%1], 16;" :: "r"(dst), "l"(src))
#define CP_COMMIT() asm volatile("cp.async.commit_group;" ::: "memory")
#define CP_WAIT1()  asm volatile("cp.async.wait_group 1;" ::: "memory")
#define CP_WAIT0()  asm volatile("cp.async.wait_group 0;" ::: "memory")

#define LDSM_X4(r0, r1, r2, r3, addr) \
    asm volatile("ldmatrix.sync.aligned.m8n8.x4.shared.b16 {%0,%1,%2,%3}, [%4];" \
        : "=r"(r0), "=r"(r1), "=r"(r2), "=r"(r3) : "r"(addr))
#define LDSM_X4_T(r0, r1, r2, r3, addr) \
    asm volatile("ldmatrix.sync.aligned.m8n8.x4.trans.shared.b16 {%0,%1,%2,%3}, [%4];" \
        : "=r"(r0), "=r"(r1), "=r"(r2), "=r"(r3) : "r"(addr))

#define MMA_(c, a0, a1, a2, a3, b0, b1) \
    asm volatile("mma.sync.aligned.m16n8k16.row.col.f32.bf16.bf16.f32 " \
        "{%0,%1,%2,%3}, {%4,%5,%6,%7}, {%8,%9}, {%0,%1,%2,%3};" \
        : "+f"((c)[0]), "+f"((c)[1]), "+f"((c)[2]), "+f"((c)[3]) \
        : "r"(a0), "r"(a1), "r"(a2), "r"(a3), "r"(b0), "r"(b1))

#define MMA16816(c, a, b) MMA_(c, (a)[0], (a)[1], (a)[2], (a)[3], (b)[0], (b)[1])

__device__ __forceinline__ uint32_t pack_bf16(float lo, float hi) {
    uint32_t r;
    asm("cvt.rn.bf16x2.f32 %0, %1, %2;" : "=r"(r) : "f"(hi), "f"(lo));
    return r;
}
__device__ __forceinline__ float bf16lo_f(uint32_t r) { return __int_as_float(r << 16); }
__device__ __forceinline__ float bf16hi_f(uint32_t r) { return __int_as_float(r & 0xffff0000u); }

// Fast exp on FMA pipe: e^x = 2^(x*log2e); deg-5 poly for 2^f, f in [-0.5,0.5].
__device__ __forceinline__ float fexp(float x) {
    float y = fmaxf(x * 1.4426950408889634f, -126.0f);
    int ni = __float2int_rn(y);
    float f = y - (float)ni;
    float p = 1.3333558e-3f;
    p = p * f + 9.6181291e-3f;
    p = p * f + 5.5504109e-2f;
    p = p * f + 2.4022651e-1f;
    p = p * f + 6.9314718e-1f;
    p = p * f + 1.0f;
    return __int_as_float(__float_as_int(p) + ni * 8388608);
}

// ---------------------------------------------------------------------------
// Kernel A: fp32 -> bf16 hi/lo split.  mode 0: x, 1: W_attn, 2: W_proj
// ---------------------------------------------------------------------------
__global__ void __launch_bounds__(256) split_kernel(const float4* __restrict__ in, int mode)
{
    __nv_bfloat16 *hi, *lo;
    if (mode == 0)      { hi = g_Xhi;  lo = g_Xlo;  }
    else if (mode == 1) { hi = g_Wahi; lo = g_Walo; }
    else                { hi = g_Wphi; lo = g_Wplo; }

    size_t i = (size_t)blockIdx.x * blockDim.x + threadIdx.x;
    float4 v = in[i];
    __nv_bfloat16 hx = __float2bfloat16(v.x), hy = __float2bfloat16(v.y);
    __nv_bfloat16 hz = __float2bfloat16(v.z), hw = __float2bfloat16(v.w);
    __nv_bfloat16 lx = __float2bfloat16(v.x - __bfloat162float(hx));
    __nv_bfloat16 ly = __float2bfloat16(v.y - __bfloat162float(hy));
    __nv_bfloat16 lz = __float2bfloat16(v.z - __bfloat162float(hz));
    __nv_bfloat16 lw = __float2bfloat16(v.w - __bfloat162float(hw));
    __nv_bfloat162* Hh = reinterpret_cast<__nv_bfloat162*>(hi + 4 * i);
    __nv_bfloat162* Ll = reinterpret_cast<__nv_bfloat162*>(lo + 4 * i);
    Hh[0] = __halves2bfloat162(hx, hy); Hh[1] = __halves2bfloat162(hz, hw);
    Ll[0] = __halves2bfloat162(lx, ly); Ll[1] = __halves2bfloat162(lz, lw);
}

// ---------------------------------------------------------------------------
// Kernel B: HMMA split-precision GEMM (as Round 3, epilogue mode 0 now emits
// bf16 hi/lo Q/K/V in [B,H,T,HD]; Q pre-scaled by 1/8).
// ---------------------------------------------------------------------------
#define BK_     32
#define ROWB    80
#define TILE_B  (128 * ROWB)
#define STAGE_B (4 * TILE_B)
#define GEMM_SMEM_BYTES (2 * STAGE_B)

__global__ void __launch_bounds__(256) hmma_gemm_kernel(
    const float* __restrict__ bias, float* __restrict__ Cout, int mode)
{
    extern __shared__ __align__(128) char smem[];
    const __nv_bfloat16 *Ahi, *Alo, *Bhi, *Blo;
    if (mode == 0) { Ahi = g_Xhi; Alo = g_Xlo; Bhi = g_Wahi; Blo = g_Walo; }
    else           { Ahi = g_Ohi; Alo = g_Olo; Bhi = g_Wphi; Blo = g_Wplo; }

    uint32_t sb = smem_u32(smem);
    int tid = threadIdx.x, lane = tid & 31, wid = tid >> 5;
    int bm = blockIdx.y * 128, bn = blockIdx.x * 128;
    int warp_m = wid >> 2;
    int warp_n = wid & 3;

    auto prefetch = [&](int chunk, int stage) {
        int k0 = chunk * BK_;
        uint32_t sbase = sb + stage * STAGE_B;
#pragma unroll
        for (int it = 0; it < 8; it++) {
            int idx = tid + it * 256;
            int tile = idx >> 9;
            int within = idx & 511;
            int row = within >> 2;
            int ch = within & 3;
            int rb = (tile < 2) ? bm : bn;
            const __nv_bfloat16* base =
                (tile == 0) ? Ahi : (tile == 1) ? Alo : (tile == 2) ? Bhi : Blo;
            const __nv_bfloat16* g = base + (size_t)(rb + row) * KD_ + k0 + ch * 8;
            CP_ASYNC16(sbase + tile * TILE_B + row * ROWB + ch * 16, g);
        }
        CP_COMMIT();
    };

    float acc[4][4][4];
#pragma unroll
    for (int mi = 0; mi < 4; mi++)
#pragma unroll
        for (int ni = 0; ni < 4; ni++)
#pragma unroll
            for (int r = 0; r < 4; r++) acc[mi][ni][r] = 0.f;

    prefetch(0, 0);
    prefetch(1, 1);

    const int NCH = KD_ / BK_;
    for (int ch = 0; ch < NCH; ch++) {
        if (ch < NCH - 1) CP_WAIT1(); else CP_WAIT0();
        __syncthreads();

        uint32_t sbase = sb + (ch & 1) * STAGE_B;
        uint32_t abase = sbase + (warp_m * 64) * ROWB;
        uint32_t bbase = sbase + 2 * TILE_B + (warp_n * 32) * ROWB;

#pragma unroll
        for (int ks = 0; ks < 2; ks++) {
            uint32_t ah[4][4], al[4][4], bh[4][2], bl[4][2];
            int acol = (ks * 16 + ((lane >> 4) << 3)) * 2;
#pragma unroll
            for (int mi = 0; mi < 4; mi++) {
                uint32_t addr = abase + (mi * 16 + (lane & 15)) * ROWB + acol;
                LDSM_X4(ah[mi][0], ah[mi][1], ah[mi][2], ah[mi][3], addr);
                addr += TILE_B;
                LDSM_X4(al[mi][0], al[mi][1], al[mi][2], al[mi][3], addr);
            }
            int brow = ((lane >> 4) << 3) + (lane & 7);
            int bcol = (ks * 16 + (((lane >> 3) & 1) << 3)) * 2;
#pragma unroll
            for (int np = 0; np < 2; np++) {
                uint32_t addr = bbase + (np * 16 + brow) * ROWB + bcol;
                LDSM_X4(bh[2*np][0], bh[2*np][1], bh[2*np+1][0], bh[2*np+1][1], addr);
                addr += TILE_B;
                LDSM_X4(bl[2*np][0], bl[2*np][1], bl[2*np+1][0], bl[2*np+1][1], addr);
            }
#pragma unroll
            for (int mi = 0; mi < 4; mi++)
#pragma unroll
                for (int ni = 0; ni < 4; ni++) {
                    MMA16816(acc[mi][ni], ah[mi], bh[ni]);
                    MMA16816(acc[mi][ni], ah[mi], bl[ni]);
                    MMA16816(acc[mi][ni], al[mi], bh[ni]);
                    if (mode == 0)
                        MMA16816(acc[mi][ni], al[mi], bl[ni]);
                }
        }
        __syncthreads();
        if (ch + 2 < NCH) prefetch(ch + 2, ch & 1);
    }

    int g = lane >> 2, t = lane & 3;
    if (mode == 0) {
#pragma unroll
        for (int mi = 0; mi < 4; mi++)
#pragma unroll
            for (int ni = 0; ni < 4; ni++) {
                int r0 = bm + warp_m * 64 + mi * 16 + g;
                int c0 = bn + warp_n * 32 + ni * 8 + t * 2;
#pragma unroll
                for (int e = 0; e < 4; e++) {
                    int m = r0 + (e >> 1) * 8;
                    int col = c0 + (e & 1);
                    float v = acc[mi][ni][e] + bias[col];
                    int b = m >> 11, tt = m & 2047;
                    int seg = col >> 10, cn = col & 1023;
                    int h = cn >> 6, d = cn & 63;
                    size_t o = (((size_t)(b * H_ + h) * T_) + tt) * HD_ + d;
                    if (seg == 0) v *= 0.125f;
                    __nv_bfloat16 vh = __float2bfloat16(v);
                    __nv_bfloat16 vl = __float2bfloat16(v - __bfloat162float(vh));
                    if (seg == 0)      { g_Qh[o] = vh; g_Ql[o] = vl; }
                    else if (seg == 1) { g_Kh[o] = vh; g_Kl[o] = vl; }
                    else               { g_Vh[o] = vh; g_Vl[o] = vl; }
                }
            }
    } else {
#pragma unroll
        for (int mi = 0; mi < 4; mi++)
#pragma unroll
            for (int ni = 0; ni < 4; ni++) {
                int r0 = bm + warp_m * 64 + mi * 16 + g;
                int c0 = bn + warp_n * 32 + ni * 8 + t * 2;
                float2 v0 = make_float2(acc[mi][ni][0] + bias[c0],
                                        acc[mi][ni][1] + bias[c0 + 1]);
                float2 v1 = make_float2(acc[mi][ni][2] + bias[c0],
                                        acc[mi][ni][3] + bias[c0 + 1]);
                *reinterpret_cast<float2*>(&Cout[(size_t)r0 * C_ + c0]) = v0;
                *reinterpret_cast<float2*>(&Cout[(size_t)(r0 + 8) * C_ + c0]) = v1;
            }
    }
}

// ---------------------------------------------------------------------------
// Kernel C: tensor-core flash attention.
// grid (T/128, BH), 256 threads (8 warps x 16 q-rows).
// K/V 64-key tiles, bf16 hi/lo, cp.async double buffer.
// S and PV via mma.m16n8k16 with 3-term splits; softmax with poly exp.
// ---------------------------------------------------------------------------
#define AROWB      144                     // 64 bf16 = 128B + 16B pad
#define KV_TILE_B  (64 * AROWB)            // 9216
#define KV_STAGE_B (4 * KV_TILE_B)         // 36864: Khi,Klo,Vhi,Vlo
#define ATTN_SMEM_BYTES (2 * KV_STAGE_B)   // 73728

__global__ void __launch_bounds__(256) attn_hmma_kernel()
{
    extern __shared__ __align__(128) char smem[];
    uint32_t sb = smem_u32(smem);
    int tid = threadIdx.x, lane = tid & 31, wid = tid >> 5;
    int bh = blockIdx.y, q0 = blockIdx.x * 128;
    size_t bhbase = (size_t)bh * T_ * HD_;

    // ---- stage Q tile (hi/lo) and load into registers ----
    {
        const __nv_bfloat16* Qh = g_Qh + bhbase + (size_t)q0 * HD_;
        const __nv_bfloat16* Ql = g_Ql + bhbase + (size_t)q0 * HD_;
#pragma unroll
        for (int it = 0; it < 8; it++) {
            int idx = tid + it * 256;
            int tile = idx >> 10, within = idx & 1023;
            int row = within >> 3, ch = within & 7;
            const __nv_bfloat16* src = (tile ? Ql : Qh) + (size_t)row * HD_ + ch * 8;
            CP_ASYNC16(sb + tile * (128 * AROWB) + row * AROWB + ch * 16, src);
        }
        CP_COMMIT(); CP_WAIT0();
        __syncthreads();
    }

    uint32_t qh[4][4], ql[4][4];
    {
        int arow = wid * 16 + (lane & 15);
        uint32_t acolb = ((lane >> 4) << 3) * 2;
#pragma unroll
        for (int ks = 0; ks < 4; ks++) {
            uint32_t addr = sb + arow * AROWB + ks * 32 + acolb;
            LDSM_X4(qh[ks][0], qh[ks][1], qh[ks][2], qh[ks][3], addr);
            LDSM_X4(ql[ks][0], ql[ks][1], ql[ks][2], ql[ks][3], addr + 128 * AROWB);
        }
    }
    __syncthreads();

    const __nv_bfloat16 *Kh = g_Kh + bhbase, *Kl = g_Kl + bhbase;
    const __nv_bfloat16 *Vh = g_Vh + bhbase, *Vl = g_Vl + bhbase;

    auto kv_prefetch = [&](int kt) {
        uint32_t sbase = sb + (kt & 1) * KV_STAGE_B;
        int k0 = kt * 64;
#pragma unroll
        for (int it = 0; it < 8; it++) {
            int idx = tid + it * 256;
            int tile = idx >> 9, within = idx & 511;
            int row = within >> 3, ch = within & 7;
            const __nv_bfloat16* base =
                (tile == 0) ? Kh : (tile == 1) ? Kl : (tile == 2) ? Vh : Vl;
            CP_ASYNC16(sbase + tile * KV_TILE_B + row * AROWB + ch * 16,
                       base + (size_t)(k0 + row) * HD_ + ch * 8);
        }
        CP_COMMIT();
    };

    float o[8][4];
#pragma unroll
    for (int j = 0; j < 8; j++)
#pragma unroll
        for (int r = 0; r < 4; r++) o[j][r] = 0.f;
    float m0 = -1e30f, m1 = -1e30f, l0 = 0.f, l1 = 0.f;

    kv_prefetch(0);

    for (int kt = 0; kt < T_ / 64; kt++) {
        CP_WAIT0();
        __syncthreads();
        if (kt + 1 < T_ / 64) kv_prefetch(kt + 1);
        uint32_t sbase = sb + (kt & 1) * KV_STAGE_B;

        // ---- S = Q K^T ----
        float s[8][4];
#pragma unroll
        for (int j = 0; j < 8; j++)
#pragma unroll
            for (int r = 0; r < 4; r++) s[j][r] = 0.f;

        int brow = ((lane >> 4) << 3) + (lane & 7);
        uint32_t bcolb = (((lane >> 3) & 1) << 3) * 2;
#pragma unroll
        for (int ks = 0; ks < 4; ks++) {
#pragma unroll
            for (int np = 0; np < 4; np++) {
                uint32_t addr = sbase + (np * 16 + brow) * AROWB + ks * 32 + bcolb;
                uint32_t k0r, k1r, k2r, k3r, l0r, l1r, l2r, l3r;
                LDSM_X4(k0r, k1r, k2r, k3r, addr);
                LDSM_X4(l0r, l1r, l2r, l3r, addr + KV_TILE_B);
                MMA_(s[2*np],   qh[ks][0], qh[ks][1], qh[ks][2], qh[ks][3], k0r, k1r);
                MMA_(s[2*np],   qh[ks][0], qh[ks][1], qh[ks][2], qh[ks][3], l0r, l1r);
                MMA_(s[2*np],   ql[ks][0], ql[ks][1], ql[ks][2], ql[ks][3], k0r, k1r);
                MMA_(s[2*np+1], qh[ks][0], qh[ks][1], qh[ks][2], qh[ks][3], k2r, k3r);
                MMA_(s[2*np+1], qh[ks][0], qh[ks][1], qh[ks][2], qh[ks][3], l2r, l3r);
                MMA_(s[2*np+1], ql[ks][0], ql[ks][1], ql[ks][2], ql[ks][3], k2r, k3r);
            }
        }

        // ---- online softmax ----
        float mt0 = -1e30f, mt1 = -1e30f;
#pragma unroll
        for (int j = 0; j < 8; j++) {
            mt0 = fmaxf(mt0, fmaxf(s[j][0], s[j][1]));
            mt1 = fmaxf(mt1, fmaxf(s[j][2], s[j][3]));
        }
        mt0 = fmaxf(mt0, __shfl_xor_sync(0xffffffffu, mt0, 1));
        mt0 = fmaxf(mt0, __shfl_xor_sync(0xffffffffu, mt0, 2));
        mt1 = fmaxf(mt1, __shfl_xor_sync(0xffffffffu, mt1, 1));
        mt1 = fmaxf(mt1, __shfl_xor_sync(0xffffffffu, mt1, 2));
        float mn0 = fmaxf(m0, mt0), mn1 = fmaxf(m1, mt1);
        float corr0 = fexp(m0 - mn0), corr1 = fexp(m1 - mn1);
        float sum0 = 0.f, sum1 = 0.f;
#pragma unroll
        for (int j = 0; j < 8; j++) {
            s[j][0] = fexp(s[j][0] - mn0);
            s[j][1] = fexp(s[j][1] - mn0);
            s[j][2] = fexp(s[j][2] - mn1);
            s[j][3] = fexp(s[j][3] - mn1);
            sum0 += s[j][0] + s[j][1];
            sum1 += s[j][2] + s[j][3];
        }
        sum0 += __shfl_xor_sync(0xffffffffu, sum0, 1);
        sum0 += __shfl_xor_sync(0xffffffffu, sum0, 2);
        sum1 += __shfl_xor_sync(0xffffffffu, sum1, 1);
        sum1 += __shfl_xor_sync(0xffffffffu, sum1, 2);
        l0 = l0 * corr0 + sum0;
        l1 = l1 * corr1 + sum1;
        m0 = mn0; m1 = mn1;
#pragma unroll
        for (int j = 0; j < 8; j++) {
            o[j][0] *= corr0; o[j][1] *= corr0;
            o[j][2] *= corr1; o[j][3] *= corr1;
        }

        // ---- O += P V ----
        uint32_t vbase = sbase + 2 * KV_TILE_B;
        uint32_t vrow = (lane & 15);
        uint32_t vcolb = ((lane >> 4) << 3) * 2;
#pragma unroll
        for (int ks = 0; ks < 4; ks++) {
            uint32_t ah0 = pack_bf16(s[2*ks][0],   s[2*ks][1]);
            uint32_t ah1 = pack_bf16(s[2*ks][2],   s[2*ks][3]);
            uint32_t ah2 = pack_bf16(s[2*ks+1][0], s[2*ks+1][1]);
            uint32_t ah3 = pack_bf16(s[2*ks+1][2], s[2*ks+1][3]);
            uint32_t al0 = pack_bf16(s[2*ks][0]   - bf16lo_f(ah0), s[2*ks][1]   - bf16hi_f(ah0));
            uint32_t al1 = pack_bf16(s[2*ks][2]   - bf16lo_f(ah1), s[2*ks][3]   - bf16hi_f(ah1));
            uint32_t al2 = pack_bf16(s[2*ks+1][0] - bf16lo_f(ah2), s[2*ks+1][1] - bf16hi_f(ah2));
            uint32_t al3 = pack_bf16(s[2*ks+1][2] - bf16lo_f(ah3), s[2*ks+1][3] - bf16hi_f(ah3));
#pragma unroll
            for (int jp = 0; jp < 4; jp++) {
                uint32_t addr = vbase + (ks * 16 + vrow) * AROWB + jp * 32 + vcolb;
                uint32_t v0, v1, v2, v3, w0, w1, w2, w3;
                LDSM_X4_T(v0, v1, v2, v3, addr);
                LDSM_X4_T(w0, w1, w2, w3, addr + KV_TILE_B);
                MMA_(o[2*jp],   ah0, ah1, ah2, ah3, v0, v1);
                MMA_(o[2*jp],   ah0, ah1, ah2, ah3, w0, w1);
                MMA_(o[2*jp],   al0, al1, al2, al3, v0, v1);
                MMA_(o[2*jp+1], ah0, ah1, ah2, ah3, v2, v3);
                MMA_(o[2*jp+1], ah0, ah1, ah2, ah3, w2, w3);
                MMA_(o[2*jp+1], al0, al1, al2, al3, v2, v3);
            }
        }
    }

    // ---- finalize: O /= l, write bf16 hi/lo to g_O ----
    int g = lane >> 2, t = lane & 3;
    float inv0 = 1.0f / l0, inv1 = 1.0f / l1;
    int b = bh >> 4, h = bh & 15;
    int row0 = q0 + wid * 16 + g;
    size_t ob0 = ((size_t)(b * T_) + row0) * C_ + h * 64 + t * 2;
    size_t ob1 = ob0 + (size_t)8 * C_;
#pragma unroll
    for (int j = 0; j < 8; j++) {
        float v0 = o[j][0] * inv0, v1 = o[j][1] * inv0;
        float v2 = o[j][2] * inv1, v3 = o[j][3] * inv1;
        uint32_t h0 = pack_bf16(v0, v1);
        uint32_t h1 = pack_bf16(v2, v3);
        uint32_t l0p = pack_bf16(v0 - bf16lo_f(h0), v1 - bf16hi_f(h0));
        uint32_t l1p = pack_bf16(v2 - bf16lo_f(h1), v3 - bf16hi_f(h1));
        *reinterpret_cast<uint32_t*>(g_Ohi + ob0 + j * 8) = h0;
        *reinterpret_cast<uint32_t*>(g_Ohi + ob1 + j * 8) = h1;
        *reinterpret_cast<uint32_t*>(g_Olo + ob0 + j * 8) = l0p;
        *reinterpret_cast<uint32_t*>(g_Olo + ob1 + j * 8) = l1p;
    }
}

// ---------------------------------------------------------------------------
extern "C" void kernel_launch(void* const* d_in, const int* in_sizes, int n_in,
                              void* d_out, int out_size)
{
    const float* x      = (const float*)d_in[0];
    const float* W_attn = (const float*)d_in[1];
    const float* b_attn = (const float*)d_in[2];
    const float* W_proj = (const float*)d_in[3];
    const float* b_proj = (const float*)d_in[4];
    float* out = (float*)d_out;

    cudaFuncSetAttribute(hmma_gemm_kernel,
                         cudaFuncAttributeMaxDynamicSharedMemorySize, GEMM_SMEM_BYTES);
    cudaFuncSetAttribute(attn_hmma_kernel,
                         cudaFuncAttributeMaxDynamicSharedMemorySize, ATTN_SMEM_BYTES);

    split_kernel<<<(B_*T_*C_) / 4 / 256, 256>>>((const float4*)x, 0);
    split_kernel<<<(3*C_*C_)  / 4 / 256, 256>>>((const float4*)W_attn, 1);
    split_kernel<<<(C_*C_)    / 4 / 256, 256>>>((const float4*)W_proj, 2);

    hmma_gemm_kernel<<<dim3(3 * C_ / 128, B_ * T_ / 128), 256, GEMM_SMEM_BYTES>>>(
        b_attn, nullptr, 0);

    attn_hmma_kernel<<<dim3(T_ / 128, BH_), 256, ATTN_SMEM_BYTES>>>();

    hmma_gemm_kernel<<<dim3(C_ / 128, B_ * T_ / 128), 256, GEMM_SMEM_BYTES>>>(
        b_proj, out, 1);
}

// round 5
// speedup vs baseline: 2.8995x; 1.0934x over previous
#include <cuda_runtime.h>
#include <cuda_bf16.h>
#include <cstdint>

#define B_  4
#define T_  2048
#define C_  1024
#define H_  16
#define HD_ 64
#define BH_ (B_*H_)
#define KD_ 1024

// ---------------------------------------------------------------------------
// Device-global scratch
// ---------------------------------------------------------------------------
__device__ __nv_bfloat16 g_Qh[(size_t)BH_*T_*HD_], g_Ql[(size_t)BH_*T_*HD_];
__device__ __nv_bfloat16 g_Kh[(size_t)BH_*T_*HD_], g_Kl[(size_t)BH_*T_*HD_];
__device__ __nv_bfloat16 g_Vh[(size_t)BH_*T_*HD_], g_Vl[(size_t)BH_*T_*HD_];

__device__ __nv_bfloat16 g_Xhi[(size_t)B_*T_*C_],   g_Xlo[(size_t)B_*T_*C_];
__device__ __nv_bfloat16 g_Wahi[(size_t)3*C_*C_],   g_Walo[(size_t)3*C_*C_];
__device__ __nv_bfloat16 g_Wphi[(size_t)C_*C_],     g_Wplo[(size_t)C_*C_];
__device__ __nv_bfloat16 g_Ohi[(size_t)B_*T_*C_],   g_Olo[(size_t)B_*T_*C_];

// ---------------------------------------------------------------------------
// Helpers
// ---------------------------------------------------------------------------
__device__ __forceinline__ uint32_t smem_u32(const void* p) {
    uint32_t a;
    asm("{ .reg .u64 t; cvta.to.shared.u64 t, %1; cvt.u32.u64 %0, t; }"
        : "=r"(a) : "l"(p));
    return a;
}

#define CP_ASYNC16(dst, src) \
    asm volatile("cp.async.cg.shared.global [%0], [%1], 16;" :: "r"(dst), "l"(src))
#define CP_COMMIT() asm volatile("cp.async.commit_group;" ::: "memory")
#define CP_WAIT1()  asm volatile("cp.async.wait_group 1;" ::: "memory")
#define CP_WAIT0()  asm volatile("cp.async.wait_group 0;" ::: "memory")

#define LDSM_X4(r0, r1, r2, r3, addr) \
    asm volatile("ldmatrix.sync.aligned.m8n8.x4.shared.b16 {%0,%1,%2,%3}, [%4];" \
        : "=r"(r0), "=r"(r1), "=r"(r2), "=r"(r3) : "r"(addr))
#define LDSM_X4_T(r0, r1, r2, r3, addr) \
    asm volatile("ldmatrix.sync.aligned.m8n8.x4.trans.shared.b16 {%0,%1,%2,%3}, [%4];" \
        : "=r"(r0), "=r"(r1), "=r"(r2), "=r"(r3) : "r"(addr))

#define MMA_(c, a0, a1, a2, a3, b0, b1) \
    asm volatile("mma.sync.aligned.m16n8k16.row.col.f32.bf16.bf16.f32 " \
        "{%0,%1,%2,%3}, {%4,%5,%6,%7}, {%8,%9}, {%0,%1,%2,%3};" \
        : "+f"((c)[0]), "+f"((c)[1]), "+f"((c)[2]), "+f"((c)[3]) \
        : "r"(a0), "r"(a1), "r"(a2), "r"(a3), "r"(b0), "r"(b1))

#define MMA16816(c, a, b) MMA_(c, (a)[0], (a)[1], (a)[2], (a)[3], (b)[0], (b)[1])

__device__ __forceinline__ uint32_t pack_bf16(float lo, float hi) {
    uint32_t r;
    asm("cvt.rn.bf16x2.f32 %0, %1, %2;" : "=r"(r) : "f"(hi), "f"(lo));
    return r;
}
__device__ __forceinline__ float bf16lo_f(uint32_t r) { return __int_as_float(r << 16); }
__device__ __forceinline__ float bf16hi_f(uint32_t r) { return __int_as_float(r & 0xffff0000u); }

// Fast exp on FMA pipe.
__device__ __forceinline__ float fexp(float x) {
    float y = fmaxf(x * 1.4426950408889634f, -126.0f);
    int ni = __float2int_rn(y);
    float f = y - (float)ni;
    float p = 1.3333558e-3f;
    p = p * f + 9.6181291e-3f;
    p = p * f + 5.5504109e-2f;
    p = p * f + 2.4022651e-1f;
    p = p * f + 6.9314718e-1f;
    p = p * f + 1.0f;
    return __int_as_float(__float_as_int(p) + ni * 8388608);
}

// ---------------------------------------------------------------------------
// Kernel A: fp32 -> bf16 hi/lo split.  mode 0: x, 1: W_attn, 2: W_proj
// ---------------------------------------------------------------------------
__global__ void __launch_bounds__(256) split_kernel(const float4* __restrict__ in, int mode)
{
    __nv_bfloat16 *hi, *lo;
    if (mode == 0)      { hi = g_Xhi;  lo = g_Xlo;  }
    else if (mode == 1) { hi = g_Wahi; lo = g_Walo; }
    else                { hi = g_Wphi; lo = g_Wplo; }

    size_t i = (size_t)blockIdx.x * blockDim.x + threadIdx.x;
    float4 v = in[i];
    __nv_bfloat16 hx = __float2bfloat16(v.x), hy = __float2bfloat16(v.y);
    __nv_bfloat16 hz = __float2bfloat16(v.z), hw = __float2bfloat16(v.w);
    __nv_bfloat16 lx = __float2bfloat16(v.x - __bfloat162float(hx));
    __nv_bfloat16 ly = __float2bfloat16(v.y - __bfloat162float(hy));
    __nv_bfloat16 lz = __float2bfloat16(v.z - __bfloat162float(hz));
    __nv_bfloat16 lw = __float2bfloat16(v.w - __bfloat162float(hw));
    __nv_bfloat162* Hh = reinterpret_cast<__nv_bfloat162*>(hi + 4 * i);
    __nv_bfloat162* Ll = reinterpret_cast<__nv_bfloat162*>(lo + 4 * i);
    Hh[0] = __halves2bfloat162(hx, hy); Hh[1] = __halves2bfloat162(hz, hw);
    Ll[0] = __halves2bfloat162(lx, ly); Ll[1] = __halves2bfloat162(lz, lw);
}

// ---------------------------------------------------------------------------
// Kernel B: HMMA split-precision GEMM (3 terms, term-major MMA issue order).
// ---------------------------------------------------------------------------
#define BK_     32
#define ROWB    80
#define TILE_B  (128 * ROWB)
#define STAGE_B (4 * TILE_B)
#define GEMM_SMEM_BYTES (2 * STAGE_B)

__global__ void __launch_bounds__(256) hmma_gemm_kernel(
    const float* __restrict__ bias, float* __restrict__ Cout, int mode)
{
    extern __shared__ __align__(128) char smem[];
    const __nv_bfloat16 *Ahi, *Alo, *Bhi, *Blo;
    if (mode == 0) { Ahi = g_Xhi; Alo = g_Xlo; Bhi = g_Wahi; Blo = g_Walo; }
    else           { Ahi = g_Ohi; Alo = g_Olo; Bhi = g_Wphi; Blo = g_Wplo; }

    uint32_t sb = smem_u32(smem);
    int tid = threadIdx.x, lane = tid & 31, wid = tid >> 5;
    int bm = blockIdx.y * 128, bn = blockIdx.x * 128;
    int warp_m = wid >> 2;
    int warp_n = wid & 3;

    auto prefetch = [&](int chunk, int stage) {
        int k0 = chunk * BK_;
        uint32_t sbase = sb + stage * STAGE_B;
#pragma unroll
        for (int it = 0; it < 8; it++) {
            int idx = tid + it * 256;
            int tile = idx >> 9;
            int within = idx & 511;
            int row = within >> 2;
            int ch = within & 3;
            int rb = (tile < 2) ? bm : bn;
            const __nv_bfloat16* base =
                (tile == 0) ? Ahi : (tile == 1) ? Alo : (tile == 2) ? Bhi : Blo;
            const __nv_bfloat16* g = base + (size_t)(rb + row) * KD_ + k0 + ch * 8;
            CP_ASYNC16(sbase + tile * TILE_B + row * ROWB + ch * 16, g);
        }
        CP_COMMIT();
    };

    float acc[4][4][4];
#pragma unroll
    for (int mi = 0; mi < 4; mi++)
#pragma unroll
        for (int ni = 0; ni < 4; ni++)
#pragma unroll
            for (int r = 0; r < 4; r++) acc[mi][ni][r] = 0.f;

    prefetch(0, 0);
    prefetch(1, 1);

    const int NCH = KD_ / BK_;
    for (int ch = 0; ch < NCH; ch++) {
        if (ch < NCH - 1) CP_WAIT1(); else CP_WAIT0();
        __syncthreads();

        uint32_t sbase = sb + (ch & 1) * STAGE_B;
        uint32_t abase = sbase + (warp_m * 64) * ROWB;
        uint32_t bbase = sbase + 2 * TILE_B + (warp_n * 32) * ROWB;

#pragma unroll
        for (int ks = 0; ks < 2; ks++) {
            uint32_t ah[4][4], al[4][4], bh[4][2], bl[4][2];
            int acol = (ks * 16 + ((lane >> 4) << 3)) * 2;
#pragma unroll
            for (int mi = 0; mi < 4; mi++) {
                uint32_t addr = abase + (mi * 16 + (lane & 15)) * ROWB + acol;
                LDSM_X4(ah[mi][0], ah[mi][1], ah[mi][2], ah[mi][3], addr);
                addr += TILE_B;
                LDSM_X4(al[mi][0], al[mi][1], al[mi][2], al[mi][3], addr);
            }
            int brow = ((lane >> 4) << 3) + (lane & 7);
            int bcol = (ks * 16 + (((lane >> 3) & 1) << 3)) * 2;
#pragma unroll
            for (int np = 0; np < 2; np++) {
                uint32_t addr = bbase + (np * 16 + brow) * ROWB + bcol;
                LDSM_X4(bh[2*np][0], bh[2*np][1], bh[2*np+1][0], bh[2*np+1][1], addr);
                addr += TILE_B;
                LDSM_X4(bl[2*np][0], bl[2*np][1], bl[2*np+1][0], bl[2*np+1][1], addr);
            }
            // term-major: consecutive MMAs hit different accumulators
#pragma unroll
            for (int mi = 0; mi < 4; mi++)
#pragma unroll
                for (int ni = 0; ni < 4; ni++)
                    MMA16816(acc[mi][ni], ah[mi], bh[ni]);
#pragma unroll
            for (int mi = 0; mi < 4; mi++)
#pragma unroll
                for (int ni = 0; ni < 4; ni++)
                    MMA16816(acc[mi][ni], ah[mi], bl[ni]);
#pragma unroll
            for (int mi = 0; mi < 4; mi++)
#pragma unroll
                for (int ni = 0; ni < 4; ni++)
                    MMA16816(acc[mi][ni], al[mi], bh[ni]);
        }
        __syncthreads();
        if (ch + 2 < NCH) prefetch(ch + 2, ch & 1);
    }

    int g = lane >> 2, t = lane & 3;
    if (mode == 0) {
#pragma unroll
        for (int mi = 0; mi < 4; mi++)
#pragma unroll
            for (int ni = 0; ni < 4; ni++) {
                int r0 = bm + warp_m * 64 + mi * 16 + g;
                int c0 = bn + warp_n * 32 + ni * 8 + t * 2;
#pragma unroll
                for (int e = 0; e < 4; e++) {
                    int m = r0 + (e >> 1) * 8;
                    int col = c0 + (e & 1);
                    float v = acc[mi][ni][e] + bias[col];
                    int b = m >> 11, tt = m & 2047;
                    int seg = col >> 10, cn = col & 1023;
                    int h = cn >> 6, d = cn & 63;
                    size_t o = (((size_t)(b * H_ + h) * T_) + tt) * HD_ + d;
                    if (seg == 0) v *= 0.125f;
                    __nv_bfloat16 vh = __float2bfloat16(v);
                    __nv_bfloat16 vl = __float2bfloat16(v - __bfloat162float(vh));
                    if (seg == 0)      { g_Qh[o] = vh; g_Ql[o] = vl; }
                    else if (seg == 1) { g_Kh[o] = vh; g_Kl[o] = vl; }
                    else               { g_Vh[o] = vh; g_Vl[o] = vl; }
                }
            }
    } else {
#pragma unroll
        for (int mi = 0; mi < 4; mi++)
#pragma unroll
            for (int ni = 0; ni < 4; ni++) {
                int r0 = bm + warp_m * 64 + mi * 16 + g;
                int c0 = bn + warp_n * 32 + ni * 8 + t * 2;
                float2 v0 = make_float2(acc[mi][ni][0] + bias[c0],
                                        acc[mi][ni][1] + bias[c0 + 1]);
                float2 v1 = make_float2(acc[mi][ni][2] + bias[c0],
                                        acc[mi][ni][3] + bias[c0 + 1]);
                *reinterpret_cast<float2*>(&Cout[(size_t)r0 * C_ + c0]) = v0;
                *reinterpret_cast<float2*>(&Cout[(size_t)(r0 + 8) * C_ + c0]) = v1;
            }
    }
}

// ---------------------------------------------------------------------------
// Kernel C: tensor-core flash attention (term-major MMA issue order).
// ---------------------------------------------------------------------------
#define AROWB      144
#define KV_TILE_B  (64 * AROWB)
#define KV_STAGE_B (4 * KV_TILE_B)
#define ATTN_SMEM_BYTES (2 * KV_STAGE_B)

__global__ void __launch_bounds__(256) attn_hmma_kernel()
{
    extern __shared__ __align__(128) char smem[];
    uint32_t sb = smem_u32(smem);
    int tid = threadIdx.x, lane = tid & 31, wid = tid >> 5;
    int bh = blockIdx.y, q0 = blockIdx.x * 128;
    size_t bhbase = (size_t)bh * T_ * HD_;

    {
        const __nv_bfloat16* Qh = g_Qh + bhbase + (size_t)q0 * HD_;
        const __nv_bfloat16* Ql = g_Ql + bhbase + (size_t)q0 * HD_;
#pragma unroll
        for (int it = 0; it < 8; it++) {
            int idx = tid + it * 256;
            int tile = idx >> 10, within = idx & 1023;
            int row = within >> 3, ch = within & 7;
            const __nv_bfloat16* src = (tile ? Ql : Qh) + (size_t)row * HD_ + ch * 8;
            CP_ASYNC16(sb + tile * (128 * AROWB) + row * AROWB + ch * 16, src);
        }
        CP_COMMIT(); CP_WAIT0();
        __syncthreads();
    }

    uint32_t qh[4][4], ql[4][4];
    {
        int arow = wid * 16 + (lane & 15);
        uint32_t acolb = ((lane >> 4) << 3) * 2;
#pragma unroll
        for (int ks = 0; ks < 4; ks++) {
            uint32_t addr = sb + arow * AROWB + ks * 32 + acolb;
            LDSM_X4(qh[ks][0], qh[ks][1], qh[ks][2], qh[ks][3], addr);
            LDSM_X4(ql[ks][0], ql[ks][1], ql[ks][2], ql[ks][3], addr + 128 * AROWB);
        }
    }
    __syncthreads();

    const __nv_bfloat16 *Kh = g_Kh + bhbase, *Kl = g_Kl + bhbase;
    const __nv_bfloat16 *Vh = g_Vh + bhbase, *Vl = g_Vl + bhbase;

    auto kv_prefetch = [&](int kt) {
        uint32_t sbase = sb + (kt & 1) * KV_STAGE_B;
        int k0 = kt * 64;
#pragma unroll
        for (int it = 0; it < 8; it++) {
            int idx = tid + it * 256;
            int tile = idx >> 9, within = idx & 511;
            int row = within >> 3, ch = within & 7;
            const __nv_bfloat16* base =
                (tile == 0) ? Kh : (tile == 1) ? Kl : (tile == 2) ? Vh : Vl;
            CP_ASYNC16(sbase + tile * KV_TILE_B + row * AROWB + ch * 16,
                       base + (size_t)(k0 + row) * HD_ + ch * 8);
        }
        CP_COMMIT();
    };

    float o[8][4];
#pragma unroll
    for (int j = 0; j < 8; j++)
#pragma unroll
        for (int r = 0; r < 4; r++) o[j][r] = 0.f;
    float m0 = -1e30f, m1 = -1e30f, l0 = 0.f, l1 = 0.f;

    kv_prefetch(0);

    for (int kt = 0; kt < T_ / 64; kt++) {
        CP_WAIT0();
        __syncthreads();
        if (kt + 1 < T_ / 64) kv_prefetch(kt + 1);
        uint32_t sbase = sb + (kt & 1) * KV_STAGE_B;

        // ---- S = Q K^T (term-major over np pairs: 4 independent accs) ----
        float s[8][4];
#pragma unroll
        for (int j = 0; j < 8; j++)
#pragma unroll
            for (int r = 0; r < 4; r++) s[j][r] = 0.f;

        int brow = ((lane >> 4) << 3) + (lane & 7);
        uint32_t bcolb = (((lane >> 3) & 1) << 3) * 2;
#pragma unroll
        for (int ks = 0; ks < 4; ks++) {
#pragma unroll
            for (int npp = 0; npp < 2; npp++) {
                uint32_t a0 = sbase + ((2*npp) * 16 + brow) * AROWB + ks * 32 + bcolb;
                uint32_t a1 = sbase + ((2*npp+1) * 16 + brow) * AROWB + ks * 32 + bcolb;
                uint32_t kh0[4], kh1[4], kl0[4], kl1[4];
                LDSM_X4(kh0[0], kh0[1], kh0[2], kh0[3], a0);
                LDSM_X4(kh1[0], kh1[1], kh1[2], kh1[3], a1);
                LDSM_X4(kl0[0], kl0[1], kl0[2], kl0[3], a0 + KV_TILE_B);
                LDSM_X4(kl1[0], kl1[1], kl1[2], kl1[3], a1 + KV_TILE_B);
                float* s0 = s[4*npp+0]; float* s1 = s[4*npp+1];
                float* s2 = s[4*npp+2]; float* s3 = s[4*npp+3];
                MMA_(s0, qh[ks][0], qh[ks][1], qh[ks][2], qh[ks][3], kh0[0], kh0[1]);
                MMA_(s1, qh[ks][0], qh[ks][1], qh[ks][2], qh[ks][3], kh0[2], kh0[3]);
                MMA_(s2, qh[ks][0], qh[ks][1], qh[ks][2], qh[ks][3], kh1[0], kh1[1]);
                MMA_(s3, qh[ks][0], qh[ks][1], qh[ks][2], qh[ks][3], kh1[2], kh1[3]);
                MMA_(s0, qh[ks][0], qh[ks][1], qh[ks][2], qh[ks][3], kl0[0], kl0[1]);
                MMA_(s1, qh[ks][0], qh[ks][1], qh[ks][2], qh[ks][3], kl0[2], kl0[3]);
                MMA_(s2, qh[ks][0], qh[ks][1], qh[ks][2], qh[ks][3], kl1[0], kl1[1]);
                MMA_(s3, qh[ks][0], qh[ks][1], qh[ks][2], qh[ks][3], kl1[2], kl1[3]);
                MMA_(s0, ql[ks][0], ql[ks][1], ql[ks][2], ql[ks][3], kh0[0], kh0[1]);
                MMA_(s1, ql[ks][0], ql[ks][1], ql[ks][2], ql[ks][3], kh0[2], kh0[3]);
                MMA_(s2, ql[ks][0], ql[ks][1], ql[ks][2], ql[ks][3], kh1[0], kh1[1]);
                MMA_(s3, ql[ks][0], ql[ks][1], ql[ks][2], ql[ks][3], kh1[2], kh1[3]);
            }
        }

        // Note: s index mapping unchanged: s[2*np], s[2*np+1] == s[4*npp + ...]

        // ---- online softmax ----
        float mt0 = -1e30f, mt1 = -1e30f;
#pragma unroll
        for (int j = 0; j < 8; j++) {
            mt0 = fmaxf(mt0, fmaxf(s[j][0], s[j][1]));
            mt1 = fmaxf(mt1, fmaxf(s[j][2], s[j][3]));
        }
        mt0 = fmaxf(mt0, __shfl_xor_sync(0xffffffffu, mt0, 1));
        mt0 = fmaxf(mt0, __shfl_xor_sync(0xffffffffu, mt0, 2));
        mt1 = fmaxf(mt1, __shfl_xor_sync(0xffffffffu, mt1, 1));
        mt1 = fmaxf(mt1, __shfl_xor_sync(0xffffffffu, mt1, 2));
        float mn0 = fmaxf(m0, mt0), mn1 = fmaxf(m1, mt1);
        float corr0 = fexp(m0 - mn0), corr1 = fexp(m1 - mn1);
        float sum0 = 0.f, sum1 = 0.f;
#pragma unroll
        for (int j = 0; j < 8; j++) {
            s[j][0] = fexp(s[j][0] - mn0);
            s[j][1] = fexp(s[j][1] - mn0);
            s[j][2] = fexp(s[j][2] - mn1);
            s[j][3] = fexp(s[j][3] - mn1);
            sum0 += s[j][0] + s[j][1];
            sum1 += s[j][2] + s[j][3];
        }
        sum0 += __shfl_xor_sync(0xffffffffu, sum0, 1);
        sum0 += __shfl_xor_sync(0xffffffffu, sum0, 2);
        sum1 += __shfl_xor_sync(0xffffffffu, sum1, 1);
        sum1 += __shfl_xor_sync(0xffffffffu, sum1, 2);
        l0 = l0 * corr0 + sum0;
        l1 = l1 * corr1 + sum1;
        m0 = mn0; m1 = mn1;
#pragma unroll
        for (int j = 0; j < 8; j++) {
            o[j][0] *= corr0; o[j][1] *= corr0;
            o[j][2] *= corr1; o[j][3] *= corr1;
        }

        // ---- O += P V (term-major over jp pairs) ----
        uint32_t vbase = sbase + 2 * KV_TILE_B;
        uint32_t vrow = (lane & 15);
        uint32_t vcolb = ((lane >> 4) << 3) * 2;
#pragma unroll
        for (int ks = 0; ks < 4; ks++) {
            uint32_t ah0 = pack_bf16(s[2*ks][0],   s[2*ks][1]);
            uint32_t ah1 = pack_bf16(s[2*ks][2],   s[2*ks][3]);
            uint32_t ah2 = pack_bf16(s[2*ks+1][0], s[2*ks+1][1]);
            uint32_t ah3 = pack_bf16(s[2*ks+1][2], s[2*ks+1][3]);
            uint32_t al0 = pack_bf16(s[2*ks][0]   - bf16lo_f(ah0), s[2*ks][1]   - bf16hi_f(ah0));
            uint32_t al1 = pack_bf16(s[2*ks][2]   - bf16lo_f(ah1), s[2*ks][3]   - bf16hi_f(ah1));
            uint32_t al2 = pack_bf16(s[2*ks+1][0] - bf16lo_f(ah2), s[2*ks+1][1] - bf16hi_f(ah2));
            uint32_t al3 = pack_bf16(s[2*ks+1][2] - bf16lo_f(ah3), s[2*ks+1][3] - bf16hi_f(ah3));
#pragma unroll
            for (int jpp = 0; jpp < 2; jpp++) {
                uint32_t a0 = vbase + (ks * 16 + vrow) * AROWB + (2*jpp) * 32 + vcolb;
                uint32_t a1 = vbase + (ks * 16 + vrow) * AROWB + (2*jpp+1) * 32 + vcolb;
                uint32_t vh0[4], vh1[4], vl0[4], vl1[4];
                LDSM_X4_T(vh0[0], vh0[1], vh0[2], vh0[3], a0);
                LDSM_X4_T(vh1[0], vh1[1], vh1[2], vh1[3], a1);
                LDSM_X4_T(vl0[0], vl0[1], vl0[2], vl0[3], a0 + KV_TILE_B);
                LDSM_X4_T(vl1[0], vl1[1], vl1[2], vl1[3], a1 + KV_TILE_B);
                float* o0 = o[4*jpp+0]; float* o1 = o[4*jpp+1];
                float* o2 = o[4*jpp+2]; float* o3 = o[4*jpp+3];
                MMA_(o0, ah0, ah1, ah2, ah3, vh0[0], vh0[1]);
                MMA_(o1, ah0, ah1, ah2, ah3, vh0[2], vh0[3]);
                MMA_(o2, ah0, ah1, ah2, ah3, vh1[0], vh1[1]);
                MMA_(o3, ah0, ah1, ah2, ah3, vh1[2], vh1[3]);
                MMA_(o0, ah0, ah1, ah2, ah3, vl0[0], vl0[1]);
                MMA_(o1, ah0, ah1, ah2, ah3, vl0[2], vl0[3]);
                MMA_(o2, ah0, ah1, ah2, ah3, vl1[0], vl1[1]);
                MMA_(o3, ah0, ah1, ah2, ah3, vl1[2], vl1[3]);
                MMA_(o0, al0, al1, al2, al3, vh0[0], vh0[1]);
                MMA_(o1, al0, al1, al2, al3, vh0[2], vh0[3]);
                MMA_(o2, al0, al1, al2, al3, vh1[0], vh1[1]);
                MMA_(o3, al0, al1, al2, al3, vh1[2], vh1[3]);
            }
        }
    }

    // ---- finalize ----
    int g = lane >> 2, t = lane & 3;
    float inv0 = 1.0f / l0, inv1 = 1.0f / l1;
    int b = bh >> 4, h = bh & 15;
    int row0 = q0 + wid * 16 + g;
    size_t ob0 = ((size_t)(b * T_) + row0) * C_ + h * 64 + t * 2;
    size_t ob1 = ob0 + (size_t)8 * C_;
#pragma unroll
    for (int j = 0; j < 8; j++) {
        float v0 = o[j][0] * inv0, v1 = o[j][1] * inv0;
        float v2 = o[j][2] * inv1, v3 = o[j][3] * inv1;
        uint32_t h0 = pack_bf16(v0, v1);
        uint32_t h1 = pack_bf16(v2, v3);
        uint32_t l0p = pack_bf16(v0 - bf16lo_f(h0), v1 - bf16hi_f(h0));
        uint32_t l1p = pack_bf16(v2 - bf16lo_f(h1), v3 - bf16hi_f(h1));
        *reinterpret_cast<uint32_t*>(g_Ohi + ob0 + j * 8) = h0;
        *reinterpret_cast<uint32_t*>(g_Ohi + ob1 + j * 8) = h1;
        *reinterpret_cast<uint32_t*>(g_Olo + ob0 + j * 8) = l0p;
        *reinterpret_cast<uint32_t*>(g_Olo + ob1 + j * 8) = l1p;
    }
}

// ---------------------------------------------------------------------------
extern "C" void kernel_launch(void* const* d_in, const int* in_sizes, int n_in,
                              void* d_out, int out_size)
{
    const float* x      = (const float*)d_in[0];
    const float* W_attn = (const float*)d_in[1];
    const float* b_attn = (const float*)d_in[2];
    const float* W_proj = (const float*)d_in[3];
    const float* b_proj = (const float*)d_in[4];
    float* out = (float*)d_out;

    cudaFuncSetAttribute(hmma_gemm_kernel,
                         cudaFuncAttributeMaxDynamicSharedMemorySize, GEMM_SMEM_BYTES);
    cudaFuncSetAttribute(attn_hmma_kernel,
                         cudaFuncAttributeMaxDynamicSharedMemorySize, ATTN_SMEM_BYTES);

    split_kernel<<<(B_*T_*C_) / 4 / 256, 256>>>((const float4*)x, 0);
    split_kernel<<<(3*C_*C_)  / 4 / 256, 256>>>((const float4*)W_attn, 1);
    split_kernel<<<(C_*C_)    / 4 / 256, 256>>>((const float4*)W_proj, 2);

    hmma_gemm_kernel<<<dim3(3 * C_ / 128, B_ * T_ / 128), 256, GEMM_SMEM_BYTES>>>(
        b_attn, nullptr, 0);

    attn_hmma_kernel<<<dim3(T_ / 128, BH_), 256, ATTN_SMEM_BYTES>>>();

    hmma_gemm_kernel<<<dim3(C_ / 128, B_ * T_ / 128), 256, GEMM_SMEM_BYTES>>>(
        b_proj, out, 1);
}

// round 6
// speedup vs baseline: 3.1621x; 1.0906x over previous
#include <cuda_runtime.h>
#include <cuda_bf16.h>
#include <cstdint>

#define B_  4
#define T_  2048
#define C_  1024
#define H_  16
#define HD_ 64
#define BH_ (B_*H_)
#define KD_ 1024

// ---------------------------------------------------------------------------
// Device-global scratch
// ---------------------------------------------------------------------------
__device__ __nv_bfloat16 g_Qh[(size_t)BH_*T_*HD_], g_Ql[(size_t)BH_*T_*HD_];
__device__ __nv_bfloat16 g_Kh[(size_t)BH_*T_*HD_], g_Kl[(size_t)BH_*T_*HD_];
__device__ __nv_bfloat16 g_Vh[(size_t)BH_*T_*HD_], g_Vl[(size_t)BH_*T_*HD_];

__device__ __nv_bfloat16 g_Xhi[(size_t)B_*T_*C_],   g_Xlo[(size_t)B_*T_*C_];
__device__ __nv_bfloat16 g_Wahi[(size_t)3*C_*C_],   g_Walo[(size_t)3*C_*C_];
__device__ __nv_bfloat16 g_Wphi[(size_t)C_*C_],     g_Wplo[(size_t)C_*C_];
__device__ __nv_bfloat16 g_Ohi[(size_t)B_*T_*C_],   g_Olo[(size_t)B_*T_*C_];

// ---------------------------------------------------------------------------
// Helpers
// ---------------------------------------------------------------------------
__device__ __forceinline__ uint32_t smem_u32(const void* p) {
    uint32_t a;
    asm("{ .reg .u64 t; cvta.to.shared.u64 t, %1; cvt.u32.u64 %0, t; }"
        : "=r"(a) : "l"(p));
    return a;
}

#define CP_ASYNC16(dst, src) \
    asm volatile("cp.async.cg.shared.global [%0], [%1], 16;" :: "r"(dst), "l"(src))
#define CP_COMMIT() asm volatile("cp.async.commit_group;" ::: "memory")
#define CP_WAIT1()  asm volatile("cp.async.wait_group 1;" ::: "memory")
#define CP_WAIT0()  asm volatile("cp.async.wait_group 0;" ::: "memory")

#define LDSM_X4(r0, r1, r2, r3, addr) \
    asm volatile("ldmatrix.sync.aligned.m8n8.x4.shared.b16 {%0,%1,%2,%3}, [%4];" \
        : "=r"(r0), "=r"(r1), "=r"(r2), "=r"(r3) : "r"(addr))
#define LDSM_X4_T(r0, r1, r2, r3, addr) \
    asm volatile("ldmatrix.sync.aligned.m8n8.x4.trans.shared.b16 {%0,%1,%2,%3}, [%4];" \
        : "=r"(r0), "=r"(r1), "=r"(r2), "=r"(r3) : "r"(addr))

#define MMA_(c, a0, a1, a2, a3, b0, b1) \
    asm volatile("mma.sync.aligned.m16n8k16.row.col.f32.bf16.bf16.f32 " \
        "{%0,%1,%2,%3}, {%4,%5,%6,%7}, {%8,%9}, {%0,%1,%2,%3};" \
        : "+f"((c)[0]), "+f"((c)[1]), "+f"((c)[2]), "+f"((c)[3]) \
        : "r"(a0), "r"(a1), "r"(a2), "r"(a3), "r"(b0), "r"(b1))

__device__ __forceinline__ uint32_t pack_bf16(float lo, float hi) {
    uint32_t r;
    asm("cvt.rn.bf16x2.f32 %0, %1, %2;" : "=r"(r) : "f"(hi), "f"(lo));
    return r;
}
__device__ __forceinline__ float bf16lo_f(uint32_t r) { return __int_as_float(r << 16); }
__device__ __forceinline__ float bf16hi_f(uint32_t r) { return __int_as_float(r & 0xffff0000u); }

__device__ __forceinline__ float fexp(float x) {
    float y = fmaxf(x * 1.4426950408889634f, -126.0f);
    int ni = __float2int_rn(y);
    float f = y - (float)ni;
    float p = 1.3333558e-3f;
    p = p * f + 9.6181291e-3f;
    p = p * f + 5.5504109e-2f;
    p = p * f + 2.4022651e-1f;
    p = p * f + 6.9314718e-1f;
    p = p * f + 1.0f;
    return __int_as_float(__float_as_int(p) + ni * 8388608);
}

// Swizzled 64B-row offset: rows of 4x16B chunks; phys chunk = ch ^ ((row>>1)&3)
__device__ __forceinline__ uint32_t sw64(int row, int ch) {
    return (uint32_t)(row * 64 + ((ch ^ ((row >> 1) & 3)) << 4));
}

// ---------------------------------------------------------------------------
// Kernel A: fp32 -> bf16 hi/lo split.
// ---------------------------------------------------------------------------
__global__ void __launch_bounds__(256) split_kernel(const float4* __restrict__ in, int mode)
{
    __nv_bfloat16 *hi, *lo;
    if (mode == 0)      { hi = g_Xhi;  lo = g_Xlo;  }
    else if (mode == 1) { hi = g_Wahi; lo = g_Walo; }
    else                { hi = g_Wphi; lo = g_Wplo; }

    size_t i = (size_t)blockIdx.x * blockDim.x + threadIdx.x;
    float4 v = in[i];
    __nv_bfloat16 hx = __float2bfloat16(v.x), hy = __float2bfloat16(v.y);
    __nv_bfloat16 hz = __float2bfloat16(v.z), hw = __float2bfloat16(v.w);
    __nv_bfloat16 lx = __float2bfloat16(v.x - __bfloat162float(hx));
    __nv_bfloat16 ly = __float2bfloat16(v.y - __bfloat162float(hy));
    __nv_bfloat16 lz = __float2bfloat16(v.z - __bfloat162float(hz));
    __nv_bfloat16 lw = __float2bfloat16(v.w - __bfloat162float(hw));
    __nv_bfloat162* Hh = reinterpret_cast<__nv_bfloat162*>(hi + 4 * i);
    __nv_bfloat162* Ll = reinterpret_cast<__nv_bfloat162*>(lo + 4 * i);
    Hh[0] = __halves2bfloat162(hx, hy); Hh[1] = __halves2bfloat162(hz, hw);
    Ll[0] = __halves2bfloat162(lx, ly); Ll[1] = __halves2bfloat162(lz, lw);
}

// ---------------------------------------------------------------------------
// Kernel B: HMMA split GEMM. CTA tile 64x128, 8 warps of 32x32, BK=32,
// swizzled 64B rows, 2-stage cp.async, 3 CTAs/SM target.
// Stage layout: Ahi[64x64B] Alo[64x64B] Bhi[128x64B] Blo[128x64B] = 24576B
// ---------------------------------------------------------------------------
#define BK_       32
#define GA_TILE   4096
#define GB_TILE   8192
#define GSTAGE    (2*GA_TILE + 2*GB_TILE)   // 24576
#define GEMM_SMEM_BYTES (2 * GSTAGE)        // 49152

__global__ void __launch_bounds__(256, 3) hmma_gemm_kernel(
    const float* __restrict__ bias, float* __restrict__ Cout, int mode)
{
    extern __shared__ __align__(128) char smem[];
    const __nv_bfloat16 *Ahi, *Alo, *Bhi, *Blo;
    if (mode == 0) { Ahi = g_Xhi; Alo = g_Xlo; Bhi = g_Wahi; Blo = g_Walo; }
    else           { Ahi = g_Ohi; Alo = g_Olo; Bhi = g_Wphi; Blo = g_Wplo; }

    uint32_t sb = smem_u32(smem);
    int tid = threadIdx.x, lane = tid & 31, wid = tid >> 5;
    int bm = blockIdx.y * 64, bn = blockIdx.x * 128;
    int wm = wid >> 2;          // 0..1: 32 A-rows each
    int wn = wid & 3;           // 0..3: 32 B-rows each

    auto prefetch = [&](int chunk, int stage) {
        int k0 = chunk * BK_;
        uint32_t sbase = sb + stage * GSTAGE;
#pragma unroll
        for (int it = 0; it < 6; it++) {
            int idx = tid + it * 256;          // 0..1535
            if (idx < 512) {                   // A: 128 rows (hi 64 + lo 64)
                int row = idx >> 2, ch = idx & 3;
                int r = row & 63;
                const __nv_bfloat16* src =
                    ((row < 64) ? Ahi : Alo) + (size_t)(bm + r) * KD_ + k0 + ch * 8;
                CP_ASYNC16(sbase + ((row < 64) ? 0 : GA_TILE) + sw64(r, ch), src);
            } else {                           // B: 256 rows (hi 128 + lo 128)
                int j = idx - 512;
                int row = j >> 2, ch = j & 3;
                int r = row & 127;
                const __nv_bfloat16* src =
                    ((row < 128) ? Bhi : Blo) + (size_t)(bn + r) * KD_ + k0 + ch * 8;
                CP_ASYNC16(sbase + 2 * GA_TILE + ((row < 128) ? 0 : GB_TILE) + sw64(r, ch), src);
            }
        }
        CP_COMMIT();
    };

    float acc[2][4][4];
#pragma unroll
    for (int mi = 0; mi < 2; mi++)
#pragma unroll
        for (int ni = 0; ni < 4; ni++)
#pragma unroll
            for (int r = 0; r < 4; r++) acc[mi][ni][r] = 0.f;

    prefetch(0, 0);
    prefetch(1, 1);

    const int NCH = KD_ / BK_;   // 32
    for (int ch = 0; ch < NCH; ch++) {
        if (ch < NCH - 1) CP_WAIT1(); else CP_WAIT0();
        __syncthreads();

        uint32_t sbase = sb + (ch & 1) * GSTAGE;
        uint32_t bbase = sbase + 2 * GA_TILE;

#pragma unroll
        for (int ks = 0; ks < 2; ks++) {
            uint32_t ah[2][4], al[2][4], bh[2][4], bl[2][4];
            int ac = ks * 2 + (lane >> 4);
#pragma unroll
            for (int mi = 0; mi < 2; mi++) {
                int ar = wm * 32 + mi * 16 + (lane & 15);
                uint32_t ad = sbase + sw64(ar, ac);
                LDSM_X4(ah[mi][0], ah[mi][1], ah[mi][2], ah[mi][3], ad);
                LDSM_X4(al[mi][0], al[mi][1], al[mi][2], al[mi][3], ad + GA_TILE);
            }
            int bc = ks * 2 + ((lane >> 3) & 1);
            int brl = ((lane >> 4) << 3) + (lane & 7);
#pragma unroll
            for (int np = 0; np < 2; np++) {
                int br = wn * 32 + np * 16 + brl;
                uint32_t bd = bbase + sw64(br, bc);
                LDSM_X4(bh[np][0], bh[np][1], bh[np][2], bh[np][3], bd);
                LDSM_X4(bl[np][0], bl[np][1], bl[np][2], bl[np][3], bd + GB_TILE);
            }
#pragma unroll
            for (int mi = 0; mi < 2; mi++)
#pragma unroll
                for (int np = 0; np < 2; np++) {
                    MMA_(acc[mi][2*np],   ah[mi][0], ah[mi][1], ah[mi][2], ah[mi][3], bh[np][0], bh[np][1]);
                    MMA_(acc[mi][2*np+1], ah[mi][0], ah[mi][1], ah[mi][2], ah[mi][3], bh[np][2], bh[np][3]);
                }
#pragma unroll
            for (int mi = 0; mi < 2; mi++)
#pragma unroll
                for (int np = 0; np < 2; np++) {
                    MMA_(acc[mi][2*np],   ah[mi][0], ah[mi][1], ah[mi][2], ah[mi][3], bl[np][0], bl[np][1]);
                    MMA_(acc[mi][2*np+1], ah[mi][0], ah[mi][1], ah[mi][2], ah[mi][3], bl[np][2], bl[np][3]);
                }
#pragma unroll
            for (int mi = 0; mi < 2; mi++)
#pragma unroll
                for (int np = 0; np < 2; np++) {
                    MMA_(acc[mi][2*np],   al[mi][0], al[mi][1], al[mi][2], al[mi][3], bh[np][0], bh[np][1]);
                    MMA_(acc[mi][2*np+1], al[mi][0], al[mi][1], al[mi][2], al[mi][3], bh[np][2], bh[np][3]);
                }
        }
        __syncthreads();
        if (ch + 2 < NCH) prefetch(ch + 2, ch & 1);
    }

    int g = lane >> 2, t = lane & 3;
    if (mode == 0) {
#pragma unroll
        for (int mi = 0; mi < 2; mi++)
#pragma unroll
            for (int ni = 0; ni < 4; ni++) {
                int r0 = bm + wm * 32 + mi * 16 + g;
                int c0 = bn + wn * 32 + ni * 8 + t * 2;
#pragma unroll
                for (int e = 0; e < 4; e++) {
                    int m = r0 + (e >> 1) * 8;
                    int col = c0 + (e & 1);
                    float v = acc[mi][ni][e] + bias[col];
                    int b = m >> 11, tt = m & 2047;
                    int seg = col >> 10, cn = col & 1023;
                    int h = cn >> 6, d = cn & 63;
                    size_t o = (((size_t)(b * H_ + h) * T_) + tt) * HD_ + d;
                    if (seg == 0) v *= 0.125f;
                    __nv_bfloat16 vh = __float2bfloat16(v);
                    __nv_bfloat16 vl = __float2bfloat16(v - __bfloat162float(vh));
                    if (seg == 0)      { g_Qh[o] = vh; g_Ql[o] = vl; }
                    else if (seg == 1) { g_Kh[o] = vh; g_Kl[o] = vl; }
                    else               { g_Vh[o] = vh; g_Vl[o] = vl; }
                }
            }
    } else {
#pragma unroll
        for (int mi = 0; mi < 2; mi++)
#pragma unroll
            for (int ni = 0; ni < 4; ni++) {
                int r0 = bm + wm * 32 + mi * 16 + g;
                int c0 = bn + wn * 32 + ni * 8 + t * 2;
                float2 v0 = make_float2(acc[mi][ni][0] + bias[c0],
                                        acc[mi][ni][1] + bias[c0 + 1]);
                float2 v1 = make_float2(acc[mi][ni][2] + bias[c0],
                                        acc[mi][ni][3] + bias[c0 + 1]);
                *reinterpret_cast<float2*>(&Cout[(size_t)r0 * C_ + c0]) = v0;
                *reinterpret_cast<float2*>(&Cout[(size_t)(r0 + 8) * C_ + c0]) = v1;
            }
    }
}

// ---------------------------------------------------------------------------
// Kernel C: tensor-core flash attention (unchanged from Round 5).
// ---------------------------------------------------------------------------
#define AROWB      144
#define KV_TILE_B  (64 * AROWB)
#define KV_STAGE_B (4 * KV_TILE_B)
#define ATTN_SMEM_BYTES (2 * KV_STAGE_B)

__global__ void __launch_bounds__(256) attn_hmma_kernel()
{
    extern __shared__ __align__(128) char smem[];
    uint32_t sb = smem_u32(smem);
    int tid = threadIdx.x, lane = tid & 31, wid = tid >> 5;
    int bh = blockIdx.y, q0 = blockIdx.x * 128;
    size_t bhbase = (size_t)bh * T_ * HD_;

    {
        const __nv_bfloat16* Qh = g_Qh + bhbase + (size_t)q0 * HD_;
        const __nv_bfloat16* Ql = g_Ql + bhbase + (size_t)q0 * HD_;
#pragma unroll
        for (int it = 0; it < 8; it++) {
            int idx = tid + it * 256;
            int tile = idx >> 10, within = idx & 1023;
            int row = within >> 3, ch = within & 7;
            const __nv_bfloat16* src = (tile ? Ql : Qh) + (size_t)row * HD_ + ch * 8;
            CP_ASYNC16(sb + tile * (128 * AROWB) + row * AROWB + ch * 16, src);
        }
        CP_COMMIT(); CP_WAIT0();
        __syncthreads();
    }

    uint32_t qh[4][4], ql[4][4];
    {
        int arow = wid * 16 + (lane & 15);
        uint32_t acolb = ((lane >> 4) << 3) * 2;
#pragma unroll
        for (int ks = 0; ks < 4; ks++) {
            uint32_t addr = sb + arow * AROWB + ks * 32 + acolb;
            LDSM_X4(qh[ks][0], qh[ks][1], qh[ks][2], qh[ks][3], addr);
            LDSM_X4(ql[ks][0], ql[ks][1], ql[ks][2], ql[ks][3], addr + 128 * AROWB);
        }
    }
    __syncthreads();

    const __nv_bfloat16 *Kh = g_Kh + bhbase, *Kl = g_Kl + bhbase;
    const __nv_bfloat16 *Vh = g_Vh + bhbase, *Vl = g_Vl + bhbase;

    auto kv_prefetch = [&](int kt) {
        uint32_t sbase = sb + (kt & 1) * KV_STAGE_B;
        int k0 = kt * 64;
#pragma unroll
        for (int it = 0; it < 8; it++) {
            int idx = tid + it * 256;
            int tile = idx >> 9, within = idx & 511;
            int row = within >> 3, ch = within & 7;
            const __nv_bfloat16* base =
                (tile == 0) ? Kh : (tile == 1) ? Kl : (tile == 2) ? Vh : Vl;
            CP_ASYNC16(sbase + tile * KV_TILE_B + row * AROWB + ch * 16,
                       base + (size_t)(k0 + row) * HD_ + ch * 8);
        }
        CP_COMMIT();
    };

    float o[8][4];
#pragma unroll
    for (int j = 0; j < 8; j++)
#pragma unroll
        for (int r = 0; r < 4; r++) o[j][r] = 0.f;
    float m0 = -1e30f, m1 = -1e30f, l0 = 0.f, l1 = 0.f;

    kv_prefetch(0);

    for (int kt = 0; kt < T_ / 64; kt++) {
        CP_WAIT0();
        __syncthreads();
        if (kt + 1 < T_ / 64) kv_prefetch(kt + 1);
        uint32_t sbase = sb + (kt & 1) * KV_STAGE_B;

        float s[8][4];
#pragma unroll
        for (int j = 0; j < 8; j++)
#pragma unroll
            for (int r = 0; r < 4; r++) s[j][r] = 0.f;

        int brow = ((lane >> 4) << 3) + (lane & 7);
        uint32_t bcolb = (((lane >> 3) & 1) << 3) * 2;
#pragma unroll
        for (int ks = 0; ks < 4; ks++) {
#pragma unroll
            for (int npp = 0; npp < 2; npp++) {
                uint32_t a0 = sbase + ((2*npp) * 16 + brow) * AROWB + ks * 32 + bcolb;
                uint32_t a1 = sbase + ((2*npp+1) * 16 + brow) * AROWB + ks * 32 + bcolb;
                uint32_t kh0[4], kh1[4], kl0[4], kl1[4];
                LDSM_X4(kh0[0], kh0[1], kh0[2], kh0[3], a0);
                LDSM_X4(kh1[0], kh1[1], kh1[2], kh1[3], a1);
                LDSM_X4(kl0[0], kl0[1], kl0[2], kl0[3], a0 + KV_TILE_B);
                LDSM_X4(kl1[0], kl1[1], kl1[2], kl1[3], a1 + KV_TILE_B);
                float* s0 = s[4*npp+0]; float* s1 = s[4*npp+1];
                float* s2 = s[4*npp+2]; float* s3 = s[4*npp+3];
                MMA_(s0, qh[ks][0], qh[ks][1], qh[ks][2], qh[ks][3], kh0[0], kh0[1]);
                MMA_(s1, qh[ks][0], qh[ks][1], qh[ks][2], qh[ks][3], kh0[2], kh0[3]);
                MMA_(s2, qh[ks][0], qh[ks][1], qh[ks][2], qh[ks][3], kh1[0], kh1[1]);
                MMA_(s3, qh[ks][0], qh[ks][1], qh[ks][2], qh[ks][3], kh1[2], kh1[3]);
                MMA_(s0, qh[ks][0], qh[ks][1], qh[ks][2], qh[ks][3], kl0[0], kl0[1]);
                MMA_(s1, qh[ks][0], qh[ks][1], qh[ks][2], qh[ks][3], kl0[2], kl0[3]);
                MMA_(s2, qh[ks][0], qh[ks][1], qh[ks][2], qh[ks][3], kl1[0], kl1[1]);
                MMA_(s3, qh[ks][0], qh[ks][1], qh[ks][2], qh[ks][3], kl1[2], kl1[3]);
                MMA_(s0, ql[ks][0], ql[ks][1], ql[ks][2], ql[ks][3], kh0[0], kh0[1]);
                MMA_(s1, ql[ks][0], ql[ks][1], ql[ks][2], ql[ks][3], kh0[2], kh0[3]);
                MMA_(s2, ql[ks][0], ql[ks][1], ql[ks][2], ql[ks][3], kh1[0], kh1[1]);
                MMA_(s3, ql[ks][0], ql[ks][1], ql[ks][2], ql[ks][3], kh1[2], kh1[3]);
            }
        }

        float mt0 = -1e30f, mt1 = -1e30f;
#pragma unroll
        for (int j = 0; j < 8; j++) {
            mt0 = fmaxf(mt0, fmaxf(s[j][0], s[j][1]));
            mt1 = fmaxf(mt1, fmaxf(s[j][2], s[j][3]));
        }
        mt0 = fmaxf(mt0, __shfl_xor_sync(0xffffffffu, mt0, 1));
        mt0 = fmaxf(mt0, __shfl_xor_sync(0xffffffffu, mt0, 2));
        mt1 = fmaxf(mt1, __shfl_xor_sync(0xffffffffu, mt1, 1));
        mt1 = fmaxf(mt1, __shfl_xor_sync(0xffffffffu, mt1, 2));
        float mn0 = fmaxf(m0, mt0), mn1 = fmaxf(m1, mt1);
        float corr0 = fexp(m0 - mn0), corr1 = fexp(m1 - mn1);
        float sum0 = 0.f, sum1 = 0.f;
#pragma unroll
        for (int j = 0; j < 8; j++) {
            s[j][0] = fexp(s[j][0] - mn0);
            s[j][1] = fexp(s[j][1] - mn0);
            s[j][2] = fexp(s[j][2] - mn1);
            s[j][3] = fexp(s[j][3] - mn1);
            sum0 += s[j][0] + s[j][1];
            sum1 += s[j][2] + s[j][3];
        }
        sum0 += __shfl_xor_sync(0xffffffffu, sum0, 1);
        sum0 += __shfl_xor_sync(0xffffffffu, sum0, 2);
        sum1 += __shfl_xor_sync(0xffffffffu, sum1, 1);
        sum1 += __shfl_xor_sync(0xffffffffu, sum1, 2);
        l0 = l0 * corr0 + sum0;
        l1 = l1 * corr1 + sum1;
        m0 = mn0; m1 = mn1;
#pragma unroll
        for (int j = 0; j < 8; j++) {
            o[j][0] *= corr0; o[j][1] *= corr0;
            o[j][2] *= corr1; o[j][3] *= corr1;
        }

        uint32_t vbase = sbase + 2 * KV_TILE_B;
        uint32_t vrow = (lane & 15);
        uint32_t vcolb = ((lane >> 4) << 3) * 2;
#pragma unroll
        for (int ks = 0; ks < 4; ks++) {
            uint32_t ah0 = pack_bf16(s[2*ks][0],   s[2*ks][1]);
            uint32_t ah1 = pack_bf16(s[2*ks][2],   s[2*ks][3]);
            uint32_t ah2 = pack_bf16(s[2*ks+1][0], s[2*ks+1][1]);
            uint32_t ah3 = pack_bf16(s[2*ks+1][2], s[2*ks+1][3]);
            uint32_t al0 = pack_bf16(s[2*ks][0]   - bf16lo_f(ah0), s[2*ks][1]   - bf16hi_f(ah0));
            uint32_t al1 = pack_bf16(s[2*ks][2]   - bf16lo_f(ah1), s[2*ks][3]   - bf16hi_f(ah1));
            uint32_t al2 = pack_bf16(s[2*ks+1][0] - bf16lo_f(ah2), s[2*ks+1][1] - bf16hi_f(ah2));
            uint32_t al3 = pack_bf16(s[2*ks+1][2] - bf16lo_f(ah3), s[2*ks+1][3] - bf16hi_f(ah3));
#pragma unroll
            for (int jpp = 0; jpp < 2; jpp++) {
                uint32_t a0 = vbase + (ks * 16 + vrow) * AROWB + (2*jpp) * 32 + vcolb;
                uint32_t a1 = vbase + (ks * 16 + vrow) * AROWB + (2*jpp+1) * 32 + vcolb;
                uint32_t vh0[4], vh1[4], vl0[4], vl1[4];
                LDSM_X4_T(vh0[0], vh0[1], vh0[2], vh0[3], a0);
                LDSM_X4_T(vh1[0], vh1[1], vh1[2], vh1[3], a1);
                LDSM_X4_T(vl0[0], vl0[1], vl0[2], vl0[3], a0 + KV_TILE_B);
                LDSM_X4_T(vl1[0], vl1[1], vl1[2], vl1[3], a1 + KV_TILE_B);
                float* o0 = o[4*jpp+0]; float* o1 = o[4*jpp+1];
                float* o2 = o[4*jpp+2]; float* o3 = o[4*jpp+3];
                MMA_(o0, ah0, ah1, ah2, ah3, vh0[0], vh0[1]);
                MMA_(o1, ah0, ah1, ah2, ah3, vh0[2], vh0[3]);
                MMA_(o2, ah0, ah1, ah2, ah3, vh1[0], vh1[1]);
                MMA_(o3, ah0, ah1, ah2, ah3, vh1[2], vh1[3]);
                MMA_(o0, ah0, ah1, ah2, ah3, vl0[0], vl0[1]);
                MMA_(o1, ah0, ah1, ah2, ah3, vl0[2], vl0[3]);
                MMA_(o2, ah0, ah1, ah2, ah3, vl1[0], vl1[1]);
                MMA_(o3, ah0, ah1, ah2, ah3, vl1[2], vl1[3]);
                MMA_(o0, al0, al1, al2, al3, vh0[0], vh0[1]);
                MMA_(o1, al0, al1, al2, al3, vh0[2], vh0[3]);
                MMA_(o2, al0, al1, al2, al3, vh1[0], vh1[1]);
                MMA_(o3, al0, al1, al2, al3, vh1[2], vh1[3]);
            }
        }
    }

    int g = lane >> 2, t = lane & 3;
    float inv0 = 1.0f / l0, inv1 = 1.0f / l1;
    int b = bh >> 4, h = bh & 15;
    int row0 = q0 + wid * 16 + g;
    size_t ob0 = ((size_t)(b * T_) + row0) * C_ + h * 64 + t * 2;
    size_t ob1 = ob0 + (size_t)8 * C_;
#pragma unroll
    for (int j = 0; j < 8; j++) {
        float v0 = o[j][0] * inv0, v1 = o[j][1] * inv0;
        float v2 = o[j][2] * inv1, v3 = o[j][3] * inv1;
        uint32_t h0 = pack_bf16(v0, v1);
        uint32_t h1 = pack_bf16(v2, v3);
        uint32_t l0p = pack_bf16(v0 - bf16lo_f(h0), v1 - bf16hi_f(h0));
        uint32_t l1p = pack_bf16(v2 - bf16lo_f(h1), v3 - bf16hi_f(h1));
        *reinterpret_cast<uint32_t*>(g_Ohi + ob0 + j * 8) = h0;
        *reinterpret_cast<uint32_t*>(g_Ohi + ob1 + j * 8) = h1;
        *reinterpret_cast<uint32_t*>(g_Olo + ob0 + j * 8) = l0p;
        *reinterpret_cast<uint32_t*>(g_Olo + ob1 + j * 8) = l1p;
    }
}

// ---------------------------------------------------------------------------
extern "C" void kernel_launch(void* const* d_in, const int* in_sizes, int n_in,
                              void* d_out, int out_size)
{
    const float* x      = (const float*)d_in[0];
    const float* W_attn = (const float*)d_in[1];
    const float* b_attn = (const float*)d_in[2];
    const float* W_proj = (const float*)d_in[3];
    const float* b_proj = (const float*)d_in[4];
    float* out = (float*)d_out;

    cudaFuncSetAttribute(hmma_gemm_kernel,
                         cudaFuncAttributeMaxDynamicSharedMemorySize, GEMM_SMEM_BYTES);
    cudaFuncSetAttribute(attn_hmma_kernel,
                         cudaFuncAttributeMaxDynamicSharedMemorySize, ATTN_SMEM_BYTES);

    split_kernel<<<(B_*T_*C_) / 4 / 256, 256>>>((const float4*)x, 0);
    split_kernel<<<(3*C_*C_)  / 4 / 256, 256>>>((const float4*)W_attn, 1);
    split_kernel<<<(C_*C_)    / 4 / 256, 256>>>((const float4*)W_proj, 2);

    // QKV GEMM: M=8192 (64-row tiles), N=3072 (128-col tiles)
    hmma_gemm_kernel<<<dim3(3 * C_ / 128, B_ * T_ / 64), 256, GEMM_SMEM_BYTES>>>(
        b_attn, nullptr, 0);

    attn_hmma_kernel<<<dim3(T_ / 128, BH_), 256, ATTN_SMEM_BYTES>>>();

    // proj GEMM: M=8192, N=1024
    hmma_gemm_kernel<<<dim3(C_ / 128, B_ * T_ / 64), 256, GEMM_SMEM_BYTES>>>(
        b_proj, out, 1);
}

// round 7
// speedup vs baseline: 3.4339x; 1.0859x over previous
#include <cuda_runtime.h>
#include <cuda_bf16.h>
#include <cstdint>

#define B_  4
#define T_  2048
#define C_  1024
#define H_  16
#define HD_ 64
#define BH_ (B_*H_)
#define KD_ 1024

// ---------------------------------------------------------------------------
// Device-global scratch
// ---------------------------------------------------------------------------
__device__ __nv_bfloat16 g_Qh[(size_t)BH_*T_*HD_], g_Ql[(size_t)BH_*T_*HD_];
__device__ __nv_bfloat16 g_Kh[(size_t)BH_*T_*HD_], g_Kl[(size_t)BH_*T_*HD_];
__device__ __nv_bfloat16 g_Vh[(size_t)BH_*T_*HD_], g_Vl[(size_t)BH_*T_*HD_];

__device__ __nv_bfloat16 g_Xhi[(size_t)B_*T_*C_],   g_Xlo[(size_t)B_*T_*C_];
__device__ __nv_bfloat16 g_Wahi[(size_t)3*C_*C_],   g_Walo[(size_t)3*C_*C_];
__device__ __nv_bfloat16 g_Wphi[(size_t)C_*C_],     g_Wplo[(size_t)C_*C_];
__device__ __nv_bfloat16 g_Ohi[(size_t)B_*T_*C_],   g_Olo[(size_t)B_*T_*C_];

// ---------------------------------------------------------------------------
// Helpers
// ---------------------------------------------------------------------------
__device__ __forceinline__ uint32_t smem_u32(const void* p) {
    uint32_t a;
    asm("{ .reg .u64 t; cvta.to.shared.u64 t, %1; cvt.u32.u64 %0, t; }"
        : "=r"(a) : "l"(p));
    return a;
}

#define CP_ASYNC16(dst, src) \
    asm volatile("cp.async.cg.shared.global [%0], [%1], 16;" :: "r"(dst), "l"(src))
#define CP_COMMIT() asm volatile("cp.async.commit_group;" ::: "memory")
#define CP_WAIT1()  asm volatile("cp.async.wait_group 1;" ::: "memory")
#define CP_WAIT0()  asm volatile("cp.async.wait_group 0;" ::: "memory")

#define LDSM_X4(r0, r1, r2, r3, addr) \
    asm volatile("ldmatrix.sync.aligned.m8n8.x4.shared.b16 {%0,%1,%2,%3}, [%4];" \
        : "=r"(r0), "=r"(r1), "=r"(r2), "=r"(r3) : "r"(addr))
#define LDSM_X4_T(r0, r1, r2, r3, addr) \
    asm volatile("ldmatrix.sync.aligned.m8n8.x4.trans.shared.b16 {%0,%1,%2,%3}, [%4];" \
        : "=r"(r0), "=r"(r1), "=r"(r2), "=r"(r3) : "r"(addr))

#define MMA_(c, a0, a1, a2, a3, b0, b1) \
    asm volatile("mma.sync.aligned.m16n8k16.row.col.f32.bf16.bf16.f32 " \
        "{%0,%1,%2,%3}, {%4,%5,%6,%7}, {%8,%9}, {%0,%1,%2,%3};" \
        : "+f"((c)[0]), "+f"((c)[1]), "+f"((c)[2]), "+f"((c)[3]) \
        : "r"(a0), "r"(a1), "r"(a2), "r"(a3), "r"(b0), "r"(b1))

__device__ __forceinline__ uint32_t pack_bf16(float lo, float hi) {
    uint32_t r;
    asm("cvt.rn.bf16x2.f32 %0, %1, %2;" : "=r"(r) : "f"(hi), "f"(lo));
    return r;
}
__device__ __forceinline__ float bf16lo_f(uint32_t r) { return __int_as_float(r << 16); }
__device__ __forceinline__ float bf16hi_f(uint32_t r) { return __int_as_float(r & 0xffff0000u); }

__device__ __forceinline__ float fexp(float x) {
    float y = fmaxf(x * 1.4426950408889634f, -126.0f);
    int ni = __float2int_rn(y);
    float f = y - (float)ni;
    float p = 1.3333558e-3f;
    p = p * f + 9.6181291e-3f;
    p = p * f + 5.5504109e-2f;
    p = p * f + 2.4022651e-1f;
    p = p * f + 6.9314718e-1f;
    p = p * f + 1.0f;
    return __int_as_float(__float_as_int(p) + ni * 8388608);
}

// Swizzled 64B-row offset (GEMM): phys chunk = ch ^ ((row>>1)&3)
__device__ __forceinline__ uint32_t sw64(int row, int ch) {
    return (uint32_t)(row * 64 + ((ch ^ ((row >> 1) & 3)) << 4));
}
// Swizzled 128B-row offset (attention): phys chunk = ch ^ (row&7)
__device__ __forceinline__ uint32_t sw128r(int row, int ch) {
    return (uint32_t)(row * 128 + ((ch ^ (row & 7)) << 4));
}

// ---------------------------------------------------------------------------
// Kernel A: fp32 -> bf16 hi/lo split.
// ---------------------------------------------------------------------------
__global__ void __launch_bounds__(256) split_kernel(const float4* __restrict__ in, int mode)
{
    __nv_bfloat16 *hi, *lo;
    if (mode == 0)      { hi = g_Xhi;  lo = g_Xlo;  }
    else if (mode == 1) { hi = g_Wahi; lo = g_Walo; }
    else                { hi = g_Wphi; lo = g_Wplo; }

    size_t i = (size_t)blockIdx.x * blockDim.x + threadIdx.x;
    float4 v = in[i];
    __nv_bfloat16 hx = __float2bfloat16(v.x), hy = __float2bfloat16(v.y);
    __nv_bfloat16 hz = __float2bfloat16(v.z), hw = __float2bfloat16(v.w);
    __nv_bfloat16 lx = __float2bfloat16(v.x - __bfloat162float(hx));
    __nv_bfloat16 ly = __float2bfloat16(v.y - __bfloat162float(hy));
    __nv_bfloat16 lz = __float2bfloat16(v.z - __bfloat162float(hz));
    __nv_bfloat16 lw = __float2bfloat16(v.w - __bfloat162float(hw));
    __nv_bfloat162* Hh = reinterpret_cast<__nv_bfloat162*>(hi + 4 * i);
    __nv_bfloat162* Ll = reinterpret_cast<__nv_bfloat162*>(lo + 4 * i);
    Hh[0] = __halves2bfloat162(hx, hy); Hh[1] = __halves2bfloat162(hz, hw);
    Ll[0] = __halves2bfloat162(lx, ly); Ll[1] = __halves2bfloat162(lz, lw);
}

// ---------------------------------------------------------------------------
// Kernel B: HMMA split GEMM (unchanged from Round 6).
// ---------------------------------------------------------------------------
#define BK_       32
#define GA_TILE   4096
#define GB_TILE   8192
#define GSTAGE    (2*GA_TILE + 2*GB_TILE)   // 24576
#define GEMM_SMEM_BYTES (2 * GSTAGE)        // 49152

__global__ void __launch_bounds__(256, 3) hmma_gemm_kernel(
    const float* __restrict__ bias, float* __restrict__ Cout, int mode)
{
    extern __shared__ __align__(128) char smem[];
    const __nv_bfloat16 *Ahi, *Alo, *Bhi, *Blo;
    if (mode == 0) { Ahi = g_Xhi; Alo = g_Xlo; Bhi = g_Wahi; Blo = g_Walo; }
    else           { Ahi = g_Ohi; Alo = g_Olo; Bhi = g_Wphi; Blo = g_Wplo; }

    uint32_t sb = smem_u32(smem);
    int tid = threadIdx.x, lane = tid & 31, wid = tid >> 5;
    int bm = blockIdx.y * 64, bn = blockIdx.x * 128;
    int wm = wid >> 2;
    int wn = wid & 3;

    auto prefetch = [&](int chunk, int stage) {
        int k0 = chunk * BK_;
        uint32_t sbase = sb + stage * GSTAGE;
#pragma unroll
        for (int it = 0; it < 6; it++) {
            int idx = tid + it * 256;
            if (idx < 512) {
                int row = idx >> 2, ch = idx & 3;
                int r = row & 63;
                const __nv_bfloat16* src =
                    ((row < 64) ? Ahi : Alo) + (size_t)(bm + r) * KD_ + k0 + ch * 8;
                CP_ASYNC16(sbase + ((row < 64) ? 0 : GA_TILE) + sw64(r, ch), src);
            } else {
                int j = idx - 512;
                int row = j >> 2, ch = j & 3;
                int r = row & 127;
                const __nv_bfloat16* src =
                    ((row < 128) ? Bhi : Blo) + (size_t)(bn + r) * KD_ + k0 + ch * 8;
                CP_ASYNC16(sbase + 2 * GA_TILE + ((row < 128) ? 0 : GB_TILE) + sw64(r, ch), src);
            }
        }
        CP_COMMIT();
    };

    float acc[2][4][4];
#pragma unroll
    for (int mi = 0; mi < 2; mi++)
#pragma unroll
        for (int ni = 0; ni < 4; ni++)
#pragma unroll
            for (int r = 0; r < 4; r++) acc[mi][ni][r] = 0.f;

    prefetch(0, 0);
    prefetch(1, 1);

    const int NCH = KD_ / BK_;
    for (int ch = 0; ch < NCH; ch++) {
        if (ch < NCH - 1) CP_WAIT1(); else CP_WAIT0();
        __syncthreads();

        uint32_t sbase = sb + (ch & 1) * GSTAGE;
        uint32_t bbase = sbase + 2 * GA_TILE;

#pragma unroll
        for (int ks = 0; ks < 2; ks++) {
            uint32_t ah[2][4], al[2][4], bh[2][4], bl[2][4];
            int ac = ks * 2 + (lane >> 4);
#pragma unroll
            for (int mi = 0; mi < 2; mi++) {
                int ar = wm * 32 + mi * 16 + (lane & 15);
                uint32_t ad = sbase + sw64(ar, ac);
                LDSM_X4(ah[mi][0], ah[mi][1], ah[mi][2], ah[mi][3], ad);
                LDSM_X4(al[mi][0], al[mi][1], al[mi][2], al[mi][3], ad + GA_TILE);
            }
            int bc = ks * 2 + ((lane >> 3) & 1);
            int brl = ((lane >> 4) << 3) + (lane & 7);
#pragma unroll
            for (int np = 0; np < 2; np++) {
                int br = wn * 32 + np * 16 + brl;
                uint32_t bd = bbase + sw64(br, bc);
                LDSM_X4(bh[np][0], bh[np][1], bh[np][2], bh[np][3], bd);
                LDSM_X4(bl[np][0], bl[np][1], bl[np][2], bl[np][3], bd + GB_TILE);
            }
#pragma unroll
            for (int mi = 0; mi < 2; mi++)
#pragma unroll
                for (int np = 0; np < 2; np++) {
                    MMA_(acc[mi][2*np],   ah[mi][0], ah[mi][1], ah[mi][2], ah[mi][3], bh[np][0], bh[np][1]);
                    MMA_(acc[mi][2*np+1], ah[mi][0], ah[mi][1], ah[mi][2], ah[mi][3], bh[np][2], bh[np][3]);
                }
#pragma unroll
            for (int mi = 0; mi < 2; mi++)
#pragma unroll
                for (int np = 0; np < 2; np++) {
                    MMA_(acc[mi][2*np],   ah[mi][0], ah[mi][1], ah[mi][2], ah[mi][3], bl[np][0], bl[np][1]);
                    MMA_(acc[mi][2*np+1], ah[mi][0], ah[mi][1], ah[mi][2], ah[mi][3], bl[np][2], bl[np][3]);
                }
#pragma unroll
            for (int mi = 0; mi < 2; mi++)
#pragma unroll
                for (int np = 0; np < 2; np++) {
                    MMA_(acc[mi][2*np],   al[mi][0], al[mi][1], al[mi][2], al[mi][3], bh[np][0], bh[np][1]);
                    MMA_(acc[mi][2*np+1], al[mi][0], al[mi][1], al[mi][2], al[mi][3], bh[np][2], bh[np][3]);
                }
        }
        __syncthreads();
        if (ch + 2 < NCH) prefetch(ch + 2, ch & 1);
    }

    int g = lane >> 2, t = lane & 3;
    if (mode == 0) {
#pragma unroll
        for (int mi = 0; mi < 2; mi++)
#pragma unroll
            for (int ni = 0; ni < 4; ni++) {
                int r0 = bm + wm * 32 + mi * 16 + g;
                int c0 = bn + wn * 32 + ni * 8 + t * 2;
#pragma unroll
                for (int e = 0; e < 4; e++) {
                    int m = r0 + (e >> 1) * 8;
                    int col = c0 + (e & 1);
                    float v = acc[mi][ni][e] + bias[col];
                    int b = m >> 11, tt = m & 2047;
                    int seg = col >> 10, cn = col & 1023;
                    int h = cn >> 6, d = cn & 63;
                    size_t o = (((size_t)(b * H_ + h) * T_) + tt) * HD_ + d;
                    if (seg == 0) v *= 0.125f;
                    __nv_bfloat16 vh = __float2bfloat16(v);
                    __nv_bfloat16 vl = __float2bfloat16(v - __bfloat162float(vh));
                    if (seg == 0)      { g_Qh[o] = vh; g_Ql[o] = vl; }
                    else if (seg == 1) { g_Kh[o] = vh; g_Kl[o] = vl; }
                    else               { g_Vh[o] = vh; g_Vl[o] = vl; }
                }
            }
    } else {
#pragma unroll
        for (int mi = 0; mi < 2; mi++)
#pragma unroll
            for (int ni = 0; ni < 4; ni++) {
                int r0 = bm + wm * 32 + mi * 16 + g;
                int c0 = bn + wn * 32 + ni * 8 + t * 2;
                float2 v0 = make_float2(acc[mi][ni][0] + bias[c0],
                                        acc[mi][ni][1] + bias[c0 + 1]);
                float2 v1 = make_float2(acc[mi][ni][2] + bias[c0],
                                        acc[mi][ni][3] + bias[c0 + 1]);
                *reinterpret_cast<float2*>(&Cout[(size_t)r0 * C_ + c0]) = v0;
                *reinterpret_cast<float2*>(&Cout[(size_t)(r0 + 8) * C_ + c0]) = v1;
            }
    }
}

// ---------------------------------------------------------------------------
// Kernel C: tensor-core flash attention, 128 threads (4 warps), 64-query tile.
// 128B swizzled KV rows -> stage 32KB, double buffer 64KB -> 3 CTAs/SM.
// ---------------------------------------------------------------------------
#define KV_TILE  8192                       // 64 rows x 128B
#define KV_STAGE (4 * KV_TILE)              // 32768: Khi,Klo,Vhi,Vlo
#define ATTN_SMEM_BYTES (2 * KV_STAGE)      // 65536

__global__ void __launch_bounds__(128, 3) attn_hmma_kernel()
{
    extern __shared__ __align__(128) char smem[];
    uint32_t sb = smem_u32(smem);
    int tid = threadIdx.x, lane = tid & 31, wid = tid >> 5;
    int bh = blockIdx.y, q0 = blockIdx.x * 64;
    size_t bhbase = (size_t)bh * T_ * HD_;

    // ---- stage Q tile (64 rows hi/lo) at smem[0..16383], consume to regs ----
    {
        const __nv_bfloat16* Qh = g_Qh + bhbase + (size_t)q0 * HD_;
        const __nv_bfloat16* Ql = g_Ql + bhbase + (size_t)q0 * HD_;
#pragma unroll
        for (int it = 0; it < 8; it++) {
            int idx = tid + it * 128;          // 0..1023
            int tile = idx >> 9, within = idx & 511;
            int row = within >> 3, ch = within & 7;
            const __nv_bfloat16* src = (tile ? Ql : Qh) + (size_t)row * HD_ + ch * 8;
            CP_ASYNC16(sb + tile * 8192 + sw128r(row, ch), src);
        }
        CP_COMMIT(); CP_WAIT0();
        __syncthreads();
    }

    uint32_t qh[4][4], ql[4][4];
    {
        int arow = wid * 16 + (lane & 15);
#pragma unroll
        for (int ks = 0; ks < 4; ks++) {
            int ac = ks * 2 + (lane >> 4);
            uint32_t addr = sb + sw128r(arow, ac);
            LDSM_X4(qh[ks][0], qh[ks][1], qh[ks][2], qh[ks][3], addr);
            LDSM_X4(ql[ks][0], ql[ks][1], ql[ks][2], ql[ks][3], addr + 8192);
        }
    }
    __syncthreads();   // Q regs loaded; KV stage 0 may now overwrite Q region

    const __nv_bfloat16 *Kh = g_Kh + bhbase, *Kl = g_Kl + bhbase;
    const __nv_bfloat16 *Vh = g_Vh + bhbase, *Vl = g_Vl + bhbase;

    auto kv_prefetch = [&](int kt) {
        uint32_t sbase = sb + (kt & 1) * KV_STAGE;
        int k0 = kt * 64;
#pragma unroll
        for (int it = 0; it < 16; it++) {
            int idx = tid + it * 128;          // 0..2047
            int tile = idx >> 9, within = idx & 511;
            int row = within >> 3, ch = within & 7;
            const __nv_bfloat16* base =
                (tile == 0) ? Kh : (tile == 1) ? Kl : (tile == 2) ? Vh : Vl;
            CP_ASYNC16(sbase + tile * KV_TILE + sw128r(row, ch),
                       base + (size_t)(k0 + row) * HD_ + ch * 8);
        }
        CP_COMMIT();
    };

    float o[8][4];
#pragma unroll
    for (int j = 0; j < 8; j++)
#pragma unroll
        for (int r = 0; r < 4; r++) o[j][r] = 0.f;
    float m0 = -1e30f, m1 = -1e30f, l0 = 0.f, l1 = 0.f;

    kv_prefetch(0);

    for (int kt = 0; kt < T_ / 64; kt++) {
        CP_WAIT0();
        __syncthreads();
        if (kt + 1 < T_ / 64) kv_prefetch(kt + 1);
        uint32_t sbase = sb + (kt & 1) * KV_STAGE;

        // ---- S = Q K^T ----
        float s[8][4];
#pragma unroll
        for (int j = 0; j < 8; j++)
#pragma unroll
            for (int r = 0; r < 4; r++) s[j][r] = 0.f;

        int brl = ((lane >> 4) << 3) + (lane & 7);
        int bc  = (lane >> 3) & 1;
#pragma unroll
        for (int ks = 0; ks < 4; ks++) {
            int lc = ks * 2 + bc;
#pragma unroll
            for (int npp = 0; npp < 2; npp++) {
                int r0 = (2 * npp) * 16 + brl;
                int r1 = (2 * npp + 1) * 16 + brl;
                uint32_t a0 = sbase + sw128r(r0, lc);
                uint32_t a1 = sbase + sw128r(r1, lc);
                uint32_t kh0[4], kh1[4], kl0[4], kl1[4];
                LDSM_X4(kh0[0], kh0[1], kh0[2], kh0[3], a0);
                LDSM_X4(kh1[0], kh1[1], kh1[2], kh1[3], a1);
                LDSM_X4(kl0[0], kl0[1], kl0[2], kl0[3], a0 + KV_TILE);
                LDSM_X4(kl1[0], kl1[1], kl1[2], kl1[3], a1 + KV_TILE);
                float* s0 = s[4*npp+0]; float* s1 = s[4*npp+1];
                float* s2 = s[4*npp+2]; float* s3 = s[4*npp+3];
                MMA_(s0, qh[ks][0], qh[ks][1], qh[ks][2], qh[ks][3], kh0[0], kh0[1]);
                MMA_(s1, qh[ks][0], qh[ks][1], qh[ks][2], qh[ks][3], kh0[2], kh0[3]);
                MMA_(s2, qh[ks][0], qh[ks][1], qh[ks][2], qh[ks][3], kh1[0], kh1[1]);
                MMA_(s3, qh[ks][0], qh[ks][1], qh[ks][2], qh[ks][3], kh1[2], kh1[3]);
                MMA_(s0, qh[ks][0], qh[ks][1], qh[ks][2], qh[ks][3], kl0[0], kl0[1]);
                MMA_(s1, qh[ks][0], qh[ks][1], qh[ks][2], qh[ks][3], kl0[2], kl0[3]);
                MMA_(s2, qh[ks][0], qh[ks][1], qh[ks][2], qh[ks][3], kl1[0], kl1[1]);
                MMA_(s3, qh[ks][0], qh[ks][1], qh[ks][2], qh[ks][3], kl1[2], kl1[3]);
                MMA_(s0, ql[ks][0], ql[ks][1], ql[ks][2], ql[ks][3], kh0[0], kh0[1]);
                MMA_(s1, ql[ks][0], ql[ks][1], ql[ks][2], ql[ks][3], kh0[2], kh0[3]);
                MMA_(s2, ql[ks][0], ql[ks][1], ql[ks][2], ql[ks][3], kh1[0], kh1[1]);
                MMA_(s3, ql[ks][0], ql[ks][1], ql[ks][2], ql[ks][3], kh1[2], kh1[3]);
            }
        }

        // ---- online softmax ----
        float mt0 = -1e30f, mt1 = -1e30f;
#pragma unroll
        for (int j = 0; j < 8; j++) {
            mt0 = fmaxf(mt0, fmaxf(s[j][0], s[j][1]));
            mt1 = fmaxf(mt1, fmaxf(s[j][2], s[j][3]));
        }
        mt0 = fmaxf(mt0, __shfl_xor_sync(0xffffffffu, mt0, 1));
        mt0 = fmaxf(mt0, __shfl_xor_sync(0xffffffffu, mt0, 2));
        mt1 = fmaxf(mt1, __shfl_xor_sync(0xffffffffu, mt1, 1));
        mt1 = fmaxf(mt1, __shfl_xor_sync(0xffffffffu, mt1, 2));
        float mn0 = fmaxf(m0, mt0), mn1 = fmaxf(m1, mt1);
        float corr0 = fexp(m0 - mn0), corr1 = fexp(m1 - mn1);
        float sum0 = 0.f, sum1 = 0.f;
#pragma unroll
        for (int j = 0; j < 8; j++) {
            s[j][0] = fexp(s[j][0] - mn0);
            s[j][1] = fexp(s[j][1] - mn0);
            s[j][2] = fexp(s[j][2] - mn1);
            s[j][3] = fexp(s[j][3] - mn1);
            sum0 += s[j][0] + s[j][1];
            sum1 += s[j][2] + s[j][3];
        }
        sum0 += __shfl_xor_sync(0xffffffffu, sum0, 1);
        sum0 += __shfl_xor_sync(0xffffffffu, sum0, 2);
        sum1 += __shfl_xor_sync(0xffffffffu, sum1, 1);
        sum1 += __shfl_xor_sync(0xffffffffu, sum1, 2);
        l0 = l0 * corr0 + sum0;
        l1 = l1 * corr1 + sum1;
        m0 = mn0; m1 = mn1;
#pragma unroll
        for (int j = 0; j < 8; j++) {
            o[j][0] *= corr0; o[j][1] *= corr0;
            o[j][2] *= corr1; o[j][3] *= corr1;
        }

        // ---- O += P V ----
        uint32_t vbase = sbase + 2 * KV_TILE;
        int vrow = lane & 15;
        int vc = lane >> 4;
#pragma unroll
        for (int ks = 0; ks < 4; ks++) {
            uint32_t ah0 = pack_bf16(s[2*ks][0],   s[2*ks][1]);
            uint32_t ah1 = pack_bf16(s[2*ks][2],   s[2*ks][3]);
            uint32_t ah2 = pack_bf16(s[2*ks+1][0], s[2*ks+1][1]);
            uint32_t ah3 = pack_bf16(s[2*ks+1][2], s[2*ks+1][3]);
            uint32_t al0 = pack_bf16(s[2*ks][0]   - bf16lo_f(ah0), s[2*ks][1]   - bf16hi_f(ah0));
            uint32_t al1 = pack_bf16(s[2*ks][2]   - bf16lo_f(ah1), s[2*ks][3]   - bf16hi_f(ah1));
            uint32_t al2 = pack_bf16(s[2*ks+1][0] - bf16lo_f(ah2), s[2*ks+1][1] - bf16hi_f(ah2));
            uint32_t al3 = pack_bf16(s[2*ks+1][2] - bf16lo_f(ah3), s[2*ks+1][3] - bf16hi_f(ah3));
            int row = ks * 16 + vrow;
#pragma unroll
            for (int jpp = 0; jpp < 2; jpp++) {
                int lc0 = (2 * jpp) * 2 + vc;
                int lc1 = (2 * jpp + 1) * 2 + vc;
                uint32_t a0 = vbase + sw128r(row, lc0);
                uint32_t a1 = vbase + sw128r(row, lc1);
                uint32_t vh0[4], vh1[4], vl0[4], vl1[4];
                LDSM_X4_T(vh0[0], vh0[1], vh0[2], vh0[3], a0);
                LDSM_X4_T(vh1[0], vh1[1], vh1[2], vh1[3], a1);
                LDSM_X4_T(vl0[0], vl0[1], vl0[2], vl0[3], a0 + KV_TILE);
                LDSM_X4_T(vl1[0], vl1[1], vl1[2], vl1[3], a1 + KV_TILE);
                float* o0 = o[4*jpp+0]; float* o1 = o[4*jpp+1];
                float* o2 = o[4*jpp+2]; float* o3 = o[4*jpp+3];
                MMA_(o0, ah0, ah1, ah2, ah3, vh0[0], vh0[1]);
                MMA_(o1, ah0, ah1, ah2, ah3, vh0[2], vh0[3]);
                MMA_(o2, ah0, ah1, ah2, ah3, vh1[0], vh1[1]);
                MMA_(o3, ah0, ah1, ah2, ah3, vh1[2], vh1[3]);
                MMA_(o0, ah0, ah1, ah2, ah3, vl0[0], vl0[1]);
                MMA_(o1, ah0, ah1, ah2, ah3, vl0[2], vl0[3]);
                MMA_(o2, ah0, ah1, ah2, ah3, vl1[0], vl1[1]);
                MMA_(o3, ah0, ah1, ah2, ah3, vl1[2], vl1[3]);
                MMA_(o0, al0, al1, al2, al3, vh0[0], vh0[1]);
                MMA_(o1, al0, al1, al2, al3, vh0[2], vh0[3]);
                MMA_(o2, al0, al1, al2, al3, vh1[0], vh1[1]);
                MMA_(o3, al0, al1, al2, al3, vh1[2], vh1[3]);
            }
        }
    }

    // ---- finalize ----
    int g = lane >> 2, t = lane & 3;
    float inv0 = 1.0f / l0, inv1 = 1.0f / l1;
    int b = bh >> 4, h = bh & 15;
    int row0 = q0 + wid * 16 + g;
    size_t ob0 = ((size_t)(b * T_) + row0) * C_ + h * 64 + t * 2;
    size_t ob1 = ob0 + (size_t)8 * C_;
#pragma unroll
    for (int j = 0; j < 8; j++) {
        float v0 = o[j][0] * inv0, v1 = o[j][1] * inv0;
        float v2 = o[j][2] * inv1, v3 = o[j][3] * inv1;
        uint32_t h0 = pack_bf16(v0, v1);
        uint32_t h1 = pack_bf16(v2, v3);
        uint32_t l0p = pack_bf16(v0 - bf16lo_f(h0), v1 - bf16hi_f(h0));
        uint32_t l1p = pack_bf16(v2 - bf16lo_f(h1), v3 - bf16hi_f(h1));
        *reinterpret_cast<uint32_t*>(g_Ohi + ob0 + j * 8) = h0;
        *reinterpret_cast<uint32_t*>(g_Ohi + ob1 + j * 8) = h1;
        *reinterpret_cast<uint32_t*>(g_Olo + ob0 + j * 8) = l0p;
        *reinterpret_cast<uint32_t*>(g_Olo + ob1 + j * 8) = l1p;
    }
}

// ---------------------------------------------------------------------------
extern "C" void kernel_launch(void* const* d_in, const int* in_sizes, int n_in,
                              void* d_out, int out_size)
{
    const float* x      = (const float*)d_in[0];
    const float* W_attn = (const float*)d_in[1];
    const float* b_attn = (const float*)d_in[2];
    const float* W_proj = (const float*)d_in[3];
    const float* b_proj = (const float*)d_in[4];
    float* out = (float*)d_out;

    cudaFuncSetAttribute(hmma_gemm_kernel,
                         cudaFuncAttributeMaxDynamicSharedMemorySize, GEMM_SMEM_BYTES);
    cudaFuncSetAttribute(attn_hmma_kernel,
                         cudaFuncAttributeMaxDynamicSharedMemorySize, ATTN_SMEM_BYTES);

    split_kernel<<<(B_*T_*C_) / 4 / 256, 256>>>((const float4*)x, 0);
    split_kernel<<<(3*C_*C_)  / 4 / 256, 256>>>((const float4*)W_attn, 1);
    split_kernel<<<(C_*C_)    / 4 / 256, 256>>>((const float4*)W_proj, 2);

    hmma_gemm_kernel<<<dim3(3 * C_ / 128, B_ * T_ / 64), 256, GEMM_SMEM_BYTES>>>(
        b_attn, nullptr, 0);

    attn_hmma_kernel<<<dim3(T_ / 64, BH_), 128, ATTN_SMEM_BYTES>>>();

    hmma_gemm_kernel<<<dim3(C_ / 128, B_ * T_ / 64), 256, GEMM_SMEM_BYTES>>>(
        b_proj, out, 1);
}

// round 9
// speedup vs baseline: 3.4951x; 1.0178x over previous
#include <cuda_runtime.h>
#include <cuda_bf16.h>
#include <cstdint>

#define B_  4
#define T_  2048
#define C_  1024
#define H_  16
#define HD_ 64
#define BH_ (B_*H_)
#define KD_ 1024

// ---------------------------------------------------------------------------
// Device-global scratch
// ---------------------------------------------------------------------------
__device__ __nv_bfloat16 g_Qh[(size_t)BH_*T_*HD_], g_Ql[(size_t)BH_*T_*HD_];
__device__ __nv_bfloat16 g_Kh[(size_t)BH_*T_*HD_], g_Kl[(size_t)BH_*T_*HD_];
__device__ __nv_bfloat16 g_Vh[(size_t)BH_*T_*HD_], g_Vl[(size_t)BH_*T_*HD_];

__device__ __nv_bfloat16 g_Xhi[(size_t)B_*T_*C_],   g_Xlo[(size_t)B_*T_*C_];
__device__ __nv_bfloat16 g_Wahi[(size_t)3*C_*C_],   g_Walo[(size_t)3*C_*C_];
__device__ __nv_bfloat16 g_Wphi[(size_t)C_*C_],     g_Wplo[(size_t)C_*C_];
__device__ __nv_bfloat16 g_Ohi[(size_t)B_*T_*C_],   g_Olo[(size_t)B_*T_*C_];

// ---------------------------------------------------------------------------
// Helpers
// ---------------------------------------------------------------------------
__device__ __forceinline__ uint32_t smem_u32(const void* p) {
    uint32_t a;
    asm("{ .reg .u64 t; cvta.to.shared.u64 t, %1; cvt.u32.u64 %0, t; }"
        : "=r"(a) : "l"(p));
    return a;
}

#define CP_ASYNC16(dst, src) \
    asm volatile("cp.async.cg.shared.global [%0], [%1], 16;" :: "r"(dst), "l"(src))
#define CP_COMMIT() asm volatile("cp.async.commit_group;" ::: "memory")
#define CP_WAIT1()  asm volatile("cp.async.wait_group 1;" ::: "memory")
#define CP_WAIT0()  asm volatile("cp.async.wait_group 0;" ::: "memory")

#define LDSM_X4(r0, r1, r2, r3, addr) \
    asm volatile("ldmatrix.sync.aligned.m8n8.x4.shared.b16 {%0,%1,%2,%3}, [%4];" \
        : "=r"(r0), "=r"(r1), "=r"(r2), "=r"(r3) : "r"(addr))
#define LDSM_X4_T(r0, r1, r2, r3, addr) \
    asm volatile("ldmatrix.sync.aligned.m8n8.x4.trans.shared.b16 {%0,%1,%2,%3}, [%4];" \
        : "=r"(r0), "=r"(r1), "=r"(r2), "=r"(r3) : "r"(addr))

#define MMA_(c, a0, a1, a2, a3, b0, b1) \
    asm volatile("mma.sync.aligned.m16n8k16.row.col.f32.bf16.bf16.f32 " \
        "{%0,%1,%2,%3}, {%4,%5,%6,%7}, {%8,%9}, {%0,%1,%2,%3};" \
        : "+f"((c)[0]), "+f"((c)[1]), "+f"((c)[2]), "+f"((c)[3]) \
        : "r"(a0), "r"(a1), "r"(a2), "r"(a3), "r"(b0), "r"(b1))

__device__ __forceinline__ uint32_t pack_bf16(float lo, float hi) {
    uint32_t r;
    asm("cvt.rn.bf16x2.f32 %0, %1, %2;" : "=r"(r) : "f"(hi), "f"(lo));
    return r;
}
__device__ __forceinline__ float bf16lo_f(uint32_t r) { return __int_as_float(r << 16); }
__device__ __forceinline__ float bf16hi_f(uint32_t r) { return __int_as_float(r & 0xffff0000u); }

__device__ __forceinline__ float fexp(float x) {
    float y = fmaxf(x * 1.4426950408889634f, -126.0f);
    int ni = __float2int_rn(y);
    float f = y - (float)ni;
    float p = 1.3333558e-3f;
    p = p * f + 9.6181291e-3f;
    p = p * f + 5.5504109e-2f;
    p = p * f + 2.4022651e-1f;
    p = p * f + 6.9314718e-1f;
    p = p * f + 1.0f;
    return __int_as_float(__float_as_int(p) + ni * 8388608);
}

// Swizzled 64B-row offset (GEMM): phys chunk = ch ^ ((row>>1)&3)
__device__ __forceinline__ uint32_t sw64(int row, int ch) {
    return (uint32_t)(row * 64 + ((ch ^ ((row >> 1) & 3)) << 4));
}
// Swizzled 128B-row offset (attention): phys chunk = ch ^ (row&7)
__device__ __forceinline__ uint32_t sw128r(int row, int ch) {
    return (uint32_t)(row * 128 + ((ch ^ (row & 7)) << 4));
}

// ---------------------------------------------------------------------------
// Kernel A: fused fp32 -> bf16 hi/lo split for x, W_attn, W_proj.
// ---------------------------------------------------------------------------
#define NX4   ((B_*T_*C_) / 4)
#define NWA4  ((3*C_*C_) / 4)
#define NWP4  ((C_*C_) / 4)

__global__ void __launch_bounds__(256) split_all_kernel(
    const float4* __restrict__ x, const float4* __restrict__ wa,
    const float4* __restrict__ wp)
{
    size_t i = (size_t)blockIdx.x * blockDim.x + threadIdx.x;
    const float4* src;
    __nv_bfloat16 *hi, *lo;
    size_t j;
    if (i < NX4)                 { src = x;  j = i;               hi = g_Xhi;  lo = g_Xlo;  }
    else if (i < NX4 + NWA4)     { src = wa; j = i - NX4;         hi = g_Wahi; lo = g_Walo; }
    else                         { src = wp; j = i - NX4 - NWA4;  hi = g_Wphi; lo = g_Wplo; }

    float4 v = src[j];
    __nv_bfloat16 hx = __float2bfloat16(v.x), hy = __float2bfloat16(v.y);
    __nv_bfloat16 hz = __float2bfloat16(v.z), hw = __float2bfloat16(v.w);
    __nv_bfloat16 lx = __float2bfloat16(v.x - __bfloat162float(hx));
    __nv_bfloat16 ly = __float2bfloat16(v.y - __bfloat162float(hy));
    __nv_bfloat16 lz = __float2bfloat16(v.z - __bfloat162float(hz));
    __nv_bfloat16 lw = __float2bfloat16(v.w - __bfloat162float(hw));
    __nv_bfloat162* Hh = reinterpret_cast<__nv_bfloat162*>(hi + 4 * j);
    __nv_bfloat162* Ll = reinterpret_cast<__nv_bfloat162*>(lo + 4 * j);
    Hh[0] = __halves2bfloat162(hx, hy); Hh[1] = __halves2bfloat162(hz, hw);
    Ll[0] = __halves2bfloat162(lx, ly); Ll[1] = __halves2bfloat162(lz, lw);
}

// ---------------------------------------------------------------------------
// Kernel B: HMMA split GEMM, 3-buffer / 2-deep cp.async pipeline,
// ONE barrier per chunk. At iter ch: compute stage ch%3, prefetch chunk ch+2
// into stage (ch+2)%3 == (ch-1)%3, which every warp retired before this
// iteration's barrier (read during chunk ch-1). Consumed at iter ch+2 after
// wait_group(1) drains its group.
// ---------------------------------------------------------------------------
#define BK_       32
#define GA_TILE   4096
#define GB_TILE   8192
#define GSTAGE    (2*GA_TILE + 2*GB_TILE)   // 24576
#define GEMM_SMEM_BYTES (3 * GSTAGE)        // 73728

__global__ void __launch_bounds__(256, 3) hmma_gemm_kernel(
    const float* __restrict__ bias, float* __restrict__ Cout, int mode)
{
    extern __shared__ __align__(128) char smem[];
    const __nv_bfloat16 *Ahi, *Alo, *Bhi, *Blo;
    if (mode == 0) { Ahi = g_Xhi; Alo = g_Xlo; Bhi = g_Wahi; Blo = g_Walo; }
    else           { Ahi = g_Ohi; Alo = g_Olo; Bhi = g_Wphi; Blo = g_Wplo; }

    uint32_t sb = smem_u32(smem);
    int tid = threadIdx.x, lane = tid & 31, wid = tid >> 5;
    int bm = blockIdx.y * 64, bn = blockIdx.x * 128;
    int wm = wid >> 2;
    int wn = wid & 3;

    auto prefetch = [&](int chunk, int stage) {
        int k0 = chunk * BK_;
        uint32_t sbase = sb + stage * GSTAGE;
#pragma unroll
        for (int it = 0; it < 6; it++) {
            int idx = tid + it * 256;
            if (idx < 512) {
                int row = idx >> 2, ch = idx & 3;
                int r = row & 63;
                const __nv_bfloat16* src =
                    ((row < 64) ? Ahi : Alo) + (size_t)(bm + r) * KD_ + k0 + ch * 8;
                CP_ASYNC16(sbase + ((row < 64) ? 0 : GA_TILE) + sw64(r, ch), src);
            } else {
                int j = idx - 512;
                int row = j >> 2, ch = j & 3;
                int r = row & 127;
                const __nv_bfloat16* src =
                    ((row < 128) ? Bhi : Blo) + (size_t)(bn + r) * KD_ + k0 + ch * 8;
                CP_ASYNC16(sbase + 2 * GA_TILE + ((row < 128) ? 0 : GB_TILE) + sw64(r, ch), src);
            }
        }
        CP_COMMIT();
    };

    float acc[2][4][4];
#pragma unroll
    for (int mi = 0; mi < 2; mi++)
#pragma unroll
        for (int ni = 0; ni < 4; ni++)
#pragma unroll
            for (int r = 0; r < 4; r++) acc[mi][ni][r] = 0.f;

    prefetch(0, 0);
    prefetch(1, 1);

    const int NCH = KD_ / BK_;   // 32
    for (int ch = 0; ch < NCH; ch++) {
        if (ch < NCH - 1) CP_WAIT1(); else CP_WAIT0();
        __syncthreads();   // all warps: chunk ch data visible, chunk ch-1 retired

        int stage = ch - (ch / 3) * 3;
        uint32_t sbase = sb + stage * GSTAGE;
        uint32_t bbase = sbase + 2 * GA_TILE;

        // prefetch chunk ch+2 into the stage retired at the barrier above
        if (ch + 2 < NCH) {
            int pst = ch + 2 - ((ch + 2) / 3) * 3;
            prefetch(ch + 2, pst);
        }

#pragma unroll
        for (int ks = 0; ks < 2; ks++) {
            uint32_t ah[2][4], al[2][4], bh[2][4], bl[2][4];
            int ac = ks * 2 + (lane >> 4);
#pragma unroll
            for (int mi = 0; mi < 2; mi++) {
                int ar = wm * 32 + mi * 16 + (lane & 15);
                uint32_t ad = sbase + sw64(ar, ac);
                LDSM_X4(ah[mi][0], ah[mi][1], ah[mi][2], ah[mi][3], ad);
                LDSM_X4(al[mi][0], al[mi][1], al[mi][2], al[mi][3], ad + GA_TILE);
            }
            int bc = ks * 2 + ((lane >> 3) & 1);
            int brl = ((lane >> 4) << 3) + (lane & 7);
#pragma unroll
            for (int np = 0; np < 2; np++) {
                int br = wn * 32 + np * 16 + brl;
                uint32_t bd = bbase + sw64(br, bc);
                LDSM_X4(bh[np][0], bh[np][1], bh[np][2], bh[np][3], bd);
                LDSM_X4(bl[np][0], bl[np][1], bl[np][2], bl[np][3], bd + GB_TILE);
            }
#pragma unroll
            for (int mi = 0; mi < 2; mi++)
#pragma unroll
                for (int np = 0; np < 2; np++) {
                    MMA_(acc[mi][2*np],   ah[mi][0], ah[mi][1], ah[mi][2], ah[mi][3], bh[np][0], bh[np][1]);
                    MMA_(acc[mi][2*np+1], ah[mi][0], ah[mi][1], ah[mi][2], ah[mi][3], bh[np][2], bh[np][3]);
                }
#pragma unroll
            for (int mi = 0; mi < 2; mi++)
#pragma unroll
                for (int np = 0; np < 2; np++) {
                    MMA_(acc[mi][2*np],   ah[mi][0], ah[mi][1], ah[mi][2], ah[mi][3], bl[np][0], bl[np][1]);
                    MMA_(acc[mi][2*np+1], ah[mi][0], ah[mi][1], ah[mi][2], ah[mi][3], bl[np][2], bl[np][3]);
                }
#pragma unroll
            for (int mi = 0; mi < 2; mi++)
#pragma unroll
                for (int np = 0; np < 2; np++) {
                    MMA_(acc[mi][2*np],   al[mi][0], al[mi][1], al[mi][2], al[mi][3], bh[np][0], bh[np][1]);
                    MMA_(acc[mi][2*np+1], al[mi][0], al[mi][1], al[mi][2], al[mi][3], bh[np][2], bh[np][3]);
                }
        }
        // no trailing barrier: next iteration's barrier provides the
        // retire guarantee for this stage before anyone overwrites it.
    }

    int g = lane >> 2, t = lane & 3;
    if (mode == 0) {
#pragma unroll
        for (int mi = 0; mi < 2; mi++)
#pragma unroll
            for (int ni = 0; ni < 4; ni++) {
                int r0 = bm + wm * 32 + mi * 16 + g;
                int c0 = bn + wn * 32 + ni * 8 + t * 2;
#pragma unroll
                for (int e = 0; e < 4; e++) {
                    int m = r0 + (e >> 1) * 8;
                    int col = c0 + (e & 1);
                    float v = acc[mi][ni][e] + bias[col];
                    int b = m >> 11, tt = m & 2047;
                    int seg = col >> 10, cn = col & 1023;
                    int h = cn >> 6, d = cn & 63;
                    size_t o = (((size_t)(b * H_ + h) * T_) + tt) * HD_ + d;
                    if (seg == 0) v *= 0.125f;
                    __nv_bfloat16 vh = __float2bfloat16(v);
                    __nv_bfloat16 vl = __float2bfloat16(v - __bfloat162float(vh));
                    if (seg == 0)      { g_Qh[o] = vh; g_Ql[o] = vl; }
                    else if (seg == 1) { g_Kh[o] = vh; g_Kl[o] = vl; }
                    else               { g_Vh[o] = vh; g_Vl[o] = vl; }
                }
            }
    } else {
#pragma unroll
        for (int mi = 0; mi < 2; mi++)
#pragma unroll
            for (int ni = 0; ni < 4; ni++) {
                int r0 = bm + wm * 32 + mi * 16 + g;
                int c0 = bn + wn * 32 + ni * 8 + t * 2;
                float2 v0 = make_float2(acc[mi][ni][0] + bias[c0],
                                        acc[mi][ni][1] + bias[c0 + 1]);
                float2 v1 = make_float2(acc[mi][ni][2] + bias[c0],
                                        acc[mi][ni][3] + bias[c0 + 1]);
                *reinterpret_cast<float2*>(&Cout[(size_t)r0 * C_ + c0]) = v0;
                *reinterpret_cast<float2*>(&Cout[(size_t)(r0 + 8) * C_ + c0]) = v1;
            }
    }
}

// ---------------------------------------------------------------------------
// Kernel C: tensor-core flash attention (unchanged from Round 7).
// ---------------------------------------------------------------------------
#define KV_TILE  8192
#define KV_STAGE (4 * KV_TILE)
#define ATTN_SMEM_BYTES (2 * KV_STAGE)

__global__ void __launch_bounds__(128, 3) attn_hmma_kernel()
{
    extern __shared__ __align__(128) char smem[];
    uint32_t sb = smem_u32(smem);
    int tid = threadIdx.x, lane = tid & 31, wid = tid >> 5;
    int bh = blockIdx.y, q0 = blockIdx.x * 64;
    size_t bhbase = (size_t)bh * T_ * HD_;

    {
        const __nv_bfloat16* Qh = g_Qh + bhbase + (size_t)q0 * HD_;
        const __nv_bfloat16* Ql = g_Ql + bhbase + (size_t)q0 * HD_;
#pragma unroll
        for (int it = 0; it < 8; it++) {
            int idx = tid + it * 128;
            int tile = idx >> 9, within = idx & 511;
            int row = within >> 3, ch = within & 7;
            const __nv_bfloat16* src = (tile ? Ql : Qh) + (size_t)row * HD_ + ch * 8;
            CP_ASYNC16(sb + tile * 8192 + sw128r(row, ch), src);
        }
        CP_COMMIT(); CP_WAIT0();
        __syncthreads();
    }

    uint32_t qh[4][4], ql[4][4];
    {
        int arow = wid * 16 + (lane & 15);
#pragma unroll
        for (int ks = 0; ks < 4; ks++) {
            int ac = ks * 2 + (lane >> 4);
            uint32_t addr = sb + sw128r(arow, ac);
            LDSM_X4(qh[ks][0], qh[ks][1], qh[ks][2], qh[ks][3], addr);
            LDSM_X4(ql[ks][0], ql[ks][1], ql[ks][2], ql[ks][3], addr + 8192);
        }
    }
    __syncthreads();

    const __nv_bfloat16 *Kh = g_Kh + bhbase, *Kl = g_Kl + bhbase;
    const __nv_bfloat16 *Vh = g_Vh + bhbase, *Vl = g_Vl + bhbase;

    auto kv_prefetch = [&](int kt) {
        uint32_t sbase = sb + (kt & 1) * KV_STAGE;
        int k0 = kt * 64;
#pragma unroll
        for (int it = 0; it < 16; it++) {
            int idx = tid + it * 128;
            int tile = idx >> 9, within = idx & 511;
            int row = within >> 3, ch = within & 7;
            const __nv_bfloat16* base =
                (tile == 0) ? Kh : (tile == 1) ? Kl : (tile == 2) ? Vh : Vl;
            CP_ASYNC16(sbase + tile * KV_TILE + sw128r(row, ch),
                       base + (size_t)(k0 + row) * HD_ + ch * 8);
        }
        CP_COMMIT();
    };

    float o[8][4];
#pragma unroll
    for (int j = 0; j < 8; j++)
#pragma unroll
        for (int r = 0; r < 4; r++) o[j][r] = 0.f;
    float m0 = -1e30f, m1 = -1e30f, l0 = 0.f, l1 = 0.f;

    kv_prefetch(0);

    for (int kt = 0; kt < T_ / 64; kt++) {
        CP_WAIT0();
        __syncthreads();
        if (kt + 1 < T_ / 64) kv_prefetch(kt + 1);
        uint32_t sbase = sb + (kt & 1) * KV_STAGE;

        float s[8][4];
#pragma unroll
        for (int j = 0; j < 8; j++)
#pragma unroll
            for (int r = 0; r < 4; r++) s[j][r] = 0.f;

        int brl = ((lane >> 4) << 3) + (lane & 7);
        int bc  = (lane >> 3) & 1;
#pragma unroll
        for (int ks = 0; ks < 4; ks++) {
            int lc = ks * 2 + bc;
#pragma unroll
            for (int npp = 0; npp < 2; npp++) {
                int r0 = (2 * npp) * 16 + brl;
                int r1 = (2 * npp + 1) * 16 + brl;
                uint32_t a0 = sbase + sw128r(r0, lc);
                uint32_t a1 = sbase + sw128r(r1, lc);
                uint32_t kh0[4], kh1[4], kl0[4], kl1[4];
                LDSM_X4(kh0[0], kh0[1], kh0[2], kh0[3], a0);
                LDSM_X4(kh1[0], kh1[1], kh1[2], kh1[3], a1);
                LDSM_X4(kl0[0], kl0[1], kl0[2], kl0[3], a0 + KV_TILE);
                LDSM_X4(kl1[0], kl1[1], kl1[2], kl1[3], a1 + KV_TILE);
                float* s0 = s[4*npp+0]; float* s1 = s[4*npp+1];
                float* s2 = s[4*npp+2]; float* s3 = s[4*npp+3];
                MMA_(s0, qh[ks][0], qh[ks][1], qh[ks][2], qh[ks][3], kh0[0], kh0[1]);
                MMA_(s1, qh[ks][0], qh[ks][1], qh[ks][2], qh[ks][3], kh0[2], kh0[3]);
                MMA_(s2, qh[ks][0], qh[ks][1], qh[ks][2], qh[ks][3], kh1[0], kh1[1]);
                MMA_(s3, qh[ks][0], qh[ks][1], qh[ks][2], qh[ks][3], kh1[2], kh1[3]);
                MMA_(s0, qh[ks][0], qh[ks][1], qh[ks][2], qh[ks][3], kl0[0], kl0[1]);
                MMA_(s1, qh[ks][0], qh[ks][1], qh[ks][2], qh[ks][3], kl0[2], kl0[3]);
                MMA_(s2, qh[ks][0], qh[ks][1], qh[ks][2], qh[ks][3], kl1[0], kl1[1]);
                MMA_(s3, qh[ks][0], qh[ks][1], qh[ks][2], qh[ks][3], kl1[2], kl1[3]);
                MMA_(s0, ql[ks][0], ql[ks][1], ql[ks][2], ql[ks][3], kh0[0], kh0[1]);
                MMA_(s1, ql[ks][0], ql[ks][1], ql[ks][2], ql[ks][3], kh0[2], kh0[3]);
                MMA_(s2, ql[ks][0], ql[ks][1], ql[ks][2], ql[ks][3], kh1[0], kh1[1]);
                MMA_(s3, ql[ks][0], ql[ks][1], ql[ks][2], ql[ks][3], kh1[2], kh1[3]);
            }
        }

        float mt0 = -1e30f, mt1 = -1e30f;
#pragma unroll
        for (int j = 0; j < 8; j++) {
            mt0 = fmaxf(mt0, fmaxf(s[j][0], s[j][1]));
            mt1 = fmaxf(mt1, fmaxf(s[j][2], s[j][3]));
        }
        mt0 = fmaxf(mt0, __shfl_xor_sync(0xffffffffu, mt0, 1));
        mt0 = fmaxf(mt0, __shfl_xor_sync(0xffffffffu, mt0, 2));
        mt1 = fmaxf(mt1, __shfl_xor_sync(0xffffffffu, mt1, 1));
        mt1 = fmaxf(mt1, __shfl_xor_sync(0xffffffffu, mt1, 2));
        float mn0 = fmaxf(m0, mt0), mn1 = fmaxf(m1, mt1);
        float corr0 = fexp(m0 - mn0), corr1 = fexp(m1 - mn1);
        float sum0 = 0.f, sum1 = 0.f;
#pragma unroll
        for (int j = 0; j < 8; j++) {
            s[j][0] = fexp(s[j][0] - mn0);
            s[j][1] = fexp(s[j][1] - mn0);
            s[j][2] = fexp(s[j][2] - mn1);
            s[j][3] = fexp(s[j][3] - mn1);
            sum0 += s[j][0] + s[j][1];
            sum1 += s[j][2] + s[j][3];
        }
        sum0 += __shfl_xor_sync(0xffffffffu, sum0, 1);
        sum0 += __shfl_xor_sync(0xffffffffu, sum0, 2);
        sum1 += __shfl_xor_sync(0xffffffffu, sum1, 1);
        sum1 += __shfl_xor_sync(0xffffffffu, sum1, 2);
        l0 = l0 * corr0 + sum0;
        l1 = l1 * corr1 + sum1;
        m0 = mn0; m1 = mn1;
#pragma unroll
        for (int j = 0; j < 8; j++) {
            o[j][0] *= corr0; o[j][1] *= corr0;
            o[j][2] *= corr1; o[j][3] *= corr1;
        }

        uint32_t vbase = sbase + 2 * KV_TILE;
        int vrow = lane & 15;
        int vc = lane >> 4;
#pragma unroll
        for (int ks = 0; ks < 4; ks++) {
            uint32_t ah0 = pack_bf16(s[2*ks][0],   s[2*ks][1]);
            uint32_t ah1 = pack_bf16(s[2*ks][2],   s[2*ks][3]);
            uint32_t ah2 = pack_bf16(s[2*ks+1][0], s[2*ks+1][1]);
            uint32_t ah3 = pack_bf16(s[2*ks+1][2], s[2*ks+1][3]);
            uint32_t al0 = pack_bf16(s[2*ks][0]   - bf16lo_f(ah0), s[2*ks][1]   - bf16hi_f(ah0));
            uint32_t al1 = pack_bf16(s[2*ks][2]   - bf16lo_f(ah1), s[2*ks][3]   - bf16hi_f(ah1));
            uint32_t al2 = pack_bf16(s[2*ks+1][0] - bf16lo_f(ah2), s[2*ks+1][1] - bf16hi_f(ah2));
            uint32_t al3 = pack_bf16(s[2*ks+1][2] - bf16lo_f(ah3), s[2*ks+1][3] - bf16hi_f(ah3));
            int row = ks * 16 + vrow;
#pragma unroll
            for (int jpp = 0; jpp < 2; jpp++) {
                int lc0 = (2 * jpp) * 2 + vc;
                int lc1 = (2 * jpp + 1) * 2 + vc;
                uint32_t a0 = vbase + sw128r(row, lc0);
                uint32_t a1 = vbase + sw128r(row, lc1);
                uint32_t vh0[4], vh1[4], vl0[4], vl1[4];
                LDSM_X4_T(vh0[0], vh0[1], vh0[2], vh0[3], a0);
                LDSM_X4_T(vh1[0], vh1[1], vh1[2], vh1[3], a1);
                LDSM_X4_T(vl0[0], vl0[1], vl0[2], vl0[3], a0 + KV_TILE);
                LDSM_X4_T(vl1[0], vl1[1], vl1[2], vl1[3], a1 + KV_TILE);
                float* o0 = o[4*jpp+0]; float* o1 = o[4*jpp+1];
                float* o2 = o[4*jpp+2]; float* o3 = o[4*jpp+3];
                MMA_(o0, ah0, ah1, ah2, ah3, vh0[0], vh0[1]);
                MMA_(o1, ah0, ah1, ah2, ah3, vh0[2], vh0[3]);
                MMA_(o2, ah0, ah1, ah2, ah3, vh1[0], vh1[1]);
                MMA_(o3, ah0, ah1, ah2, ah3, vh1[2], vh1[3]);
                MMA_(o0, ah0, ah1, ah2, ah3, vl0[0], vl0[1]);
                MMA_(o1, ah0, ah1, ah2, ah3, vl0[2], vl0[3]);
                MMA_(o2, ah0, ah1, ah2, ah3, vl1[0], vl1[1]);
                MMA_(o3, ah0, ah1, ah2, ah3, vl1[2], vl1[3]);
                MMA_(o0, al0, al1, al2, al3, vh0[0], vh0[1]);
                MMA_(o1, al0, al1, al2, al3, vh0[2], vh0[3]);
                MMA_(o2, al0, al1, al2, al3, vh1[0], vh1[1]);
                MMA_(o3, al0, al1, al2, al3, vh1[2], vh1[3]);
            }
        }
    }

    int g = lane >> 2, t = lane & 3;
    float inv0 = 1.0f / l0, inv1 = 1.0f / l1;
    int b = bh >> 4, h = bh & 15;
    int row0 = q0 + wid * 16 + g;
    size_t ob0 = ((size_t)(b * T_) + row0) * C_ + h * 64 + t * 2;
    size_t ob1 = ob0 + (size_t)8 * C_;
#pragma unroll
    for (int j = 0; j < 8; j++) {
        float v0 = o[j][0] * inv0, v1 = o[j][1] * inv0;
        float v2 = o[j][2] * inv1, v3 = o[j][3] * inv1;
        uint32_t h0 = pack_bf16(v0, v1);
        uint32_t h1 = pack_bf16(v2, v3);
        uint32_t l0p = pack_bf16(v0 - bf16lo_f(h0), v1 - bf16hi_f(h0));
        uint32_t l1p = pack_bf16(v2 - bf16lo_f(h1), v3 - bf16hi_f(h1));
        *reinterpret_cast<uint32_t*>(g_Ohi + ob0 + j * 8) = h0;
        *reinterpret_cast<uint32_t*>(g_Ohi + ob1 + j * 8) = h1;
        *reinterpret_cast<uint32_t*>(g_Olo + ob0 + j * 8) = l0p;
        *reinterpret_cast<uint32_t*>(g_Olo + ob1 + j * 8) = l1p;
    }
}

// ---------------------------------------------------------------------------
extern "C" void kernel_launch(void* const* d_in, const int* in_sizes, int n_in,
                              void* d_out, int out_size)
{
    const float* x      = (const float*)d_in[0];
    const float* W_attn = (const float*)d_in[1];
    const float* b_attn = (const float*)d_in[2];
    const float* W_proj = (const float*)d_in[3];
    const float* b_proj = (const float*)d_in[4];
    float* out = (float*)d_out;

    cudaFuncSetAttribute(hmma_gemm_kernel,
                         cudaFuncAttributeMaxDynamicSharedMemorySize, GEMM_SMEM_BYTES);
    cudaFuncSetAttribute(attn_hmma_kernel,
                         cudaFuncAttributeMaxDynamicSharedMemorySize, ATTN_SMEM_BYTES);

    int splitBlocks = (NX4 + NWA4 + NWP4) / 256;
    split_all_kernel<<<splitBlocks, 256>>>(
        (const float4*)x, (const float4*)W_attn, (const float4*)W_proj);

    hmma_gemm_kernel<<<dim3(3 * C_ / 128, B_ * T_ / 64), 256, GEMM_SMEM_BYTES>>>(
        b_attn, nullptr, 0);

    attn_hmma_kernel<<<dim3(T_ / 64, BH_), 128, ATTN_SMEM_BYTES>>>();

    hmma_gemm_kernel<<<dim3(C_ / 128, B_ * T_ / 64), 256, GEMM_SMEM_BYTES>>>(
        b_proj, out, 1);
}

// round 10
// speedup vs baseline: 3.9453x; 1.1288x over previous
#include <cuda_runtime.h>
#include <cuda_bf16.h>
#include <cstdint>

#define B_  4
#define T_  2048
#define C_  1024
#define H_  16
#define HD_ 64
#define BH_ (B_*H_)
#define KD_ 1024

// ---------------------------------------------------------------------------
// Device-global scratch
// ---------------------------------------------------------------------------
__device__ __nv_bfloat16 g_Qh[(size_t)BH_*T_*HD_], g_Ql[(size_t)BH_*T_*HD_];
__device__ __nv_bfloat16 g_Kh[(size_t)BH_*T_*HD_], g_Kl[(size_t)BH_*T_*HD_];
__device__ __nv_bfloat16 g_Vh[(size_t)BH_*T_*HD_], g_Vl[(size_t)BH_*T_*HD_];

__device__ __nv_bfloat16 g_Xhi[(size_t)B_*T_*C_],   g_Xlo[(size_t)B_*T_*C_];
__device__ __nv_bfloat16 g_Wahi[(size_t)3*C_*C_],   g_Walo[(size_t)3*C_*C_];
__device__ __nv_bfloat16 g_Wphi[(size_t)C_*C_],     g_Wplo[(size_t)C_*C_];
__device__ __nv_bfloat16 g_Ohi[(size_t)B_*T_*C_],   g_Olo[(size_t)B_*T_*C_];

// ---------------------------------------------------------------------------
// Helpers
// ---------------------------------------------------------------------------
__device__ __forceinline__ uint32_t smem_u32(const void* p) {
    uint32_t a;
    asm("{ .reg .u64 t; cvta.to.shared.u64 t, %1; cvt.u32.u64 %0, t; }"
        : "=r"(a) : "l"(p));
    return a;
}

#define CP_ASYNC16(dst, src) \
    asm volatile("cp.async.cg.shared.global [%0], [%1], 16;" :: "r"(dst), "l"(src))
#define CP_COMMIT() asm volatile("cp.async.commit_group;" ::: "memory")
#define CP_WAIT1()  asm volatile("cp.async.wait_group 1;" ::: "memory")
#define CP_WAIT0()  asm volatile("cp.async.wait_group 0;" ::: "memory")

#define LDSM_X4(r0, r1, r2, r3, addr) \
    asm volatile("ldmatrix.sync.aligned.m8n8.x4.shared.b16 {%0,%1,%2,%3}, [%4];" \
        : "=r"(r0), "=r"(r1), "=r"(r2), "=r"(r3) : "r"(addr))
#define LDSM_X4_T(r0, r1, r2, r3, addr) \
    asm volatile("ldmatrix.sync.aligned.m8n8.x4.trans.shared.b16 {%0,%1,%2,%3}, [%4];" \
        : "=r"(r0), "=r"(r1), "=r"(r2), "=r"(r3) : "r"(addr))

#define MMA_(c, a0, a1, a2, a3, b0, b1) \
    asm volatile("mma.sync.aligned.m16n8k16.row.col.f32.bf16.bf16.f32 " \
        "{%0,%1,%2,%3}, {%4,%5,%6,%7}, {%8,%9}, {%0,%1,%2,%3};" \
        : "+f"((c)[0]), "+f"((c)[1]), "+f"((c)[2]), "+f"((c)[3]) \
        : "r"(a0), "r"(a1), "r"(a2), "r"(a3), "r"(b0), "r"(b1))

__device__ __forceinline__ uint32_t pack_bf16(float lo, float hi) {
    uint32_t r;
    asm("cvt.rn.bf16x2.f32 %0, %1, %2;" : "=r"(r) : "f"(hi), "f"(lo));
    return r;
}
__device__ __forceinline__ float bf16lo_f(uint32_t r) { return __int_as_float(r << 16); }
__device__ __forceinline__ float bf16hi_f(uint32_t r) { return __int_as_float(r & 0xffff0000u); }

// exp via MUFU: 2 instrs, runs on the (idle) MUFU pipe instead of FMA.
__device__ __forceinline__ float fexp(float x) {
    float y;
    asm("ex2.approx.ftz.f32 %0, %1;" : "=f"(y) : "f"(x * 1.4426950408889634f));
    return y;
}

// Swizzled 64B-row offset (GEMM): phys chunk = ch ^ ((row>>1)&3)
__device__ __forceinline__ uint32_t sw64(int row, int ch) {
    return (uint32_t)(row * 64 + ((ch ^ ((row >> 1) & 3)) << 4));
}
// Swizzled 128B-row offset (attention): phys chunk = ch ^ (row&7)
__device__ __forceinline__ uint32_t sw128r(int row, int ch) {
    return (uint32_t)(row * 128 + ((ch ^ (row & 7)) << 4));
}

// ---------------------------------------------------------------------------
// Kernel A: fused fp32 -> bf16 hi/lo split for x, W_attn, W_proj.
// ---------------------------------------------------------------------------
#define NX4   ((B_*T_*C_) / 4)
#define NWA4  ((3*C_*C_) / 4)
#define NWP4  ((C_*C_) / 4)

__global__ void __launch_bounds__(256) split_all_kernel(
    const float4* __restrict__ x, const float4* __restrict__ wa,
    const float4* __restrict__ wp)
{
    size_t i = (size_t)blockIdx.x * blockDim.x + threadIdx.x;
    const float4* src;
    __nv_bfloat16 *hi, *lo;
    size_t j;
    if (i < NX4)                 { src = x;  j = i;               hi = g_Xhi;  lo = g_Xlo;  }
    else if (i < NX4 + NWA4)     { src = wa; j = i - NX4;         hi = g_Wahi; lo = g_Walo; }
    else                         { src = wp; j = i - NX4 - NWA4;  hi = g_Wphi; lo = g_Wplo; }

    float4 v = src[j];
    __nv_bfloat16 hx = __float2bfloat16(v.x), hy = __float2bfloat16(v.y);
    __nv_bfloat16 hz = __float2bfloat16(v.z), hw = __float2bfloat16(v.w);
    __nv_bfloat16 lx = __float2bfloat16(v.x - __bfloat162float(hx));
    __nv_bfloat16 ly = __float2bfloat16(v.y - __bfloat162float(hy));
    __nv_bfloat16 lz = __float2bfloat16(v.z - __bfloat162float(hz));
    __nv_bfloat16 lw = __float2bfloat16(v.w - __bfloat162float(hw));
    __nv_bfloat162* Hh = reinterpret_cast<__nv_bfloat162*>(hi + 4 * j);
    __nv_bfloat162* Ll = reinterpret_cast<__nv_bfloat162*>(lo + 4 * j);
    Hh[0] = __halves2bfloat162(hx, hy); Hh[1] = __halves2bfloat162(hz, hw);
    Ll[0] = __halves2bfloat162(lx, ly); Ll[1] = __halves2bfloat162(lz, lw);
}

// ---------------------------------------------------------------------------
// Kernel B: HMMA split GEMM, 3-buffer / 2-deep cp.async pipeline,
// one barrier per chunk (schedule validated in R9).
// ---------------------------------------------------------------------------
#define BK_       32
#define GA_TILE   4096
#define GB_TILE   8192
#define GSTAGE    (2*GA_TILE + 2*GB_TILE)   // 24576
#define GEMM_SMEM_BYTES (3 * GSTAGE)        // 73728

__global__ void __launch_bounds__(256, 3) hmma_gemm_kernel(
    const float* __restrict__ bias, float* __restrict__ Cout, int mode)
{
    extern __shared__ __align__(128) char smem[];
    const __nv_bfloat16 *Ahi, *Alo, *Bhi, *Blo;
    if (mode == 0) { Ahi = g_Xhi; Alo = g_Xlo; Bhi = g_Wahi; Blo = g_Walo; }
    else           { Ahi = g_Ohi; Alo = g_Olo; Bhi = g_Wphi; Blo = g_Wplo; }

    uint32_t sb = smem_u32(smem);
    int tid = threadIdx.x, lane = tid & 31, wid = tid >> 5;
    int bm = blockIdx.y * 64, bn = blockIdx.x * 128;
    int wm = wid >> 2;
    int wn = wid & 3;

    auto prefetch = [&](int chunk, int stage) {
        int k0 = chunk * BK_;
        uint32_t sbase = sb + stage * GSTAGE;
#pragma unroll
        for (int it = 0; it < 6; it++) {
            int idx = tid + it * 256;
            if (idx < 512) {
                int row = idx >> 2, ch = idx & 3;
                int r = row & 63;
                const __nv_bfloat16* src =
                    ((row < 64) ? Ahi : Alo) + (size_t)(bm + r) * KD_ + k0 + ch * 8;
                CP_ASYNC16(sbase + ((row < 64) ? 0 : GA_TILE) + sw64(r, ch), src);
            } else {
                int j = idx - 512;
                int row = j >> 2, ch = j & 3;
                int r = row & 127;
                const __nv_bfloat16* src =
                    ((row < 128) ? Bhi : Blo) + (size_t)(bn + r) * KD_ + k0 + ch * 8;
                CP_ASYNC16(sbase + 2 * GA_TILE + ((row < 128) ? 0 : GB_TILE) + sw64(r, ch), src);
            }
        }
        CP_COMMIT();
    };

    float acc[2][4][4];
#pragma unroll
    for (int mi = 0; mi < 2; mi++)
#pragma unroll
        for (int ni = 0; ni < 4; ni++)
#pragma unroll
            for (int r = 0; r < 4; r++) acc[mi][ni][r] = 0.f;

    prefetch(0, 0);
    prefetch(1, 1);

    const int NCH = KD_ / BK_;   // 32
    for (int ch = 0; ch < NCH; ch++) {
        if (ch < NCH - 1) CP_WAIT1(); else CP_WAIT0();
        __syncthreads();

        int stage = ch - (ch / 3) * 3;
        uint32_t sbase = sb + stage * GSTAGE;
        uint32_t bbase = sbase + 2 * GA_TILE;

        if (ch + 2 < NCH) {
            int pst = ch + 2 - ((ch + 2) / 3) * 3;
            prefetch(ch + 2, pst);
        }

#pragma unroll
        for (int ks = 0; ks < 2; ks++) {
            uint32_t ah[2][4], al[2][4], bh[2][4], bl[2][4];
            int ac = ks * 2 + (lane >> 4);
#pragma unroll
            for (int mi = 0; mi < 2; mi++) {
                int ar = wm * 32 + mi * 16 + (lane & 15);
                uint32_t ad = sbase + sw64(ar, ac);
                LDSM_X4(ah[mi][0], ah[mi][1], ah[mi][2], ah[mi][3], ad);
                LDSM_X4(al[mi][0], al[mi][1], al[mi][2], al[mi][3], ad + GA_TILE);
            }
            int bc = ks * 2 + ((lane >> 3) & 1);
            int brl = ((lane >> 4) << 3) + (lane & 7);
#pragma unroll
            for (int np = 0; np < 2; np++) {
                int br = wn * 32 + np * 16 + brl;
                uint32_t bd = bbase + sw64(br, bc);
                LDSM_X4(bh[np][0], bh[np][1], bh[np][2], bh[np][3], bd);
                LDSM_X4(bl[np][0], bl[np][1], bl[np][2], bl[np][3], bd + GB_TILE);
            }
#pragma unroll
            for (int mi = 0; mi < 2; mi++)
#pragma unroll
                for (int np = 0; np < 2; np++) {
                    MMA_(acc[mi][2*np],   ah[mi][0], ah[mi][1], ah[mi][2], ah[mi][3], bh[np][0], bh[np][1]);
                    MMA_(acc[mi][2*np+1], ah[mi][0], ah[mi][1], ah[mi][2], ah[mi][3], bh[np][2], bh[np][3]);
                }
#pragma unroll
            for (int mi = 0; mi < 2; mi++)
#pragma unroll
                for (int np = 0; np < 2; np++) {
                    MMA_(acc[mi][2*np],   ah[mi][0], ah[mi][1], ah[mi][2], ah[mi][3], bl[np][0], bl[np][1]);
                    MMA_(acc[mi][2*np+1], ah[mi][0], ah[mi][1], ah[mi][2], ah[mi][3], bl[np][2], bl[np][3]);
                }
#pragma unroll
            for (int mi = 0; mi < 2; mi++)
#pragma unroll
                for (int np = 0; np < 2; np++) {
                    MMA_(acc[mi][2*np],   al[mi][0], al[mi][1], al[mi][2], al[mi][3], bh[np][0], bh[np][1]);
                    MMA_(acc[mi][2*np+1], al[mi][0], al[mi][1], al[mi][2], al[mi][3], bh[np][2], bh[np][3]);
                }
        }
    }

    int g = lane >> 2, t = lane & 3;
    if (mode == 0) {
        // bf16x2-packed scatter: col pairs (c0,c0+1) are same seg/head, d even.
#pragma unroll
        for (int mi = 0; mi < 2; mi++)
#pragma unroll
            for (int ni = 0; ni < 4; ni++) {
                int c0 = bn + wn * 32 + ni * 8 + t * 2;
                int seg = c0 >> 10, cn = c0 & 1023;
                int h = cn >> 6, d = cn & 63;
                float b0 = bias[c0], b1 = bias[c0 + 1];
#pragma unroll
                for (int half = 0; half < 2; half++) {
                    int m = bm + wm * 32 + mi * 16 + g + half * 8;
                    int b = m >> 11, tt = m & 2047;
                    float v0 = acc[mi][ni][half * 2 + 0] + b0;
                    float v1 = acc[mi][ni][half * 2 + 1] + b1;
                    if (seg == 0) { v0 *= 0.125f; v1 *= 0.125f; }
                    uint32_t hp = pack_bf16(v0, v1);
                    uint32_t lp = pack_bf16(v0 - bf16lo_f(hp), v1 - bf16hi_f(hp));
                    size_t o = (((size_t)(b * H_ + h) * T_) + tt) * HD_ + d;
                    __nv_bfloat16 *dh, *dl;
                    if (seg == 0)      { dh = g_Qh; dl = g_Ql; }
                    else if (seg == 1) { dh = g_Kh; dl = g_Kl; }
                    else               { dh = g_Vh; dl = g_Vl; }
                    *reinterpret_cast<uint32_t*>(dh + o) = hp;
                    *reinterpret_cast<uint32_t*>(dl + o) = lp;
                }
            }
    } else {
#pragma unroll
        for (int mi = 0; mi < 2; mi++)
#pragma unroll
            for (int ni = 0; ni < 4; ni++) {
                int r0 = bm + wm * 32 + mi * 16 + g;
                int c0 = bn + wn * 32 + ni * 8 + t * 2;
                float2 v0 = make_float2(acc[mi][ni][0] + bias[c0],
                                        acc[mi][ni][1] + bias[c0 + 1]);
                float2 v1 = make_float2(acc[mi][ni][2] + bias[c0],
                                        acc[mi][ni][3] + bias[c0 + 1]);
                *reinterpret_cast<float2*>(&Cout[(size_t)r0 * C_ + c0]) = v0;
                *reinterpret_cast<float2*>(&Cout[(size_t)(r0 + 8) * C_ + c0]) = v1;
            }
    }
}

// ---------------------------------------------------------------------------
// Kernel C: tensor-core flash attention (ex2-based exp).
// ---------------------------------------------------------------------------
#define KV_TILE  8192
#define KV_STAGE (4 * KV_TILE)
#define ATTN_SMEM_BYTES (2 * KV_STAGE)

__global__ void __launch_bounds__(128, 3) attn_hmma_kernel()
{
    extern __shared__ __align__(128) char smem[];
    uint32_t sb = smem_u32(smem);
    int tid = threadIdx.x, lane = tid & 31, wid = tid >> 5;
    int bh = blockIdx.y, q0 = blockIdx.x * 64;
    size_t bhbase = (size_t)bh * T_ * HD_;

    {
        const __nv_bfloat16* Qh = g_Qh + bhbase + (size_t)q0 * HD_;
        const __nv_bfloat16* Ql = g_Ql + bhbase + (size_t)q0 * HD_;
#pragma unroll
        for (int it = 0; it < 8; it++) {
            int idx = tid + it * 128;
            int tile = idx >> 9, within = idx & 511;
            int row = within >> 3, ch = within & 7;
            const __nv_bfloat16* src = (tile ? Ql : Qh) + (size_t)row * HD_ + ch * 8;
            CP_ASYNC16(sb + tile * 8192 + sw128r(row, ch), src);
        }
        CP_COMMIT(); CP_WAIT0();
        __syncthreads();
    }

    uint32_t qh[4][4], ql[4][4];
    {
        int arow = wid * 16 + (lane & 15);
#pragma unroll
        for (int ks = 0; ks < 4; ks++) {
            int ac = ks * 2 + (lane >> 4);
            uint32_t addr = sb + sw128r(arow, ac);
            LDSM_X4(qh[ks][0], qh[ks][1], qh[ks][2], qh[ks][3], addr);
            LDSM_X4(ql[ks][0], ql[ks][1], ql[ks][2], ql[ks][3], addr + 8192);
        }
    }
    __syncthreads();

    const __nv_bfloat16 *Kh = g_Kh + bhbase, *Kl = g_Kl + bhbase;
    const __nv_bfloat16 *Vh = g_Vh + bhbase, *Vl = g_Vl + bhbase;

    auto kv_prefetch = [&](int kt) {
        uint32_t sbase = sb + (kt & 1) * KV_STAGE;
        int k0 = kt * 64;
#pragma unroll
        for (int it = 0; it < 16; it++) {
            int idx = tid + it * 128;
            int tile = idx >> 9, within = idx & 511;
            int row = within >> 3, ch = within & 7;
            const __nv_bfloat16* base =
                (tile == 0) ? Kh : (tile == 1) ? Kl : (tile == 2) ? Vh : Vl;
            CP_ASYNC16(sbase + tile * KV_TILE + sw128r(row, ch),
                       base + (size_t)(k0 + row) * HD_ + ch * 8);
        }
        CP_COMMIT();
    };

    float o[8][4];
#pragma unroll
    for (int j = 0; j < 8; j++)
#pragma unroll
        for (int r = 0; r < 4; r++) o[j][r] = 0.f;
    float m0 = -1e30f, m1 = -1e30f, l0 = 0.f, l1 = 0.f;

    kv_prefetch(0);

    for (int kt = 0; kt < T_ / 64; kt++) {
        CP_WAIT0();
        __syncthreads();
        if (kt + 1 < T_ / 64) kv_prefetch(kt + 1);
        uint32_t sbase = sb + (kt & 1) * KV_STAGE;

        float s[8][4];
#pragma unroll
        for (int j = 0; j < 8; j++)
#pragma unroll
            for (int r = 0; r < 4; r++) s[j][r] = 0.f;

        int brl = ((lane >> 4) << 3) + (lane & 7);
        int bc  = (lane >> 3) & 1;
#pragma unroll
        for (int ks = 0; ks < 4; ks++) {
            int lc = ks * 2 + bc;
#pragma unroll
            for (int npp = 0; npp < 2; npp++) {
                int r0 = (2 * npp) * 16 + brl;
                int r1 = (2 * npp + 1) * 16 + brl;
                uint32_t a0 = sbase + sw128r(r0, lc);
                uint32_t a1 = sbase + sw128r(r1, lc);
                uint32_t kh0[4], kh1[4], kl0[4], kl1[4];
                LDSM_X4(kh0[0], kh0[1], kh0[2], kh0[3], a0);
                LDSM_X4(kh1[0], kh1[1], kh1[2], kh1[3], a1);
                LDSM_X4(kl0[0], kl0[1], kl0[2], kl0[3], a0 + KV_TILE);
                LDSM_X4(kl1[0], kl1[1], kl1[2], kl1[3], a1 + KV_TILE);
                float* s0 = s[4*npp+0]; float* s1 = s[4*npp+1];
                float* s2 = s[4*npp+2]; float* s3 = s[4*npp+3];
                MMA_(s0, qh[ks][0], qh[ks][1], qh[ks][2], qh[ks][3], kh0[0], kh0[1]);
                MMA_(s1, qh[ks][0], qh[ks][1], qh[ks][2], qh[ks][3], kh0[2], kh0[3]);
                MMA_(s2, qh[ks][0], qh[ks][1], qh[ks][2], qh[ks][3], kh1[0], kh1[1]);
                MMA_(s3, qh[ks][0], qh[ks][1], qh[ks][2], qh[ks][3], kh1[2], kh1[3]);
                MMA_(s0, qh[ks][0], qh[ks][1], qh[ks][2], qh[ks][3], kl0[0], kl0[1]);
                MMA_(s1, qh[ks][0], qh[ks][1], qh[ks][2], qh[ks][3], kl0[2], kl0[3]);
                MMA_(s2, qh[ks][0], qh[ks][1], qh[ks][2], qh[ks][3], kl1[0], kl1[1]);
                MMA_(s3, qh[ks][0], qh[ks][1], qh[ks][2], qh[ks][3], kl1[2], kl1[3]);
                MMA_(s0, ql[ks][0], ql[ks][1], ql[ks][2], ql[ks][3], kh0[0], kh0[1]);
                MMA_(s1, ql[ks][0], ql[ks][1], ql[ks][2], ql[ks][3], kh0[2], kh0[3]);
                MMA_(s2, ql[ks][0], ql[ks][1], ql[ks][2], ql[ks][3], kh1[0], kh1[1]);
                MMA_(s3, ql[ks][0], ql[ks][1], ql[ks][2], ql[ks][3], kh1[2], kh1[3]);
            }
        }

        float mt0 = -1e30f, mt1 = -1e30f;
#pragma unroll
        for (int j = 0; j < 8; j++) {
            mt0 = fmaxf(mt0, fmaxf(s[j][0], s[j][1]));
            mt1 = fmaxf(mt1, fmaxf(s[j][2], s[j][3]));
        }
        mt0 = fmaxf(mt0, __shfl_xor_sync(0xffffffffu, mt0, 1));
        mt0 = fmaxf(mt0, __shfl_xor_sync(0xffffffffu, mt0, 2));
        mt1 = fmaxf(mt1, __shfl_xor_sync(0xffffffffu, mt1, 1));
        mt1 = fmaxf(mt1, __shfl_xor_sync(0xffffffffu, mt1, 2));
        float mn0 = fmaxf(m0, mt0), mn1 = fmaxf(m1, mt1);
        float corr0 = fexp(m0 - mn0), corr1 = fexp(m1 - mn1);
        float sum0 = 0.f, sum1 = 0.f;
#pragma unroll
        for (int j = 0; j < 8; j++) {
            s[j][0] = fexp(s[j][0] - mn0);
            s[j][1] = fexp(s[j][1] - mn0);
            s[j][2] = fexp(s[j][2] - mn1);
            s[j][3] = fexp(s[j][3] - mn1);
            sum0 += s[j][0] + s[j][1];
            sum1 += s[j][2] + s[j][3];
        }
        sum0 += __shfl_xor_sync(0xffffffffu, sum0, 1);
        sum0 += __shfl_xor_sync(0xffffffffu, sum0, 2);
        sum1 += __shfl_xor_sync(0xffffffffu, sum1, 1);
        sum1 += __shfl_xor_sync(0xffffffffu, sum1, 2);
        l0 = l0 * corr0 + sum0;
        l1 = l1 * corr1 + sum1;
        m0 = mn0; m1 = mn1;
#pragma unroll
        for (int j = 0; j < 8; j++) {
            o[j][0] *= corr0; o[j][1] *= corr0;
            o[j][2] *= corr1; o[j][3] *= corr1;
        }

        uint32_t vbase = sbase + 2 * KV_TILE;
        int vrow = lane & 15;
        int vc = lane >> 4;
#pragma unroll
        for (int ks = 0; ks < 4; ks++) {
            uint32_t ah0 = pack_bf16(s[2*ks][0],   s[2*ks][1]);
            uint32_t ah1 = pack_bf16(s[2*ks][2],   s[2*ks][3]);
            uint32_t ah2 = pack_bf16(s[2*ks+1][0], s[2*ks+1][1]);
            uint32_t ah3 = pack_bf16(s[2*ks+1][2], s[2*ks+1][3]);
            uint32_t al0 = pack_bf16(s[2*ks][0]   - bf16lo_f(ah0), s[2*ks][1]   - bf16hi_f(ah0));
            uint32_t al1 = pack_bf16(s[2*ks][2]   - bf16lo_f(ah1), s[2*ks][3]   - bf16hi_f(ah1));
            uint32_t al2 = pack_bf16(s[2*ks+1][0] - bf16lo_f(ah2), s[2*ks+1][1] - bf16hi_f(ah2));
            uint32_t al3 = pack_bf16(s[2*ks+1][2] - bf16lo_f(ah3), s[2*ks+1][3] - bf16hi_f(ah3));
            int row = ks * 16 + vrow;
#pragma unroll
            for (int jpp = 0; jpp < 2; jpp++) {
                int lc0 = (2 * jpp) * 2 + vc;
                int lc1 = (2 * jpp + 1) * 2 + vc;
                uint32_t a0 = vbase + sw128r(row, lc0);
                uint32_t a1 = vbase + sw128r(row, lc1);
                uint32_t vh0[4], vh1[4], vl0[4], vl1[4];
                LDSM_X4_T(vh0[0], vh0[1], vh0[2], vh0[3], a0);
                LDSM_X4_T(vh1[0], vh1[1], vh1[2], vh1[3], a1);
                LDSM_X4_T(vl0[0], vl0[1], vl0[2], vl0[3], a0 + KV_TILE);
                LDSM_X4_T(vl1[0], vl1[1], vl1[2], vl1[3], a1 + KV_TILE);
                float* o0 = o[4*jpp+0]; float* o1 = o[4*jpp+1];
                float* o2 = o[4*jpp+2]; float* o3 = o[4*jpp+3];
                MMA_(o0, ah0, ah1, ah2, ah3, vh0[0], vh0[1]);
                MMA_(o1, ah0, ah1, ah2, ah3, vh0[2], vh0[3]);
                MMA_(o2, ah0, ah1, ah2, ah3, vh1[0], vh1[1]);
                MMA_(o3, ah0, ah1, ah2, ah3, vh1[2], vh1[3]);
                MMA_(o0, ah0, ah1, ah2, ah3, vl0[0], vl0[1]);
                MMA_(o1, ah0, ah1, ah2, ah3, vl0[2], vl0[3]);
                MMA_(o2, ah0, ah1, ah2, ah3, vl1[0], vl1[1]);
                MMA_(o3, ah0, ah1, ah2, ah3, vl1[2], vl1[3]);
                MMA_(o0, al0, al1, al2, al3, vh0[0], vh0[1]);
                MMA_(o1, al0, al1, al2, al3, vh0[2], vh0[3]);
                MMA_(o2, al0, al1, al2, al3, vh1[0], vh1[1]);
                MMA_(o3, al0, al1, al2, al3, vh1[2], vh1[3]);
            }
        }
    }

    int g = lane >> 2, t = lane & 3;
    float inv0 = 1.0f / l0, inv1 = 1.0f / l1;
    int b = bh >> 4, h = bh & 15;
    int row0 = q0 + wid * 16 + g;
    size_t ob0 = ((size_t)(b * T_) + row0) * C_ + h * 64 + t * 2;
    size_t ob1 = ob0 + (size_t)8 * C_;
#pragma unroll
    for (int j = 0; j < 8; j++) {
        float v0 = o[j][0] * inv0, v1 = o[j][1] * inv0;
        float v2 = o[j][2] * inv1, v3 = o[j][3] * inv1;
        uint32_t h0 = pack_bf16(v0, v1);
        uint32_t h1 = pack_bf16(v2, v3);
        uint32_t l0p = pack_bf16(v0 - bf16lo_f(h0), v1 - bf16hi_f(h0));
        uint32_t l1p = pack_bf16(v2 - bf16lo_f(h1), v3 - bf16hi_f(h1));
        *reinterpret_cast<uint32_t*>(g_Ohi + ob0 + j * 8) = h0;
        *reinterpret_cast<uint32_t*>(g_Ohi + ob1 + j * 8) = h1;
        *reinterpret_cast<uint32_t*>(g_Olo + ob0 + j * 8) = l0p;
        *reinterpret_cast<uint32_t*>(g_Olo + ob1 + j * 8) = l1p;
    }
}

// ---------------------------------------------------------------------------
extern "C" void kernel_launch(void* const* d_in, const int* in_sizes, int n_in,
                              void* d_out, int out_size)
{
    const float* x      = (const float*)d_in[0];
    const float* W_attn = (const float*)d_in[1];
    const float* b_attn = (const float*)d_in[2];
    const float* W_proj = (const float*)d_in[3];
    const float* b_proj = (const float*)d_in[4];
    float* out = (float*)d_out;

    cudaFuncSetAttribute(hmma_gemm_kernel,
                         cudaFuncAttributeMaxDynamicSharedMemorySize, GEMM_SMEM_BYTES);
    cudaFuncSetAttribute(attn_hmma_kernel,
                         cudaFuncAttributeMaxDynamicSharedMemorySize, ATTN_SMEM_BYTES);

    int splitBlocks = (NX4 + NWA4 + NWP4) / 256;
    split_all_kernel<<<splitBlocks, 256>>>(
        (const float4*)x, (const float4*)W_attn, (const float4*)W_proj);

    hmma_gemm_kernel<<<dim3(3 * C_ / 128, B_ * T_ / 64), 256, GEMM_SMEM_BYTES>>>(
        b_attn, nullptr, 0);

    attn_hmma_kernel<<<dim3(T_ / 64, BH_), 128, ATTN_SMEM_BYTES>>>();

    hmma_gemm_kernel<<<dim3(C_ / 128, B_ * T_ / 64), 256, GEMM_SMEM_BYTES>>>(
        b_proj, out, 1);
}

// round 11
// speedup vs baseline: 3.9514x; 1.0015x over previous
#include <cuda_runtime.h>
#include <cuda_bf16.h>
#include <cstdint>

#define B_  4
#define T_  2048
#define C_  1024
#define H_  16
#define HD_ 64
#define BH_ (B_*H_)
#define KD_ 1024

// ---------------------------------------------------------------------------
// Device-global scratch
// ---------------------------------------------------------------------------
__device__ __nv_bfloat16 g_Qh[(size_t)BH_*T_*HD_], g_Ql[(size_t)BH_*T_*HD_];
__device__ __nv_bfloat16 g_Kh[(size_t)BH_*T_*HD_], g_Kl[(size_t)BH_*T_*HD_];
__device__ __nv_bfloat16 g_Vh[(size_t)BH_*T_*HD_], g_Vl[(size_t)BH_*T_*HD_];

__device__ __nv_bfloat16 g_Xhi[(size_t)B_*T_*C_],   g_Xlo[(size_t)B_*T_*C_];
__device__ __nv_bfloat16 g_Wahi[(size_t)3*C_*C_],   g_Walo[(size_t)3*C_*C_];
__device__ __nv_bfloat16 g_Wphi[(size_t)C_*C_],     g_Wplo[(size_t)C_*C_];
__device__ __nv_bfloat16 g_Ohi[(size_t)B_*T_*C_],   g_Olo[(size_t)B_*T_*C_];

// ---------------------------------------------------------------------------
// Helpers
// ---------------------------------------------------------------------------
__device__ __forceinline__ uint32_t smem_u32(const void* p) {
    uint32_t a;
    asm("{ .reg .u64 t; cvta.to.shared.u64 t, %1; cvt.u32.u64 %0, t; }"
        : "=r"(a) : "l"(p));
    return a;
}

#define CP_ASYNC16(dst, src) \
    asm volatile("cp.async.cg.shared.global [%0], [%1], 16;" :: "r"(dst), "l"(src))
#define CP_COMMIT() asm volatile("cp.async.commit_group;" ::: "memory")
#define CP_WAIT1()  asm volatile("cp.async.wait_group 1;" ::: "memory")
#define CP_WAIT0()  asm volatile("cp.async.wait_group 0;" ::: "memory")

#define LDSM_X4(r0, r1, r2, r3, addr) \
    asm volatile("ldmatrix.sync.aligned.m8n8.x4.shared.b16 {%0,%1,%2,%3}, [%4];" \
        : "=r"(r0), "=r"(r1), "=r"(r2), "=r"(r3) : "r"(addr))
#define LDSM_X4_T(r0, r1, r2, r3, addr) \
    asm volatile("ldmatrix.sync.aligned.m8n8.x4.trans.shared.b16 {%0,%1,%2,%3}, [%4];" \
        : "=r"(r0), "=r"(r1), "=r"(r2), "=r"(r3) : "r"(addr))

#define MMA_(c, a0, a1, a2, a3, b0, b1) \
    asm volatile("mma.sync.aligned.m16n8k16.row.col.f32.bf16.bf16.f32 " \
        "{%0,%1,%2,%3}, {%4,%5,%6,%7}, {%8,%9}, {%0,%1,%2,%3};" \
        : "+f"((c)[0]), "+f"((c)[1]), "+f"((c)[2]), "+f"((c)[3]) \
        : "r"(a0), "r"(a1), "r"(a2), "r"(a3), "r"(b0), "r"(b1))

__device__ __forceinline__ uint32_t pack_bf16(float lo, float hi) {
    uint32_t r;
    asm("cvt.rn.bf16x2.f32 %0, %1, %2;" : "=r"(r) : "f"(hi), "f"(lo));
    return r;
}
__device__ __forceinline__ float bf16lo_f(uint32_t r) { return __int_as_float(r << 16); }
__device__ __forceinline__ float bf16hi_f(uint32_t r) { return __int_as_float(r & 0xffff0000u); }

// exp via MUFU pipe.
__device__ __forceinline__ float fexp(float x) {
    float y;
    asm("ex2.approx.ftz.f32 %0, %1;" : "=f"(y) : "f"(x * 1.4426950408889634f));
    return y;
}

// Swizzled 64B-row offset (GEMM): phys chunk = ch ^ ((row>>1)&3)
__device__ __forceinline__ uint32_t sw64(int row, int ch) {
    return (uint32_t)(row * 64 + ((ch ^ ((row >> 1) & 3)) << 4));
}
// Swizzled 128B-row offset (attention): phys chunk = ch ^ (row&7)
__device__ __forceinline__ uint32_t sw128r(int row, int ch) {
    return (uint32_t)(row * 128 + ((ch ^ (row & 7)) << 4));
}

// ---------------------------------------------------------------------------
// Kernel A: fused fp32 -> bf16 hi/lo split for x, W_attn, W_proj.
// ---------------------------------------------------------------------------
#define NX4   ((B_*T_*C_) / 4)
#define NWA4  ((3*C_*C_) / 4)
#define NWP4  ((C_*C_) / 4)

__global__ void __launch_bounds__(256) split_all_kernel(
    const float4* __restrict__ x, const float4* __restrict__ wa,
    const float4* __restrict__ wp)
{
    size_t i = (size_t)blockIdx.x * blockDim.x + threadIdx.x;
    const float4* src;
    __nv_bfloat16 *hi, *lo;
    size_t j;
    if (i < NX4)                 { src = x;  j = i;               hi = g_Xhi;  lo = g_Xlo;  }
    else if (i < NX4 + NWA4)     { src = wa; j = i - NX4;         hi = g_Wahi; lo = g_Walo; }
    else                         { src = wp; j = i - NX4 - NWA4;  hi = g_Wphi; lo = g_Wplo; }

    float4 v = src[j];
    __nv_bfloat16 hx = __float2bfloat16(v.x), hy = __float2bfloat16(v.y);
    __nv_bfloat16 hz = __float2bfloat16(v.z), hw = __float2bfloat16(v.w);
    __nv_bfloat16 lx = __float2bfloat16(v.x - __bfloat162float(hx));
    __nv_bfloat16 ly = __float2bfloat16(v.y - __bfloat162float(hy));
    __nv_bfloat16 lz = __float2bfloat16(v.z - __bfloat162float(hz));
    __nv_bfloat16 lw = __float2bfloat16(v.w - __bfloat162float(hw));
    __nv_bfloat162* Hh = reinterpret_cast<__nv_bfloat162*>(hi + 4 * j);
    __nv_bfloat162* Ll = reinterpret_cast<__nv_bfloat162*>(lo + 4 * j);
    Hh[0] = __halves2bfloat162(hx, hy); Hh[1] = __halves2bfloat162(hz, hw);
    Ll[0] = __halves2bfloat162(lx, ly); Ll[1] = __halves2bfloat162(lz, lw);
}

// ---------------------------------------------------------------------------
// Kernel B: HMMA split GEMM (unchanged from Round 10).
// ---------------------------------------------------------------------------
#define BK_       32
#define GA_TILE   4096
#define GB_TILE   8192
#define GSTAGE    (2*GA_TILE + 2*GB_TILE)   // 24576
#define GEMM_SMEM_BYTES (3 * GSTAGE)        // 73728

__global__ void __launch_bounds__(256, 3) hmma_gemm_kernel(
    const float* __restrict__ bias, float* __restrict__ Cout, int mode)
{
    extern __shared__ __align__(128) char smem[];
    const __nv_bfloat16 *Ahi, *Alo, *Bhi, *Blo;
    if (mode == 0) { Ahi = g_Xhi; Alo = g_Xlo; Bhi = g_Wahi; Blo = g_Walo; }
    else           { Ahi = g_Ohi; Alo = g_Olo; Bhi = g_Wphi; Blo = g_Wplo; }

    uint32_t sb = smem_u32(smem);
    int tid = threadIdx.x, lane = tid & 31, wid = tid >> 5;
    int bm = blockIdx.y * 64, bn = blockIdx.x * 128;
    int wm = wid >> 2;
    int wn = wid & 3;

    auto prefetch = [&](int chunk, int stage) {
        int k0 = chunk * BK_;
        uint32_t sbase = sb + stage * GSTAGE;
#pragma unroll
        for (int it = 0; it < 6; it++) {
            int idx = tid + it * 256;
            if (idx < 512) {
                int row = idx >> 2, ch = idx & 3;
                int r = row & 63;
                const __nv_bfloat16* src =
                    ((row < 64) ? Ahi : Alo) + (size_t)(bm + r) * KD_ + k0 + ch * 8;
                CP_ASYNC16(sbase + ((row < 64) ? 0 : GA_TILE) + sw64(r, ch), src);
            } else {
                int j = idx - 512;
                int row = j >> 2, ch = j & 3;
                int r = row & 127;
                const __nv_bfloat16* src =
                    ((row < 128) ? Bhi : Blo) + (size_t)(bn + r) * KD_ + k0 + ch * 8;
                CP_ASYNC16(sbase + 2 * GA_TILE + ((row < 128) ? 0 : GB_TILE) + sw64(r, ch), src);
            }
        }
        CP_COMMIT();
    };

    float acc[2][4][4];
#pragma unroll
    for (int mi = 0; mi < 2; mi++)
#pragma unroll
        for (int ni = 0; ni < 4; ni++)
#pragma unroll
            for (int r = 0; r < 4; r++) acc[mi][ni][r] = 0.f;

    prefetch(0, 0);
    prefetch(1, 1);

    const int NCH = KD_ / BK_;   // 32
    for (int ch = 0; ch < NCH; ch++) {
        if (ch < NCH - 1) CP_WAIT1(); else CP_WAIT0();
        __syncthreads();

        int stage = ch - (ch / 3) * 3;
        uint32_t sbase = sb + stage * GSTAGE;
        uint32_t bbase = sbase + 2 * GA_TILE;

        if (ch + 2 < NCH) {
            int pst = ch + 2 - ((ch + 2) / 3) * 3;
            prefetch(ch + 2, pst);
        }

#pragma unroll
        for (int ks = 0; ks < 2; ks++) {
            uint32_t ah[2][4], al[2][4], bh[2][4], bl[2][4];
            int ac = ks * 2 + (lane >> 4);
#pragma unroll
            for (int mi = 0; mi < 2; mi++) {
                int ar = wm * 32 + mi * 16 + (lane & 15);
                uint32_t ad = sbase + sw64(ar, ac);
                LDSM_X4(ah[mi][0], ah[mi][1], ah[mi][2], ah[mi][3], ad);
                LDSM_X4(al[mi][0], al[mi][1], al[mi][2], al[mi][3], ad + GA_TILE);
            }
            int bc = ks * 2 + ((lane >> 3) & 1);
            int brl = ((lane >> 4) << 3) + (lane & 7);
#pragma unroll
            for (int np = 0; np < 2; np++) {
                int br = wn * 32 + np * 16 + brl;
                uint32_t bd = bbase + sw64(br, bc);
                LDSM_X4(bh[np][0], bh[np][1], bh[np][2], bh[np][3], bd);
                LDSM_X4(bl[np][0], bl[np][1], bl[np][2], bl[np][3], bd + GB_TILE);
            }
#pragma unroll
            for (int mi = 0; mi < 2; mi++)
#pragma unroll
                for (int np = 0; np < 2; np++) {
                    MMA_(acc[mi][2*np],   ah[mi][0], ah[mi][1], ah[mi][2], ah[mi][3], bh[np][0], bh[np][1]);
                    MMA_(acc[mi][2*np+1], ah[mi][0], ah[mi][1], ah[mi][2], ah[mi][3], bh[np][2], bh[np][3]);
                }
#pragma unroll
            for (int mi = 0; mi < 2; mi++)
#pragma unroll
                for (int np = 0; np < 2; np++) {
                    MMA_(acc[mi][2*np],   ah[mi][0], ah[mi][1], ah[mi][2], ah[mi][3], bl[np][0], bl[np][1]);
                    MMA_(acc[mi][2*np+1], ah[mi][0], ah[mi][1], ah[mi][2], ah[mi][3], bl[np][2], bl[np][3]);
                }
#pragma unroll
            for (int mi = 0; mi < 2; mi++)
#pragma unroll
                for (int np = 0; np < 2; np++) {
                    MMA_(acc[mi][2*np],   al[mi][0], al[mi][1], al[mi][2], al[mi][3], bh[np][0], bh[np][1]);
                    MMA_(acc[mi][2*np+1], al[mi][0], al[mi][1], al[mi][2], al[mi][3], bh[np][2], bh[np][3]);
                }
        }
    }

    int g = lane >> 2, t = lane & 3;
    if (mode == 0) {
#pragma unroll
        for (int mi = 0; mi < 2; mi++)
#pragma unroll
            for (int ni = 0; ni < 4; ni++) {
                int c0 = bn + wn * 32 + ni * 8 + t * 2;
                int seg = c0 >> 10, cn = c0 & 1023;
                int h = cn >> 6, d = cn & 63;
                float b0 = bias[c0], b1 = bias[c0 + 1];
#pragma unroll
                for (int half = 0; half < 2; half++) {
                    int m = bm + wm * 32 + mi * 16 + g + half * 8;
                    int b = m >> 11, tt = m & 2047;
                    float v0 = acc[mi][ni][half * 2 + 0] + b0;
                    float v1 = acc[mi][ni][half * 2 + 1] + b1;
                    if (seg == 0) { v0 *= 0.125f; v1 *= 0.125f; }
                    uint32_t hp = pack_bf16(v0, v1);
                    uint32_t lp = pack_bf16(v0 - bf16lo_f(hp), v1 - bf16hi_f(hp));
                    size_t o = (((size_t)(b * H_ + h) * T_) + tt) * HD_ + d;
                    __nv_bfloat16 *dh, *dl;
                    if (seg == 0)      { dh = g_Qh; dl = g_Ql; }
                    else if (seg == 1) { dh = g_Kh; dl = g_Kl; }
                    else               { dh = g_Vh; dl = g_Vl; }
                    *reinterpret_cast<uint32_t*>(dh + o) = hp;
                    *reinterpret_cast<uint32_t*>(dl + o) = lp;
                }
            }
    } else {
#pragma unroll
        for (int mi = 0; mi < 2; mi++)
#pragma unroll
            for (int ni = 0; ni < 4; ni++) {
                int r0 = bm + wm * 32 + mi * 16 + g;
                int c0 = bn + wn * 32 + ni * 8 + t * 2;
                float2 v0 = make_float2(acc[mi][ni][0] + bias[c0],
                                        acc[mi][ni][1] + bias[c0 + 1]);
                float2 v1 = make_float2(acc[mi][ni][2] + bias[c0],
                                        acc[mi][ni][3] + bias[c0 + 1]);
                *reinterpret_cast<float2*>(&Cout[(size_t)r0 * C_ + c0]) = v0;
                *reinterpret_cast<float2*>(&Cout[(size_t)(r0 + 8) * C_ + c0]) = v1;
            }
    }
}

// ---------------------------------------------------------------------------
// Kernel C: flash attention, 128 queries per CTA as TWO 64-row subtiles
// over each staged KV tile -> halves KV traffic / cp.async / barrier count.
// 4 warps, __launch_bounds__(128, 2).
// ---------------------------------------------------------------------------
#define KV_TILE  8192
#define KV_STAGE (4 * KV_TILE)
#define ATTN_SMEM_BYTES (2 * KV_STAGE)      // 65536

__global__ void __launch_bounds__(128, 2) attn_hmma_kernel()
{
    extern __shared__ __align__(128) char smem[];
    uint32_t sb = smem_u32(smem);
    int tid = threadIdx.x, lane = tid & 31, wid = tid >> 5;
    int bh = blockIdx.y, q0 = blockIdx.x * 128;
    size_t bhbase = (size_t)bh * T_ * HD_;

    // ---- stage 128 Q rows (hi at [0,16K), lo at [16K,32K)), consume to regs
    {
        const __nv_bfloat16* Qh = g_Qh + bhbase + (size_t)q0 * HD_;
        const __nv_bfloat16* Ql = g_Ql + bhbase + (size_t)q0 * HD_;
#pragma unroll
        for (int it = 0; it < 16; it++) {
            int idx = tid + it * 128;          // 0..2047
            int tile = idx >> 10, within = idx & 1023;
            int row = within >> 3, ch = within & 7;
            const __nv_bfloat16* src = (tile ? Ql : Qh) + (size_t)row * HD_ + ch * 8;
            CP_ASYNC16(sb + tile * 16384 + sw128r(row, ch), src);
        }
        CP_COMMIT(); CP_WAIT0();
        __syncthreads();
    }

    uint32_t qh[2][4][4], ql[2][4][4];
#pragma unroll
    for (int sub = 0; sub < 2; sub++) {
        int arow = sub * 64 + wid * 16 + (lane & 15);
#pragma unroll
        for (int ks = 0; ks < 4; ks++) {
            int ac = ks * 2 + (lane >> 4);
            uint32_t addr = sb + sw128r(arow, ac);
            LDSM_X4(qh[sub][ks][0], qh[sub][ks][1], qh[sub][ks][2], qh[sub][ks][3], addr);
            LDSM_X4(ql[sub][ks][0], ql[sub][ks][1], ql[sub][ks][2], ql[sub][ks][3], addr + 16384);
        }
    }
    __syncthreads();   // Q consumed; KV ring may overwrite

    const __nv_bfloat16 *Kh = g_Kh + bhbase, *Kl = g_Kl + bhbase;
    const __nv_bfloat16 *Vh = g_Vh + bhbase, *Vl = g_Vl + bhbase;

    auto kv_prefetch = [&](int kt) {
        uint32_t sbase = sb + (kt & 1) * KV_STAGE;
        int k0 = kt * 64;
#pragma unroll
        for (int it = 0; it < 16; it++) {
            int idx = tid + it * 128;          // 0..2047
            int tile = idx >> 9, within = idx & 511;
            int row = within >> 3, ch = within & 7;
            const __nv_bfloat16* base =
                (tile == 0) ? Kh : (tile == 1) ? Kl : (tile == 2) ? Vh : Vl;
            CP_ASYNC16(sbase + tile * KV_TILE + sw128r(row, ch),
                       base + (size_t)(k0 + row) * HD_ + ch * 8);
        }
        CP_COMMIT();
    };

    float o[2][8][4];
#pragma unroll
    for (int sub = 0; sub < 2; sub++)
#pragma unroll
        for (int j = 0; j < 8; j++)
#pragma unroll
            for (int r = 0; r < 4; r++) o[sub][j][r] = 0.f;
    float mrow[2][2] = {{-1e30f, -1e30f}, {-1e30f, -1e30f}};
    float lrow[2][2] = {{0.f, 0.f}, {0.f, 0.f}};

    kv_prefetch(0);

    for (int kt = 0; kt < T_ / 64; kt++) {
        CP_WAIT0();
        __syncthreads();
        if (kt + 1 < T_ / 64) kv_prefetch(kt + 1);
        uint32_t sbase = sb + (kt & 1) * KV_STAGE;
        uint32_t vbase = sbase + 2 * KV_TILE;

        int brl = ((lane >> 4) << 3) + (lane & 7);
        int bc  = (lane >> 3) & 1;
        int vrow = lane & 15;
        int vc = lane >> 4;

#pragma unroll
        for (int sub = 0; sub < 2; sub++) {
            // ---- S = Q K^T for this subtile ----
            float s[8][4];
#pragma unroll
            for (int j = 0; j < 8; j++)
#pragma unroll
                for (int r = 0; r < 4; r++) s[j][r] = 0.f;

#pragma unroll
            for (int ks = 0; ks < 4; ks++) {
                int lc = ks * 2 + bc;
#pragma unroll
                for (int npp = 0; npp < 2; npp++) {
                    int r0 = (2 * npp) * 16 + brl;
                    int r1 = (2 * npp + 1) * 16 + brl;
                    uint32_t a0 = sbase + sw128r(r0, lc);
                    uint32_t a1 = sbase + sw128r(r1, lc);
                    uint32_t kh0[4], kh1[4], kl0[4], kl1[4];
                    LDSM_X4(kh0[0], kh0[1], kh0[2], kh0[3], a0);
                    LDSM_X4(kh1[0], kh1[1], kh1[2], kh1[3], a1);
                    LDSM_X4(kl0[0], kl0[1], kl0[2], kl0[3], a0 + KV_TILE);
                    LDSM_X4(kl1[0], kl1[1], kl1[2], kl1[3], a1 + KV_TILE);
                    float* s0 = s[4*npp+0]; float* s1 = s[4*npp+1];
                    float* s2 = s[4*npp+2]; float* s3 = s[4*npp+3];
                    const uint32_t* QH = qh[sub][ks];
                    const uint32_t* QL = ql[sub][ks];
                    MMA_(s0, QH[0], QH[1], QH[2], QH[3], kh0[0], kh0[1]);
                    MMA_(s1, QH[0], QH[1], QH[2], QH[3], kh0[2], kh0[3]);
                    MMA_(s2, QH[0], QH[1], QH[2], QH[3], kh1[0], kh1[1]);
                    MMA_(s3, QH[0], QH[1], QH[2], QH[3], kh1[2], kh1[3]);
                    MMA_(s0, QH[0], QH[1], QH[2], QH[3], kl0[0], kl0[1]);
                    MMA_(s1, QH[0], QH[1], QH[2], QH[3], kl0[2], kl0[3]);
                    MMA_(s2, QH[0], QH[1], QH[2], QH[3], kl1[0], kl1[1]);
                    MMA_(s3, QH[0], QH[1], QH[2], QH[3], kl1[2], kl1[3]);
                    MMA_(s0, QL[0], QL[1], QL[2], QL[3], kh0[0], kh0[1]);
                    MMA_(s1, QL[0], QL[1], QL[2], QL[3], kh0[2], kh0[3]);
                    MMA_(s2, QL[0], QL[1], QL[2], QL[3], kh1[0], kh1[1]);
                    MMA_(s3, QL[0], QL[1], QL[2], QL[3], kh1[2], kh1[3]);
                }
            }

            // ---- online softmax ----
            float mt0 = -1e30f, mt1 = -1e30f;
#pragma unroll
            for (int j = 0; j < 8; j++) {
                mt0 = fmaxf(mt0, fmaxf(s[j][0], s[j][1]));
                mt1 = fmaxf(mt1, fmaxf(s[j][2], s[j][3]));
            }
            mt0 = fmaxf(mt0, __shfl_xor_sync(0xffffffffu, mt0, 1));
            mt0 = fmaxf(mt0, __shfl_xor_sync(0xffffffffu, mt0, 2));
            mt1 = fmaxf(mt1, __shfl_xor_sync(0xffffffffu, mt1, 1));
            mt1 = fmaxf(mt1, __shfl_xor_sync(0xffffffffu, mt1, 2));
            float mn0 = fmaxf(mrow[sub][0], mt0), mn1 = fmaxf(mrow[sub][1], mt1);
            float corr0 = fexp(mrow[sub][0] - mn0), corr1 = fexp(mrow[sub][1] - mn1);
            float sum0 = 0.f, sum1 = 0.f;
#pragma unroll
            for (int j = 0; j < 8; j++) {
                s[j][0] = fexp(s[j][0] - mn0);
                s[j][1] = fexp(s[j][1] - mn0);
                s[j][2] = fexp(s[j][2] - mn1);
                s[j][3] = fexp(s[j][3] - mn1);
                sum0 += s[j][0] + s[j][1];
                sum1 += s[j][2] + s[j][3];
            }
            sum0 += __shfl_xor_sync(0xffffffffu, sum0, 1);
            sum0 += __shfl_xor_sync(0xffffffffu, sum0, 2);
            sum1 += __shfl_xor_sync(0xffffffffu, sum1, 1);
            sum1 += __shfl_xor_sync(0xffffffffu, sum1, 2);
            lrow[sub][0] = lrow[sub][0] * corr0 + sum0;
            lrow[sub][1] = lrow[sub][1] * corr1 + sum1;
            mrow[sub][0] = mn0; mrow[sub][1] = mn1;
#pragma unroll
            for (int j = 0; j < 8; j++) {
                o[sub][j][0] *= corr0; o[sub][j][1] *= corr0;
                o[sub][j][2] *= corr1; o[sub][j][3] *= corr1;
            }

            // ---- O += P V ----
#pragma unroll
            for (int ks = 0; ks < 4; ks++) {
                uint32_t ah0 = pack_bf16(s[2*ks][0],   s[2*ks][1]);
                uint32_t ah1 = pack_bf16(s[2*ks][2],   s[2*ks][3]);
                uint32_t ah2 = pack_bf16(s[2*ks+1][0], s[2*ks+1][1]);
                uint32_t ah3 = pack_bf16(s[2*ks+1][2], s[2*ks+1][3]);
                uint32_t al0 = pack_bf16(s[2*ks][0]   - bf16lo_f(ah0), s[2*ks][1]   - bf16hi_f(ah0));
                uint32_t al1 = pack_bf16(s[2*ks][2]   - bf16lo_f(ah1), s[2*ks][3]   - bf16hi_f(ah1));
                uint32_t al2 = pack_bf16(s[2*ks+1][0] - bf16lo_f(ah2), s[2*ks+1][1] - bf16hi_f(ah2));
                uint32_t al3 = pack_bf16(s[2*ks+1][2] - bf16lo_f(ah3), s[2*ks+1][3] - bf16hi_f(ah3));
                int row = ks * 16 + vrow;
#pragma unroll
                for (int jpp = 0; jpp < 2; jpp++) {
                    int lc0 = (2 * jpp) * 2 + vc;
                    int lc1 = (2 * jpp + 1) * 2 + vc;
                    uint32_t a0 = vbase + sw128r(row, lc0);
                    uint32_t a1 = vbase + sw128r(row, lc1);
                    uint32_t vh0[4], vh1[4], vl0[4], vl1[4];
                    LDSM_X4_T(vh0[0], vh0[1], vh0[2], vh0[3], a0);
                    LDSM_X4_T(vh1[0], vh1[1], vh1[2], vh1[3], a1);
                    LDSM_X4_T(vl0[0], vl0[1], vl0[2], vl0[3], a0 + KV_TILE);
                    LDSM_X4_T(vl1[0], vl1[1], vl1[2], vl1[3], a1 + KV_TILE);
                    float* o0 = o[sub][4*jpp+0]; float* o1 = o[sub][4*jpp+1];
                    float* o2 = o[sub][4*jpp+2]; float* o3 = o[sub][4*jpp+3];
                    MMA_(o0, ah0, ah1, ah2, ah3, vh0[0], vh0[1]);
                    MMA_(o1, ah0, ah1, ah2, ah3, vh0[2], vh0[3]);
                    MMA_(o2, ah0, ah1, ah2, ah3, vh1[0], vh1[1]);
                    MMA_(o3, ah0, ah1, ah2, ah3, vh1[2], vh1[3]);
                    MMA_(o0, ah0, ah1, ah2, ah3, vl0[0], vl0[1]);
                    MMA_(o1, ah0, ah1, ah2, ah3, vl0[2], vl0[3]);
                    MMA_(o2, ah0, ah1, ah2, ah3, vl1[0], vl1[1]);
                    MMA_(o3, ah0, ah1, ah2, ah3, vl1[2], vl1[3]);
                    MMA_(o0, al0, al1, al2, al3, vh0[0], vh0[1]);
                    MMA_(o1, al0, al1, al2, al3, vh0[2], vh0[3]);
                    MMA_(o2, al0, al1, al2, al3, vh1[0], vh1[1]);
                    MMA_(o3, al0, al1, al2, al3, vh1[2], vh1[3]);
                }
            }
        }
    }

    // ---- finalize ----
    int g = lane >> 2, t = lane & 3;
    int b = bh >> 4, h = bh & 15;
#pragma unroll
    for (int sub = 0; sub < 2; sub++) {
        float inv0 = 1.0f / lrow[sub][0], inv1 = 1.0f / lrow[sub][1];
        int row0 = q0 + sub * 64 + wid * 16 + g;
        size_t ob0 = ((size_t)(b * T_) + row0) * C_ + h * 64 + t * 2;
        size_t ob1 = ob0 + (size_t)8 * C_;
#pragma unroll
        for (int j = 0; j < 8; j++) {
            float v0 = o[sub][j][0] * inv0, v1 = o[sub][j][1] * inv0;
            float v2 = o[sub][j][2] * inv1, v3 = o[sub][j][3] * inv1;
            uint32_t h0 = pack_bf16(v0, v1);
            uint32_t h1 = pack_bf16(v2, v3);
            uint32_t l0p = pack_bf16(v0 - bf16lo_f(h0), v1 - bf16hi_f(h0));
            uint32_t l1p = pack_bf16(v2 - bf16lo_f(h1), v3 - bf16hi_f(h1));
            *reinterpret_cast<uint32_t*>(g_Ohi + ob0 + j * 8) = h0;
            *reinterpret_cast<uint32_t*>(g_Ohi + ob1 + j * 8) = h1;
            *reinterpret_cast<uint32_t*>(g_Olo + ob0 + j * 8) = l0p;
            *reinterpret_cast<uint32_t*>(g_Olo + ob1 + j * 8) = l1p;
        }
    }
}

// ---------------------------------------------------------------------------
extern "C" void kernel_launch(void* const* d_in, const int* in_sizes, int n_in,
                              void* d_out, int out_size)
{
    const float* x      = (const float*)d_in[0];
    const float* W_attn = (const float*)d_in[1];
    const float* b_attn = (const float*)d_in[2];
    const float* W_proj = (const float*)d_in[3];
    const float* b_proj = (const float*)d_in[4];
    float* out = (float*)d_out;

    cudaFuncSetAttribute(hmma_gemm_kernel,
                         cudaFuncAttributeMaxDynamicSharedMemorySize, GEMM_SMEM_BYTES);
    cudaFuncSetAttribute(attn_hmma_kernel,
                         cudaFuncAttributeMaxDynamicSharedMemorySize, ATTN_SMEM_BYTES);

    int splitBlocks = (NX4 + NWA4 + NWP4) / 256;
    split_all_kernel<<<splitBlocks, 256>>>(
        (const float4*)x, (const float4*)W_attn, (const float4*)W_proj);

    hmma_gemm_kernel<<<dim3(3 * C_ / 128, B_ * T_ / 64), 256, GEMM_SMEM_BYTES>>>(
        b_attn, nullptr, 0);

    attn_hmma_kernel<<<dim3(T_ / 128, BH_), 128, ATTN_SMEM_BYTES>>>();

    hmma_gemm_kernel<<<dim3(C_ / 128, B_ * T_ / 64), 256, GEMM_SMEM_BYTES>>>(
        b_proj, out, 1);
}